// round 8
// baseline (speedup 1.0000x reference)
#include <cuda_runtime.h>
#include <cuda_bf16.h>
#include <math.h>
#include <stdint.h>

// ---------------- problem constants ----------------
#define BATCH   2
#define DSZ     28
#define WS      7
#define SHIFT_  3
#define CDIM    192
#define HEADS   6
#define HD      32
#define NTOK    343
#define NWIN    64
#define TOTWIN  128
#define TOK     43904
#define HID     768
#define SCALE   0.17677669529663687f

// GEMM tiling: CTA 128x128, warp tile 64x32 (2 warps M x 4 warps N)
#define BM      128
#define BN      128
#define KB      64
#define GEMM_SMEM_BYTES 98304   // 3 x (16KB A + 16KB B)

// padded weight N dims
#define NQKV_P  640
#define NPROJ_P 256
#define NFC2_P  256

// attention tiling
#define QT      64
#define NC      64
#define KPAD    384
#define NCH     6
#define QPITCH  80
#define KPITCH  80
#define VPITCH  784
#define PPITCH  144
#define CPITCH  344
// smem offsets (bytes)
#define AOFF_K   0
#define AOFF_V   30720
#define AOFF_Q   55808
#define AOFF_P   60928
#define AOFF_RS  70144
#define ATTN_SMEM_BYTES 70656

#define COMB_ELEMS (48 * NTOK * CPITCH)

// ---------------- scratch (device globals) ----------------
__device__ __nv_bfloat16 g_xwb [TOK * CDIM];
__device__ __nv_bfloat16 g_qkvb[TOK * 3 * CDIM];
__device__ __nv_bfloat16 g_attnb[TOK * CDIM];
__device__ float         g_proj[TOK * CDIM];
__device__ float         g_xres[TOK * CDIM];
__device__ __nv_bfloat16 g_ln2b[TOK * CDIM];
__device__ __nv_bfloat16 g_h1b [TOK * HID];
__device__ __nv_bfloat16 g_wqkv[NQKV_P * CDIM];      // zero-padded rows 576..639
__device__ __nv_bfloat16 g_wproj[NPROJ_P * CDIM];    // zero-padded rows 192..255
__device__ __nv_bfloat16 g_wfc1[HID * CDIM];
__device__ __nv_bfloat16 g_wfc2[NFC2_P * HID];       // zero-padded rows 192..255
__device__ __nv_bfloat16 g_comb[COMB_ELEMS];

// ---------------- helpers ----------------
__device__ __forceinline__ uint32_t s2u(const void* p) {
    uint32_t r;
    asm("{ .reg .u64 t; cvta.to.shared.u64 t, %1; cvt.u32.u64 %0, t; }" : "=r"(r) : "l"(p));
    return r;
}
__device__ __forceinline__ float warpSum(float v) {
#pragma unroll
    for (int o = 16; o; o >>= 1) v += __shfl_xor_sync(0xffffffffu, v, o);
    return v;
}
__device__ __forceinline__ int token_to_winrow(int t) {
    int b   = t / (DSZ * DSZ * DSZ);
    int rem = t - b * (DSZ * DSZ * DSZ);
    int dd  = rem / (DSZ * DSZ);
    int hh  = (rem / DSZ) % DSZ;
    int ww  = rem % DSZ;
    int i = (dd + DSZ - SHIFT_) % DSZ;
    int j = (hh + DSZ - SHIFT_) % DSZ;
    int k = (ww + DSZ - SHIFT_) % DSZ;
    int win = (i / WS) * 16 + (j / WS) * 4 + (k / WS);
    int n   = (i % WS) * 49 + (j % WS) * 7 + (k % WS);
    return (b * NWIN + win) * NTOK + n;
}

#define CP_ASYNC16(dst_u32, src_ptr) \
    asm volatile("cp.async.cg.shared.global [%0], [%1], 16;" :: "r"(dst_u32), "l"(src_ptr))
#define CP_COMMIT() asm volatile("cp.async.commit_group;")
#define CP_WAIT(n)  asm volatile("cp.async.wait_group %0;" :: "n"(n))

#define LDMX4(r0, r1, r2, r3, addr) \
    asm volatile("ldmatrix.sync.aligned.m8n8.x4.shared.b16 {%0,%1,%2,%3}, [%4];" \
                 : "=r"(r0), "=r"(r1), "=r"(r2), "=r"(r3) : "r"(addr))

#define MMA16816(d, a0, a1, a2, a3, b0, b1) \
    asm volatile("mma.sync.aligned.m16n8k16.row.col.f32.bf16.bf16.f32 " \
                 "{%0,%1,%2,%3}, {%4,%5,%6,%7}, {%8,%9}, {%0,%1,%2,%3};" \
                 : "+f"((d)[0]), "+f"((d)[1]), "+f"((d)[2]), "+f"((d)[3]) \
                 : "r"(a0), "r"(a1), "r"(a2), "r"(a3), "r"(b0), "r"(b1))

// ---------------- merged weight conversion ----------------
__global__ void cvt4_kernel(const float* __restrict__ s0, __nv_bfloat16* __restrict__ d0, int n0,
                            const float* __restrict__ s1, __nv_bfloat16* __restrict__ d1, int n1,
                            const float* __restrict__ s2, __nv_bfloat16* __restrict__ d2, int n2,
                            const float* __restrict__ s3, __nv_bfloat16* __restrict__ d3, int n3) {
    int i = blockIdx.x * 256 + threadIdx.x;
    if (i < n0) { d0[i] = __float2bfloat16(s0[i]); return; }
    i -= n0;
    if (i < n1) { d1[i] = __float2bfloat16(s1[i]); return; }
    i -= n1;
    if (i < n2) { d2[i] = __float2bfloat16(s2[i]); return; }
    i -= n2;
    if (i < n3) { d3[i] = __float2bfloat16(s3[i]); }
}

// ---------------- combined bias+mask precompute ----------------
__global__ void comb_pre_kernel(const float* __restrict__ table,
                                __nv_bfloat16* __restrict__ comb) {
    int idx = blockIdx.x * 256 + threadIdx.x;
    if (idx >= COMB_ELEMS) return;
    int col  = idx % CPITCH;
    int rest = idx / CPITCH;
    int row  = rest % NTOK;
    int hc   = rest / NTOK;
    int h = hc >> 3, cls = hc & 7;
    float val = -100.f;
    if (col < NTOK) {
        int i3 = row / 49, j3 = (row / 7) % 7, k3 = row % 7;
        int ci = col / 49, cj = (col / 7) % 7, ck = col % 7;
        int rel = (i3 - ci + 6) * 169 + (j3 - cj + 6) * 13 + (k3 - ck + 6);
        val = table[rel * HEADS + h];
        bool diff = ((cls & 4) && ((i3 < 4) != (ci < 4))) ||
                    ((cls & 2) && ((j3 < 4) != (cj < 4))) ||
                    ((cls & 1) && ((k3 < 4) != (ck < 4)));
        if (diff) val -= 100.f;
    }
    comb[idx] = __float2bfloat16(val);
}

// ---------------- LN1 + shift + partition: warp-per-token ----------------
__global__ __launch_bounds__(256) void ln1_kernel(const float* __restrict__ x,
                                                  const float* __restrict__ g,
                                                  const float* __restrict__ b,
                                                  __nv_bfloat16* __restrict__ xw) {
    int t = blockIdx.x * 8 + (threadIdx.x >> 5);
    int lane = threadIdx.x & 31;
    const float* xp = x + (size_t)t * CDIM;
    float v[6];
    float s = 0.f, s2 = 0.f;
#pragma unroll
    for (int i = 0; i < 6; i++) {
        v[i] = xp[lane + i * 32];
        s += v[i]; s2 += v[i] * v[i];
    }
    s = warpSum(s); s2 = warpSum(s2);
    float mean = s * (1.0f / CDIM);
    float rstd = rsqrtf(s2 * (1.0f / CDIM) - mean * mean + 1e-5f);
    int row = token_to_winrow(t);
    __nv_bfloat16* op = xw + (size_t)row * CDIM;
#pragma unroll
    for (int i = 0; i < 6; i++) {
        int c = lane + i * 32;
        op[c] = __float2bfloat16((v[i] - mean) * rstd * g[c] + b[c]);
    }
}

// ---------------- GEMM tile loader (A 128 rows + B 128 rows, one chunk) ----------------
__device__ __forceinline__ void gemm_issue(const __nv_bfloat16* __restrict__ A,
                                           const __nv_bfloat16* __restrict__ Wt,
                                           int bm, int bn, int Ktot, int lr, int lc8,
                                           char* bA, char* bB, int k0) {
#pragma unroll
    for (int rr = 0; rr < 4; rr++) {
        int r = lr + rr * 32;
        uint32_t off = (uint32_t)(r * 128 + lc8 * 2);
        off ^= (off >> 3) & 0x70;
        CP_ASYNC16(s2u(bA + off), A + (size_t)(bm + r) * Ktot + k0 + lc8);
    }
#pragma unroll
    for (int rr = 0; rr < 4; rr++) {
        int br = lr + rr * 32;
        uint32_t off = (uint32_t)(br * 128 + lc8 * 2);
        off ^= (off >> 3) & 0x70;
        CP_ASYNC16(s2u(bB + off), Wt + (size_t)(bn + br) * Ktot + k0 + lc8);
    }
    CP_COMMIT();
}

// ---------------- HMMA bf16 GEMM, warp tile 64x32 ----------------
// EPI: 0 = bias -> fp32; 1 = bias+gelu -> bf16; 2 = bias+resid -> fp32; 3 = bias -> bf16
template <int EPI, bool FULLK>
__global__ __launch_bounds__(256)
void gemm_mma_kernel(const __nv_bfloat16* __restrict__ A,
                     const __nv_bfloat16* __restrict__ Wt,
                     const float* __restrict__ bias,
                     const float* __restrict__ resid,
                     void* __restrict__ Cv, int Ktot, int Ntot)
{
    extern __shared__ __align__(1024) char dsm[];
    char* bufA[3] = {dsm, dsm + 16384, dsm + 32768};
    char* bufB[3] = {dsm + 49152, dsm + 65536, dsm + 81920};

    const int tid = threadIdx.x;
    const int lane = tid & 31;
    const int wid = tid >> 5;
    const int wm = (wid & 1) * 64;     // 2 warps in M, 64 rows each
    const int wn = (wid >> 1) * 32;    // 4 warps in N, 32 cols each
    const int bm = blockIdx.y * BM;
    const int bn = blockIdx.x * BN;

    float acc[4][4][4];
#pragma unroll
    for (int a = 0; a < 4; a++)
#pragma unroll
        for (int b = 0; b < 4; b++)
#pragma unroll
            for (int c = 0; c < 4; c++) acc[a][b][c] = 0.f;

    const int lr = tid >> 3;
    const int lc8 = (tid & 7) * 8;

    if (FULLK) {
#pragma unroll
        for (int ch = 0; ch < 3; ch++)
            gemm_issue(A, Wt, bm, bn, Ktot, lr, lc8, bufA[ch], bufB[ch], ch * KB);
        CP_WAIT(0);
        __syncthreads();
#pragma unroll
        for (int ks = 0; ks < 12; ks++) {
            const int chunk = ks >> 2, kk = ks & 3;
            const uint32_t sA = s2u(bufA[chunk]);
            const uint32_t sB = s2u(bufB[chunk]);
            uint32_t a0[4], a1[4], a2[4], a3[4];
#pragma unroll
            for (int mi = 0; mi < 4; mi++) {
                uint32_t off = (uint32_t)((wm + mi * 16 + (lane & 15)) * 128 + kk * 32 + (lane >> 4) * 16);
                off ^= (off >> 3) & 0x70;
                LDMX4(a0[mi], a1[mi], a2[mi], a3[mi], sA + off);
            }
#pragma unroll
            for (int nj = 0; nj < 2; nj++) {
                uint32_t off = (uint32_t)((wn + nj * 16 + (lane & 15)) * 128 + kk * 32 + (lane >> 4) * 16);
                off ^= (off >> 3) & 0x70;
                uint32_t r0, r1, r2, r3;
                LDMX4(r0, r1, r2, r3, sB + off);
#pragma unroll
                for (int mi = 0; mi < 4; mi++) {
                    MMA16816(acc[mi][2 * nj], a0[mi], a1[mi], a2[mi], a3[mi], r0, r2);
                    MMA16816(acc[mi][2 * nj + 1], a0[mi], a1[mi], a2[mi], a3[mi], r1, r3);
                }
            }
        }
    } else {
        const int nch = Ktot / KB;
        gemm_issue(A, Wt, bm, bn, Ktot, lr, lc8, bufA[0], bufB[0], 0);
        gemm_issue(A, Wt, bm, bn, Ktot, lr, lc8, bufA[1], bufB[1], KB);
        for (int ch = 0; ch < nch; ch++) {
            if (ch + 2 < nch)
                gemm_issue(A, Wt, bm, bn, Ktot, lr, lc8,
                           bufA[(ch + 2) % 3], bufB[(ch + 2) % 3], (ch + 2) * KB);
            const int rem = nch - ch - 1;
            if (rem >= 2)      CP_WAIT(2);
            else if (rem == 1) CP_WAIT(1);
            else               CP_WAIT(0);
            __syncthreads();

            const uint32_t sA = s2u(bufA[ch % 3]);
            const uint32_t sB = s2u(bufB[ch % 3]);
#pragma unroll
            for (int kk = 0; kk < KB / 16; kk++) {
                uint32_t a0[4], a1[4], a2[4], a3[4];
#pragma unroll
                for (int mi = 0; mi < 4; mi++) {
                    uint32_t off = (uint32_t)((wm + mi * 16 + (lane & 15)) * 128 + kk * 32 + (lane >> 4) * 16);
                    off ^= (off >> 3) & 0x70;
                    LDMX4(a0[mi], a1[mi], a2[mi], a3[mi], sA + off);
                }
#pragma unroll
                for (int nj = 0; nj < 2; nj++) {
                    uint32_t off = (uint32_t)((wn + nj * 16 + (lane & 15)) * 128 + kk * 32 + (lane >> 4) * 16);
                    off ^= (off >> 3) & 0x70;
                    uint32_t r0, r1, r2, r3;
                    LDMX4(r0, r1, r2, r3, sB + off);
#pragma unroll
                    for (int mi = 0; mi < 4; mi++) {
                        MMA16816(acc[mi][2 * nj], a0[mi], a1[mi], a2[mi], a3[mi], r0, r2);
                        MMA16816(acc[mi][2 * nj + 1], a0[mi], a1[mi], a2[mi], a3[mi], r1, r3);
                    }
                }
            }
            __syncthreads();
        }
    }

    const int gq = lane >> 2;
    const int tg = lane & 3;
#pragma unroll
    for (int mi = 0; mi < 4; mi++) {
#pragma unroll
        for (int ni = 0; ni < 4; ni++) {
            int col = bn + wn + ni * 8 + tg * 2;
            if (col >= Ntot) continue;
            float bia0 = bias[col], bia1 = bias[col + 1];
#pragma unroll
            for (int half = 0; half < 2; half++) {
                int row = bm + wm + mi * 16 + gq + half * 8;
                float v0 = acc[mi][ni][half * 2 + 0] + bia0;
                float v1 = acc[mi][ni][half * 2 + 1] + bia1;
                size_t oi = (size_t)row * Ntot + col;
                if (EPI == 1) {
                    v0 = 0.5f * v0 * (1.0f + erff(v0 * 0.7071067811865476f));
                    v1 = 0.5f * v1 * (1.0f + erff(v1 * 0.7071067811865476f));
                    __nv_bfloat162 p;
                    p.x = __float2bfloat16(v0); p.y = __float2bfloat16(v1);
                    *(__nv_bfloat162*)((__nv_bfloat16*)Cv + oi) = p;
                } else if (EPI == 2) {
                    float2 rv = *(const float2*)(resid + oi);
                    float2 o; o.x = v0 + rv.x; o.y = v1 + rv.y;
                    *(float2*)((float*)Cv + oi) = o;
                } else if (EPI == 3) {
                    __nv_bfloat162 p;
                    p.x = __float2bfloat16(v0); p.y = __float2bfloat16(v1);
                    *(__nv_bfloat162*)((__nv_bfloat16*)Cv + oi) = p;
                } else {
                    float2 o; o.x = v0; o.y = v1;
                    *(float2*)((float*)Cv + oi) = o;
                }
            }
        }
    }
}

// ---------------- tensor-core attention: persistent K/V, loop q-tiles ----------------
// grid (TOTWIN*HEADS); block 256, 3 CTAs/SM.
__global__ __launch_bounds__(256, 3) void attn_tc_kernel(
    const __nv_bfloat16* __restrict__ qkv, const __nv_bfloat16* __restrict__ comb,
    __nv_bfloat16* __restrict__ out)
{
    extern __shared__ __align__(1024) char sm[];
    const uint32_t uK = s2u(sm + AOFF_K);
    const uint32_t uV = s2u(sm + AOFF_V);
    const uint32_t uQ = s2u(sm + AOFF_Q);
    const uint32_t uP = s2u(sm + AOFF_P);
    float* rs = (float*)(sm + AOFF_RS);

    const int bx = blockIdx.x;
    const int w  = bx / HEADS;
    const int h  = bx - w * HEADS;
    const int mw = w % NWIN;
    const int wd = mw >> 4, wh = (mw >> 2) & 3, ww = mw & 3;
    const int cls = ((wd == 3) << 2) | ((wh == 3) << 1) | (ww == 3);
    const int tid = threadIdx.x;
    const int lane = tid & 31;
    const int wid = tid >> 5;

    const __nv_bfloat16* base = qkv + (size_t)w * NTOK * (3 * CDIM);

    // K (once per block)
    for (int idx = tid; idx < KPAD * 4; idx += 256) {
        int j = idx >> 2, s = idx & 3;
        uint4 v = make_uint4(0, 0, 0, 0);
        if (j < NTOK) v = *(const uint4*)(base + (size_t)j * (3 * CDIM) + CDIM + h * HD + s * 8);
        *(uint4*)(sm + AOFF_K + j * KPITCH + s * 16) = v;
    }
    // V transposed (once per block)
    for (int jp = tid; jp < KPAD / 2; jp += 256) {
        int j0 = jp * 2;
        __nv_bfloat16 ta[32], tb[32];
        if (j0 < NTOK) {
            const __nv_bfloat16* vp = base + (size_t)j0 * (3 * CDIM) + 2 * CDIM + h * HD;
#pragma unroll
            for (int s = 0; s < 4; s++) *(uint4*)(ta + s * 8) = *(const uint4*)(vp + s * 8);
        } else {
#pragma unroll
            for (int d = 0; d < 32; d++) ta[d] = __float2bfloat16(0.f);
        }
        if (j0 + 1 < NTOK) {
            const __nv_bfloat16* vp = base + (size_t)(j0 + 1) * (3 * CDIM) + 2 * CDIM + h * HD;
#pragma unroll
            for (int s = 0; s < 4; s++) *(uint4*)(tb + s * 8) = *(const uint4*)(vp + s * 8);
        } else {
#pragma unroll
            for (int d = 0; d < 32; d++) tb[d] = __float2bfloat16(0.f);
        }
#pragma unroll
        for (int d = 0; d < 32; d++) {
            __nv_bfloat162 p; p.x = ta[d]; p.y = tb[d];
            *(__nv_bfloat162*)(sm + AOFF_V + d * VPITCH + j0 * 2) = p;
        }
    }

    const int wm = wid & 3, wn = wid >> 2;
    const int vm = wid & 1, vn = wid >> 1;
    const int gq_ = lane >> 2, tg = lane & 3;
    const __nv_bfloat16* cb = comb + (size_t)(h * 8 + cls) * NTOK * CPITCH;

    for (int qt = 0; qt < NCH; qt++) {
        const int q0 = qt * QT;
        // Q tile
        for (int idx = tid; idx < QT * 4; idx += 256) {
            int r = idx >> 2, s = idx & 3;
            int gq = q0 + r;
            uint4 v = make_uint4(0, 0, 0, 0);
            if (gq < NTOK) v = *(const uint4*)(base + (size_t)gq * (3 * CDIM) + h * HD + s * 8);
            *(uint4*)(sm + AOFF_Q + r * QPITCH + s * 16) = v;
        }
        __syncthreads();

        float acc_o[2][4];
#pragma unroll
        for (int t = 0; t < 2; t++)
#pragma unroll
            for (int c = 0; c < 4; c++) acc_o[t][c] = 0.f;
        float rs0 = 0.f, rs1 = 0.f;

        const int r0g = q0 + wm * 16 + gq_;
        const int r1g = r0g + 8;
        const bool v0 = (r0g < NTOK);
        const bool v1 = (r1g < NTOK);
        const __nv_bfloat16* c0p = cb + (size_t)r0g * CPITCH;
        const __nv_bfloat16* c1p = cb + (size_t)r1g * CPITCH;

        for (int ch = 0; ch < NCH; ch++) {
            const int j0 = ch * NC;
            float acc[4][4];
#pragma unroll
            for (int t = 0; t < 4; t++)
#pragma unroll
                for (int c = 0; c < 4; c++) acc[t][c] = 0.f;

#pragma unroll
            for (int ks = 0; ks < 2; ks++) {
                uint32_t a0, a1, a2, a3;
                LDMX4(a0, a1, a2, a3,
                      uQ + (uint32_t)((wm * 16 + (lane & 15)) * QPITCH + ks * 32 + (lane >> 4) * 16));
#pragma unroll
                for (int nj = 0; nj < 2; nj++) {
                    uint32_t r0, r1, r2, r3;
                    LDMX4(r0, r1, r2, r3,
                          uK + (uint32_t)((j0 + wn * 32 + nj * 16 + (lane & 15)) * KPITCH + ks * 32 + (lane >> 4) * 16));
                    MMA16816(acc[2 * nj], a0, a1, a2, a3, r0, r2);
                    MMA16816(acc[2 * nj + 1], a0, a1, a2, a3, r1, r3);
                }
            }

#pragma unroll
            for (int ti = 0; ti < 4; ti++) {
                int jl = wn * 32 + (ti >> 1) * 16 + (ti & 1) * 8 + tg * 2;
                int ja = j0 + jl;
                float e00 = 0.f, e01 = 0.f, e10 = 0.f, e11 = 0.f;
                if (ja < NTOK) {
                    if (v0) {
                        __nv_bfloat162 bp = *(const __nv_bfloat162*)(c0p + ja);
                        e00 = __expf(fmaf(acc[ti][0], SCALE, __bfloat162float(bp.x)));
                        e01 = __expf(fmaf(acc[ti][1], SCALE, __bfloat162float(bp.y)));
                    }
                    if (v1) {
                        __nv_bfloat162 bp = *(const __nv_bfloat162*)(c1p + ja);
                        e10 = __expf(fmaf(acc[ti][2], SCALE, __bfloat162float(bp.x)));
                        e11 = __expf(fmaf(acc[ti][3], SCALE, __bfloat162float(bp.y)));
                    }
                }
                rs0 += e00 + e01;
                rs1 += e10 + e11;
                __nv_bfloat162 p0, p1;
                p0.x = __float2bfloat16(e00); p0.y = __float2bfloat16(e01);
                p1.x = __float2bfloat16(e10); p1.y = __float2bfloat16(e11);
                int rloc0 = wm * 16 + gq_;
                *(__nv_bfloat162*)(sm + AOFF_P + rloc0 * PPITCH + jl * 2) = p0;
                *(__nv_bfloat162*)(sm + AOFF_P + (rloc0 + 8) * PPITCH + jl * 2) = p1;
            }
            __syncthreads();

#pragma unroll
            for (int kk = 0; kk < 4; kk++) {
                uint32_t a0, a1, a2, a3;
                LDMX4(a0, a1, a2, a3,
                      uV + (uint32_t)((vm * 16 + (lane & 15)) * VPITCH + j0 * 2 + kk * 32 + (lane >> 4) * 16));
                uint32_t r0, r1, r2, r3;
                LDMX4(r0, r1, r2, r3,
                      uP + (uint32_t)((vn * 16 + (lane & 15)) * PPITCH + kk * 32 + (lane >> 4) * 16));
                MMA16816(acc_o[0], a0, a1, a2, a3, r0, r2);
                MMA16816(acc_o[1], a0, a1, a2, a3, r1, r3);
            }
            __syncthreads();
        }

        rs0 += __shfl_xor_sync(0xffffffffu, rs0, 1);
        rs0 += __shfl_xor_sync(0xffffffffu, rs0, 2);
        rs1 += __shfl_xor_sync(0xffffffffu, rs1, 1);
        rs1 += __shfl_xor_sync(0xffffffffu, rs1, 2);
        if (tg == 0) {
            rs[(wm * 16 + gq_) * 2 + wn] = rs0;
            rs[(wm * 16 + gq_ + 8) * 2 + wn] = rs1;
        }

        float* Ost = (float*)(sm + AOFF_P);
#pragma unroll
        for (int t = 0; t < 2; t++) {
            int qc = vn * 16 + t * 8 + tg * 2;
            int d0 = vm * 16 + gq_;
            Ost[d0 * 65 + qc]     = acc_o[t][0];
            Ost[d0 * 65 + qc + 1] = acc_o[t][1];
            Ost[(d0 + 8) * 65 + qc]     = acc_o[t][2];
            Ost[(d0 + 8) * 65 + qc + 1] = acc_o[t][3];
        }
        __syncthreads();

        {
            int q = tid >> 2, ds = (tid & 3) * 8;
            int gq = q0 + q;
            if (gq < NTOK) {
                float inv = __frcp_rn(rs[q * 2] + rs[q * 2 + 1]);
                __nv_bfloat16 o[8];
#pragma unroll
                for (int u = 0; u < 8; u++)
                    o[u] = __float2bfloat16(Ost[(ds + u) * 65 + q] * inv);
                *(uint4*)(out + (size_t)(w * NTOK + gq) * CDIM + h * HD + ds) = *(uint4*)o;
            }
        }
        __syncthreads();   // protect P/rs before next q-tile
    }
}

// ---------------- reverse + residual + LN2: warp-per-token ----------------
__global__ __launch_bounds__(256) void ln2res_kernel(const float* __restrict__ x,
                                                     const float* __restrict__ proj,
                                                     const float* __restrict__ g,
                                                     const float* __restrict__ b,
                                                     float* __restrict__ xres,
                                                     __nv_bfloat16* __restrict__ ln2o) {
    int t = blockIdx.x * 8 + (threadIdx.x >> 5);
    int lane = threadIdx.x & 31;
    int row = token_to_winrow(t);
    const float* xp = x + (size_t)t * CDIM;
    const float* pp = proj + (size_t)row * CDIM;
    float* rp = xres + (size_t)t * CDIM;
    float v[6];
    float s = 0.f, s2 = 0.f;
#pragma unroll
    for (int i = 0; i < 6; i++) {
        int c = lane + i * 32;
        v[i] = xp[c] + pp[c];
        rp[c] = v[i];
        s += v[i]; s2 += v[i] * v[i];
    }
    s = warpSum(s); s2 = warpSum(s2);
    float mean = s * (1.0f / CDIM);
    float rstd = rsqrtf(s2 * (1.0f / CDIM) - mean * mean + 1e-5f);
    __nv_bfloat16* op = ln2o + (size_t)t * CDIM;
#pragma unroll
    for (int i = 0; i < 6; i++) {
        int c = lane + i * 32;
        op[c] = __float2bfloat16((v[i] - mean) * rstd * g[c] + b[c]);
    }
}

// ---------------- launch ----------------
extern "C" void kernel_launch(void* const* d_in, const int* in_sizes, int n_in,
                              void* d_out, int out_size) {
    (void)in_sizes; (void)n_in; (void)out_size;
    const float* x       = (const float*)d_in[0];
    const float* table   = (const float*)d_in[3];
    const float* n1g     = (const float*)d_in[4];
    const float* n1b     = (const float*)d_in[5];
    const float* qkv_w   = (const float*)d_in[6];
    const float* qkv_b   = (const float*)d_in[7];
    const float* proj_w  = (const float*)d_in[8];
    const float* proj_b  = (const float*)d_in[9];
    const float* n2g     = (const float*)d_in[10];
    const float* n2b     = (const float*)d_in[11];
    const float* fc1_w   = (const float*)d_in[12];
    const float* fc1_b   = (const float*)d_in[13];
    const float* fc2_w   = (const float*)d_in[14];
    const float* fc2_b   = (const float*)d_in[15];
    float* out = (float*)d_out;

    __nv_bfloat16 *xwb, *qkvb, *attnb, *ln2b, *h1b, *wqkv, *wproj, *wfc1, *wfc2, *comb;
    float *proj, *xres;
    cudaGetSymbolAddress((void**)&xwb,   g_xwb);
    cudaGetSymbolAddress((void**)&qkvb,  g_qkvb);
    cudaGetSymbolAddress((void**)&attnb, g_attnb);
    cudaGetSymbolAddress((void**)&proj,  g_proj);
    cudaGetSymbolAddress((void**)&xres,  g_xres);
    cudaGetSymbolAddress((void**)&ln2b,  g_ln2b);
    cudaGetSymbolAddress((void**)&h1b,   g_h1b);
    cudaGetSymbolAddress((void**)&wqkv,  g_wqkv);
    cudaGetSymbolAddress((void**)&wproj, g_wproj);
    cudaGetSymbolAddress((void**)&wfc1,  g_wfc1);
    cudaGetSymbolAddress((void**)&wfc2,  g_wfc2);
    cudaGetSymbolAddress((void**)&comb,  g_comb);

    cudaFuncSetAttribute(attn_tc_kernel, cudaFuncAttributeMaxDynamicSharedMemorySize,
                         ATTN_SMEM_BYTES);
    cudaFuncSetAttribute((gemm_mma_kernel<3, true>), cudaFuncAttributeMaxDynamicSharedMemorySize, GEMM_SMEM_BYTES);
    cudaFuncSetAttribute((gemm_mma_kernel<0, true>), cudaFuncAttributeMaxDynamicSharedMemorySize, GEMM_SMEM_BYTES);
    cudaFuncSetAttribute((gemm_mma_kernel<1, true>), cudaFuncAttributeMaxDynamicSharedMemorySize, GEMM_SMEM_BYTES);
    cudaFuncSetAttribute((gemm_mma_kernel<2, false>), cudaFuncAttributeMaxDynamicSharedMemorySize, GEMM_SMEM_BYTES);

    const int n0 = 3 * CDIM * CDIM, n1 = CDIM * CDIM, n2 = HID * CDIM, n3 = CDIM * HID;
    cvt4_kernel<<<(n0 + n1 + n2 + n3 + 255) / 256, 256>>>(
        qkv_w, wqkv, n0, proj_w, wproj, n1, fc1_w, wfc1, n2, fc2_w, wfc2, n3);
    comb_pre_kernel<<<(COMB_ELEMS + 255) / 256, 256>>>(table, comb);

    ln1_kernel<<<TOK / 8, 256>>>(x, n1g, n1b, xwb);
    // QKV: N=576 (padded 640)
    gemm_mma_kernel<3, true><<<dim3(NQKV_P / BN, TOK / BM), 256, GEMM_SMEM_BYTES>>>(
        xwb, wqkv, qkv_b, nullptr, qkvb, CDIM, 3 * CDIM);
    attn_tc_kernel<<<TOTWIN * HEADS, 256, ATTN_SMEM_BYTES>>>(qkvb, comb, attnb);
    // proj: N=192 (padded 256)
    gemm_mma_kernel<0, true><<<dim3(NPROJ_P / BN, TOK / BM), 256, GEMM_SMEM_BYTES>>>(
        attnb, wproj, proj_b, nullptr, proj, CDIM, CDIM);
    ln2res_kernel<<<TOK / 8, 256>>>(x, proj, n2g, n2b, xres, ln2b);
    // FC1: N=768
    gemm_mma_kernel<1, true><<<dim3(HID / BN, TOK / BM), 256, GEMM_SMEM_BYTES>>>(
        ln2b, wfc1, fc1_b, nullptr, h1b, CDIM, HID);
    // FC2: K=768, N=192 (padded 256)
    gemm_mma_kernel<2, false><<<dim3(NFC2_P / BN, TOK / BM), 256, GEMM_SMEM_BYTES>>>(
        h1b, wfc2, fc2_b, xres, out, HID, CDIM);
}

// round 9
// speedup vs baseline: 1.0433x; 1.0433x over previous
#include <cuda_runtime.h>
#include <cuda_bf16.h>
#include <math.h>
#include <stdint.h>

// ---------------- problem constants ----------------
#define BATCH   2
#define DSZ     28
#define WS      7
#define SHIFT_  3
#define CDIM    192
#define HEADS   6
#define HD      32
#define NTOK    343
#define NWIN    64
#define TOTWIN  128
#define TOK     43904
#define HID     768
#define SCALE   0.17677669529663687f

// GEMM tiling (round-7 config: CTA 128x64, warp 32x32)
#define BM      128
#define BN      64
#define KB      64
#define GEMM_SMEM_BYTES 73728

// attention tiling
#define QT      64
#define NC      64
#define KPAD    384
#define NCH     6
#define QPITCH  80
#define KPITCH  80
#define VPITCH  784
#define PPITCH  144
#define CPITCH  344
// smem offsets (bytes)
#define AOFF_K   0
#define AOFF_V   30720
#define AOFF_Q   55808
#define AOFF_P   60928
#define AOFF_RS  70144
#define ATTN_SMEM_BYTES 70656

#define COMB_ELEMS (48 * NTOK * CPITCH)

// ---------------- scratch (device globals) ----------------
__device__ __nv_bfloat16 g_xwb [TOK * CDIM];
__device__ __nv_bfloat16 g_qkvb[TOK * 3 * CDIM];
__device__ __nv_bfloat16 g_attnb[TOK * CDIM];
__device__ float         g_proj[TOK * CDIM];
__device__ float         g_xres[TOK * CDIM];
__device__ __nv_bfloat16 g_ln2b[TOK * CDIM];
__device__ __nv_bfloat16 g_h1b [TOK * HID];
__device__ __nv_bfloat16 g_wqkv[3 * CDIM * CDIM];
__device__ __nv_bfloat16 g_wproj[CDIM * CDIM];
__device__ __nv_bfloat16 g_wfc1[HID * CDIM];
__device__ __nv_bfloat16 g_wfc2[CDIM * HID];
__device__ __nv_bfloat16 g_comb[COMB_ELEMS];   // [head][maskclass][row][colpad]

// ---------------- helpers ----------------
__device__ __forceinline__ uint32_t s2u(const void* p) {
    uint32_t r;
    asm("{ .reg .u64 t; cvta.to.shared.u64 t, %1; cvt.u32.u64 %0, t; }" : "=r"(r) : "l"(p));
    return r;
}
__device__ __forceinline__ float warpSum(float v) {
#pragma unroll
    for (int o = 16; o; o >>= 1) v += __shfl_xor_sync(0xffffffffu, v, o);
    return v;
}
__device__ __forceinline__ int token_to_winrow(int t) {
    int b   = t / (DSZ * DSZ * DSZ);
    int rem = t - b * (DSZ * DSZ * DSZ);
    int dd  = rem / (DSZ * DSZ);
    int hh  = (rem / DSZ) % DSZ;
    int ww  = rem % DSZ;
    int i = (dd + DSZ - SHIFT_) % DSZ;
    int j = (hh + DSZ - SHIFT_) % DSZ;
    int k = (ww + DSZ - SHIFT_) % DSZ;
    int win = (i / WS) * 16 + (j / WS) * 4 + (k / WS);
    int n   = (i % WS) * 49 + (j % WS) * 7 + (k % WS);
    return (b * NWIN + win) * NTOK + n;
}

#define CP_ASYNC16(dst_u32, src_ptr) \
    asm volatile("cp.async.cg.shared.global [%0], [%1], 16;" :: "r"(dst_u32), "l"(src_ptr))
#define CP_COMMIT() asm volatile("cp.async.commit_group;")
#define CP_WAIT(n)  asm volatile("cp.async.wait_group %0;" :: "n"(n))

#define LDMX4(r0, r1, r2, r3, addr) \
    asm volatile("ldmatrix.sync.aligned.m8n8.x4.shared.b16 {%0,%1,%2,%3}, [%4];" \
                 : "=r"(r0), "=r"(r1), "=r"(r2), "=r"(r3) : "r"(addr))

#define MMA16816(d, a0, a1, a2, a3, b0, b1) \
    asm volatile("mma.sync.aligned.m16n8k16.row.col.f32.bf16.bf16.f32 " \
                 "{%0,%1,%2,%3}, {%4,%5,%6,%7}, {%8,%9}, {%0,%1,%2,%3};" \
                 : "+f"((d)[0]), "+f"((d)[1]), "+f"((d)[2]), "+f"((d)[3]) \
                 : "r"(a0), "r"(a1), "r"(a2), "r"(a3), "r"(b0), "r"(b1))

// ---------------- merged weight conversion ----------------
__global__ void cvt4_kernel(const float* __restrict__ s0, __nv_bfloat16* __restrict__ d0, int n0,
                            const float* __restrict__ s1, __nv_bfloat16* __restrict__ d1, int n1,
                            const float* __restrict__ s2, __nv_bfloat16* __restrict__ d2, int n2,
                            const float* __restrict__ s3, __nv_bfloat16* __restrict__ d3, int n3) {
    int i = blockIdx.x * 256 + threadIdx.x;
    if (i < n0) { d0[i] = __float2bfloat16(s0[i]); return; }
    i -= n0;
    if (i < n1) { d1[i] = __float2bfloat16(s1[i]); return; }
    i -= n1;
    if (i < n2) { d2[i] = __float2bfloat16(s2[i]); return; }
    i -= n2;
    if (i < n3) { d3[i] = __float2bfloat16(s3[i]); }
}

// ---------------- combined bias+mask precompute ----------------
__global__ void comb_pre_kernel(const float* __restrict__ table,
                                __nv_bfloat16* __restrict__ comb) {
    int idx = blockIdx.x * 256 + threadIdx.x;
    if (idx >= COMB_ELEMS) return;
    int col  = idx % CPITCH;
    int rest = idx / CPITCH;
    int row  = rest % NTOK;
    int hc   = rest / NTOK;
    int h = hc >> 3, cls = hc & 7;
    float val = -100.f;
    if (col < NTOK) {
        int i3 = row / 49, j3 = (row / 7) % 7, k3 = row % 7;
        int ci = col / 49, cj = (col / 7) % 7, ck = col % 7;
        int rel = (i3 - ci + 6) * 169 + (j3 - cj + 6) * 13 + (k3 - ck + 6);
        val = table[rel * HEADS + h];
        bool diff = ((cls & 4) && ((i3 < 4) != (ci < 4))) ||
                    ((cls & 2) && ((j3 < 4) != (cj < 4))) ||
                    ((cls & 1) && ((k3 < 4) != (ck < 4)));
        if (diff) val -= 100.f;
    }
    comb[idx] = __float2bfloat16(val);
}

// ---------------- LN1 + shift + partition: warp-per-token ----------------
__global__ __launch_bounds__(256) void ln1_kernel(const float* __restrict__ x,
                                                  const float* __restrict__ g,
                                                  const float* __restrict__ b,
                                                  __nv_bfloat16* __restrict__ xw) {
    int t = blockIdx.x * 8 + (threadIdx.x >> 5);
    int lane = threadIdx.x & 31;
    const float* xp = x + (size_t)t * CDIM;
    float v[6];
    float s = 0.f, s2 = 0.f;
#pragma unroll
    for (int i = 0; i < 6; i++) {
        v[i] = xp[lane + i * 32];
        s += v[i]; s2 += v[i] * v[i];
    }
    s = warpSum(s); s2 = warpSum(s2);
    float mean = s * (1.0f / CDIM);
    float rstd = rsqrtf(s2 * (1.0f / CDIM) - mean * mean + 1e-5f);
    int row = token_to_winrow(t);
    __nv_bfloat16* op = xw + (size_t)row * CDIM;
#pragma unroll
    for (int i = 0; i < 6; i++) {
        int c = lane + i * 32;
        op[c] = __float2bfloat16((v[i] - mean) * rstd * g[c] + b[c]);
    }
}

// ---------------- GEMM tile loader ----------------
__device__ __forceinline__ void gemm_issue(const __nv_bfloat16* __restrict__ A,
                                           const __nv_bfloat16* __restrict__ Wt,
                                           int bm, int bn, int Ktot, int lr, int lc8,
                                           char* bA, char* bB, int k0) {
#pragma unroll
    for (int rr = 0; rr < 4; rr++) {
        int r = lr + rr * 32;
        uint32_t off = (uint32_t)(r * 128 + lc8 * 2);
        off ^= (off >> 3) & 0x70;
        CP_ASYNC16(s2u(bA + off), A + (size_t)(bm + r) * Ktot + k0 + lc8);
    }
#pragma unroll
    for (int rr = 0; rr < 2; rr++) {
        int br = lr + rr * 32;
        uint32_t off = (uint32_t)(br * 128 + lc8 * 2);
        off ^= (off >> 3) & 0x70;
        CP_ASYNC16(s2u(bB + off), Wt + (size_t)(bn + br) * Ktot + k0 + lc8);
    }
    CP_COMMIT();
}

// ---------------- HMMA bf16 GEMM (round-7 tiles, progressive FULLK waits) ----------------
// EPI: 0 = bias -> fp32; 1 = bias+gelu -> bf16; 2 = bias+resid -> fp32; 3 = bias -> bf16
template <int EPI, bool FULLK>
__global__ __launch_bounds__(256)
void gemm_mma_kernel(const __nv_bfloat16* __restrict__ A,
                     const __nv_bfloat16* __restrict__ Wt,
                     const float* __restrict__ bias,
                     const float* __restrict__ resid,
                     void* __restrict__ Cv, int Ktot, int Ntot)
{
    extern __shared__ __align__(1024) char dsm[];
    char* bufA[3] = {dsm, dsm + 16384, dsm + 32768};
    char* bufB[3] = {dsm + 49152, dsm + 57344, dsm + 65536};

    const int tid = threadIdx.x;
    const int lane = tid & 31;
    const int wid = tid >> 5;
    const int wm = (wid & 3) * 32;
    const int wn = (wid >> 2) * 32;
    const int bm = blockIdx.y * BM;
    const int bn = blockIdx.x * BN;

    float acc[2][4][4];
#pragma unroll
    for (int a = 0; a < 2; a++)
#pragma unroll
        for (int b = 0; b < 4; b++)
#pragma unroll
            for (int c = 0; c < 4; c++) acc[a][b][c] = 0.f;

    const int lr = tid >> 3;
    const int lc8 = (tid & 7) * 8;

    if (FULLK) {
        // issue all three chunks; compute progressively as each lands
#pragma unroll
        for (int ch = 0; ch < 3; ch++)
            gemm_issue(A, Wt, bm, bn, Ktot, lr, lc8, bufA[ch], bufB[ch], ch * KB);
#pragma unroll
        for (int chunk = 0; chunk < 3; chunk++) {
            if (chunk == 0)      CP_WAIT(2);
            else if (chunk == 1) CP_WAIT(1);
            else                 CP_WAIT(0);
            __syncthreads();
            const uint32_t sA = s2u(bufA[chunk]);
            const uint32_t sB = s2u(bufB[chunk]);
#pragma unroll
            for (int kk = 0; kk < 4; kk++) {
                uint32_t a0[2], a1[2], a2[2], a3[2];
#pragma unroll
                for (int mi = 0; mi < 2; mi++) {
                    uint32_t off = (uint32_t)((wm + mi * 16 + (lane & 15)) * 128 + kk * 32 + (lane >> 4) * 16);
                    off ^= (off >> 3) & 0x70;
                    LDMX4(a0[mi], a1[mi], a2[mi], a3[mi], sA + off);
                }
#pragma unroll
                for (int nj = 0; nj < 2; nj++) {
                    uint32_t off = (uint32_t)((wn + nj * 16 + (lane & 15)) * 128 + kk * 32 + (lane >> 4) * 16);
                    off ^= (off >> 3) & 0x70;
                    uint32_t r0, r1, r2, r3;
                    LDMX4(r0, r1, r2, r3, sB + off);
#pragma unroll
                    for (int mi = 0; mi < 2; mi++) {
                        MMA16816(acc[mi][2 * nj], a0[mi], a1[mi], a2[mi], a3[mi], r0, r2);
                        MMA16816(acc[mi][2 * nj + 1], a0[mi], a1[mi], a2[mi], a3[mi], r1, r3);
                    }
                }
            }
        }
    } else {
        const int nch = Ktot / KB;
        gemm_issue(A, Wt, bm, bn, Ktot, lr, lc8, bufA[0], bufB[0], 0);
        gemm_issue(A, Wt, bm, bn, Ktot, lr, lc8, bufA[1], bufB[1], KB);
        for (int ch = 0; ch < nch; ch++) {
            if (ch + 2 < nch)
                gemm_issue(A, Wt, bm, bn, Ktot, lr, lc8,
                           bufA[(ch + 2) % 3], bufB[(ch + 2) % 3], (ch + 2) * KB);
            const int rem = nch - ch - 1;
            if (rem >= 2)      CP_WAIT(2);
            else if (rem == 1) CP_WAIT(1);
            else               CP_WAIT(0);
            __syncthreads();

            const uint32_t sA = s2u(bufA[ch % 3]);
            const uint32_t sB = s2u(bufB[ch % 3]);
#pragma unroll
            for (int kk = 0; kk < KB / 16; kk++) {
                uint32_t a0[2], a1[2], a2[2], a3[2];
#pragma unroll
                for (int mi = 0; mi < 2; mi++) {
                    uint32_t off = (uint32_t)((wm + mi * 16 + (lane & 15)) * 128 + kk * 32 + (lane >> 4) * 16);
                    off ^= (off >> 3) & 0x70;
                    LDMX4(a0[mi], a1[mi], a2[mi], a3[mi], sA + off);
                }
#pragma unroll
                for (int nj = 0; nj < 2; nj++) {
                    uint32_t off = (uint32_t)((wn + nj * 16 + (lane & 15)) * 128 + kk * 32 + (lane >> 4) * 16);
                    off ^= (off >> 3) & 0x70;
                    uint32_t r0, r1, r2, r3;
                    LDMX4(r0, r1, r2, r3, sB + off);
#pragma unroll
                    for (int mi = 0; mi < 2; mi++) {
                        MMA16816(acc[mi][2 * nj], a0[mi], a1[mi], a2[mi], a3[mi], r0, r2);
                        MMA16816(acc[mi][2 * nj + 1], a0[mi], a1[mi], a2[mi], a3[mi], r1, r3);
                    }
                }
            }
            __syncthreads();
        }
    }

    const int gq = lane >> 2;
    const int tg = lane & 3;
#pragma unroll
    for (int mi = 0; mi < 2; mi++) {
#pragma unroll
        for (int ni = 0; ni < 4; ni++) {
            int col = bn + wn + ni * 8 + tg * 2;
            float bia0 = bias[col], bia1 = bias[col + 1];
#pragma unroll
            for (int half = 0; half < 2; half++) {
                int row = bm + wm + mi * 16 + gq + half * 8;
                float v0 = acc[mi][ni][half * 2 + 0] + bia0;
                float v1 = acc[mi][ni][half * 2 + 1] + bia1;
                size_t oi = (size_t)row * Ntot + col;
                if (EPI == 1) {
                    v0 = 0.5f * v0 * (1.0f + erff(v0 * 0.7071067811865476f));
                    v1 = 0.5f * v1 * (1.0f + erff(v1 * 0.7071067811865476f));
                    __nv_bfloat162 p;
                    p.x = __float2bfloat16(v0); p.y = __float2bfloat16(v1);
                    *(__nv_bfloat162*)((__nv_bfloat16*)Cv + oi) = p;
                } else if (EPI == 2) {
                    float2 rv = *(const float2*)(resid + oi);
                    float2 o; o.x = v0 + rv.x; o.y = v1 + rv.y;
                    *(float2*)((float*)Cv + oi) = o;
                } else if (EPI == 3) {
                    __nv_bfloat162 p;
                    p.x = __float2bfloat16(v0); p.y = __float2bfloat16(v1);
                    *(__nv_bfloat162*)((__nv_bfloat16*)Cv + oi) = p;
                } else {
                    float2 o; o.x = v0; o.y = v1;
                    *(float2*)((float*)Cv + oi) = o;
                }
            }
        }
    }
}

// ---------------- tensor-core attention (round-7: grid (768, 6)) ----------------
__global__ __launch_bounds__(256, 3) void attn_tc_kernel(
    const __nv_bfloat16* __restrict__ qkv, const __nv_bfloat16* __restrict__ comb,
    __nv_bfloat16* __restrict__ out)
{
    extern __shared__ __align__(1024) char sm[];
    const uint32_t uK = s2u(sm + AOFF_K);
    const uint32_t uV = s2u(sm + AOFF_V);
    const uint32_t uQ = s2u(sm + AOFF_Q);
    const uint32_t uP = s2u(sm + AOFF_P);
    float* rs = (float*)(sm + AOFF_RS);

    const int bx = blockIdx.x;
    const int w  = bx / HEADS;
    const int h  = bx - w * HEADS;
    const int mw = w % NWIN;
    const int wd = mw >> 4, wh = (mw >> 2) & 3, ww = mw & 3;
    const int cls = ((wd == 3) << 2) | ((wh == 3) << 1) | (ww == 3);
    const int q0 = blockIdx.y * QT;
    const int tid = threadIdx.x;
    const int lane = tid & 31;
    const int wid = tid >> 5;

    const __nv_bfloat16* base = qkv + (size_t)w * NTOK * (3 * CDIM);

    for (int idx = tid; idx < KPAD * 4; idx += 256) {
        int j = idx >> 2, s = idx & 3;
        uint4 v = make_uint4(0, 0, 0, 0);
        if (j < NTOK) v = *(const uint4*)(base + (size_t)j * (3 * CDIM) + CDIM + h * HD + s * 8);
        *(uint4*)(sm + AOFF_K + j * KPITCH + s * 16) = v;
    }
    for (int idx = tid; idx < QT * 4; idx += 256) {
        int r = idx >> 2, s = idx & 3;
        int gq = q0 + r;
        uint4 v = make_uint4(0, 0, 0, 0);
        if (gq < NTOK) v = *(const uint4*)(base + (size_t)gq * (3 * CDIM) + h * HD + s * 8);
        *(uint4*)(sm + AOFF_Q + r * QPITCH + s * 16) = v;
    }
    for (int jp = tid; jp < KPAD / 2; jp += 256) {
        int j0 = jp * 2;
        __nv_bfloat16 ta[32], tb[32];
        if (j0 < NTOK) {
            const __nv_bfloat16* vp = base + (size_t)j0 * (3 * CDIM) + 2 * CDIM + h * HD;
#pragma unroll
            for (int s = 0; s < 4; s++) *(uint4*)(ta + s * 8) = *(const uint4*)(vp + s * 8);
        } else {
#pragma unroll
            for (int d = 0; d < 32; d++) ta[d] = __float2bfloat16(0.f);
        }
        if (j0 + 1 < NTOK) {
            const __nv_bfloat16* vp = base + (size_t)(j0 + 1) * (3 * CDIM) + 2 * CDIM + h * HD;
#pragma unroll
            for (int s = 0; s < 4; s++) *(uint4*)(tb + s * 8) = *(const uint4*)(vp + s * 8);
        } else {
#pragma unroll
            for (int d = 0; d < 32; d++) tb[d] = __float2bfloat16(0.f);
        }
#pragma unroll
        for (int d = 0; d < 32; d++) {
            __nv_bfloat162 p; p.x = ta[d]; p.y = tb[d];
            *(__nv_bfloat162*)(sm + AOFF_V + d * VPITCH + j0 * 2) = p;
        }
    }
    __syncthreads();

    const int wm = wid & 3, wn = wid >> 2;
    const int vm = wid & 1, vn = wid >> 1;
    const int gq_ = lane >> 2, tg = lane & 3;

    float acc_o[2][4];
#pragma unroll
    for (int t = 0; t < 2; t++)
#pragma unroll
        for (int c = 0; c < 4; c++) acc_o[t][c] = 0.f;
    float rs0 = 0.f, rs1 = 0.f;

    const int r0g = q0 + wm * 16 + gq_;
    const int r1g = r0g + 8;
    const bool v0 = (r0g < NTOK);
    const bool v1 = (r1g < NTOK);
    const __nv_bfloat16* cb = comb + (size_t)(h * 8 + cls) * NTOK * CPITCH;
    const __nv_bfloat16* c0p = cb + (size_t)r0g * CPITCH;
    const __nv_bfloat16* c1p = cb + (size_t)r1g * CPITCH;

    for (int ch = 0; ch < NCH; ch++) {
        const int j0 = ch * NC;
        float acc[4][4];
#pragma unroll
        for (int t = 0; t < 4; t++)
#pragma unroll
            for (int c = 0; c < 4; c++) acc[t][c] = 0.f;

#pragma unroll
        for (int ks = 0; ks < 2; ks++) {
            uint32_t a0, a1, a2, a3;
            LDMX4(a0, a1, a2, a3,
                  uQ + (uint32_t)((wm * 16 + (lane & 15)) * QPITCH + ks * 32 + (lane >> 4) * 16));
#pragma unroll
            for (int nj = 0; nj < 2; nj++) {
                uint32_t r0, r1, r2, r3;
                LDMX4(r0, r1, r2, r3,
                      uK + (uint32_t)((j0 + wn * 32 + nj * 16 + (lane & 15)) * KPITCH + ks * 32 + (lane >> 4) * 16));
                MMA16816(acc[2 * nj], a0, a1, a2, a3, r0, r2);
                MMA16816(acc[2 * nj + 1], a0, a1, a2, a3, r1, r3);
            }
        }

#pragma unroll
        for (int ti = 0; ti < 4; ti++) {
            int jl = wn * 32 + (ti >> 1) * 16 + (ti & 1) * 8 + tg * 2;
            int ja = j0 + jl;
            float e00 = 0.f, e01 = 0.f, e10 = 0.f, e11 = 0.f;
            if (ja < NTOK) {
                if (v0) {
                    __nv_bfloat162 bp = *(const __nv_bfloat162*)(c0p + ja);
                    e00 = __expf(fmaf(acc[ti][0], SCALE, __bfloat162float(bp.x)));
                    e01 = __expf(fmaf(acc[ti][1], SCALE, __bfloat162float(bp.y)));
                }
                if (v1) {
                    __nv_bfloat162 bp = *(const __nv_bfloat162*)(c1p + ja);
                    e10 = __expf(fmaf(acc[ti][2], SCALE, __bfloat162float(bp.x)));
                    e11 = __expf(fmaf(acc[ti][3], SCALE, __bfloat162float(bp.y)));
                }
            }
            rs0 += e00 + e01;
            rs1 += e10 + e11;
            __nv_bfloat162 p0, p1;
            p0.x = __float2bfloat16(e00); p0.y = __float2bfloat16(e01);
            p1.x = __float2bfloat16(e10); p1.y = __float2bfloat16(e11);
            int rloc0 = wm * 16 + gq_;
            *(__nv_bfloat162*)(sm + AOFF_P + rloc0 * PPITCH + jl * 2) = p0;
            *(__nv_bfloat162*)(sm + AOFF_P + (rloc0 + 8) * PPITCH + jl * 2) = p1;
        }
        __syncthreads();

#pragma unroll
        for (int kk = 0; kk < 4; kk++) {
            uint32_t a0, a1, a2, a3;
            LDMX4(a0, a1, a2, a3,
                  uV + (uint32_t)((vm * 16 + (lane & 15)) * VPITCH + j0 * 2 + kk * 32 + (lane >> 4) * 16));
            uint32_t r0, r1, r2, r3;
            LDMX4(r0, r1, r2, r3,
                  uP + (uint32_t)((vn * 16 + (lane & 15)) * PPITCH + kk * 32 + (lane >> 4) * 16));
            MMA16816(acc_o[0], a0, a1, a2, a3, r0, r2);
            MMA16816(acc_o[1], a0, a1, a2, a3, r1, r3);
        }
        __syncthreads();
    }

    rs0 += __shfl_xor_sync(0xffffffffu, rs0, 1);
    rs0 += __shfl_xor_sync(0xffffffffu, rs0, 2);
    rs1 += __shfl_xor_sync(0xffffffffu, rs1, 1);
    rs1 += __shfl_xor_sync(0xffffffffu, rs1, 2);
    if (tg == 0) {
        rs[(wm * 16 + gq_) * 2 + wn] = rs0;
        rs[(wm * 16 + gq_ + 8) * 2 + wn] = rs1;
    }

    float* Ost = (float*)(sm + AOFF_P);
#pragma unroll
    for (int t = 0; t < 2; t++) {
        int qc = vn * 16 + t * 8 + tg * 2;
        int d0 = vm * 16 + gq_;
        Ost[d0 * 65 + qc]     = acc_o[t][0];
        Ost[d0 * 65 + qc + 1] = acc_o[t][1];
        Ost[(d0 + 8) * 65 + qc]     = acc_o[t][2];
        Ost[(d0 + 8) * 65 + qc + 1] = acc_o[t][3];
    }
    __syncthreads();

    {
        int q = tid >> 2, ds = (tid & 3) * 8;
        int gq = q0 + q;
        if (gq < NTOK) {
            float inv = __frcp_rn(rs[q * 2] + rs[q * 2 + 1]);
            __nv_bfloat16 o[8];
#pragma unroll
            for (int u = 0; u < 8; u++)
                o[u] = __float2bfloat16(Ost[(ds + u) * 65 + q] * inv);
            *(uint4*)(out + (size_t)(w * NTOK + gq) * CDIM + h * HD + ds) = *(uint4*)o;
        }
    }
}

// ---------------- reverse + residual + LN2: warp-per-token ----------------
__global__ __launch_bounds__(256) void ln2res_kernel(const float* __restrict__ x,
                                                     const float* __restrict__ proj,
                                                     const float* __restrict__ g,
                                                     const float* __restrict__ b,
                                                     float* __restrict__ xres,
                                                     __nv_bfloat16* __restrict__ ln2o) {
    int t = blockIdx.x * 8 + (threadIdx.x >> 5);
    int lane = threadIdx.x & 31;
    int row = token_to_winrow(t);
    const float* xp = x + (size_t)t * CDIM;
    const float* pp = proj + (size_t)row * CDIM;
    float* rp = xres + (size_t)t * CDIM;
    float v[6];
    float s = 0.f, s2 = 0.f;
#pragma unroll
    for (int i = 0; i < 6; i++) {
        int c = lane + i * 32;
        v[i] = xp[c] + pp[c];
        rp[c] = v[i];
        s += v[i]; s2 += v[i] * v[i];
    }
    s = warpSum(s); s2 = warpSum(s2);
    float mean = s * (1.0f / CDIM);
    float rstd = rsqrtf(s2 * (1.0f / CDIM) - mean * mean + 1e-5f);
    __nv_bfloat16* op = ln2o + (size_t)t * CDIM;
#pragma unroll
    for (int i = 0; i < 6; i++) {
        int c = lane + i * 32;
        op[c] = __float2bfloat16((v[i] - mean) * rstd * g[c] + b[c]);
    }
}

// ---------------- launch ----------------
extern "C" void kernel_launch(void* const* d_in, const int* in_sizes, int n_in,
                              void* d_out, int out_size) {
    (void)in_sizes; (void)n_in; (void)out_size;
    const float* x       = (const float*)d_in[0];
    const float* table   = (const float*)d_in[3];
    const float* n1g     = (const float*)d_in[4];
    const float* n1b     = (const float*)d_in[5];
    const float* qkv_w   = (const float*)d_in[6];
    const float* qkv_b   = (const float*)d_in[7];
    const float* proj_w  = (const float*)d_in[8];
    const float* proj_b  = (const float*)d_in[9];
    const float* n2g     = (const float*)d_in[10];
    const float* n2b     = (const float*)d_in[11];
    const float* fc1_w   = (const float*)d_in[12];
    const float* fc1_b   = (const float*)d_in[13];
    const float* fc2_w   = (const float*)d_in[14];
    const float* fc2_b   = (const float*)d_in[15];
    float* out = (float*)d_out;

    __nv_bfloat16 *xwb, *qkvb, *attnb, *ln2b, *h1b, *wqkv, *wproj, *wfc1, *wfc2, *comb;
    float *proj, *xres;
    cudaGetSymbolAddress((void**)&xwb,   g_xwb);
    cudaGetSymbolAddress((void**)&qkvb,  g_qkvb);
    cudaGetSymbolAddress((void**)&attnb, g_attnb);
    cudaGetSymbolAddress((void**)&proj,  g_proj);
    cudaGetSymbolAddress((void**)&xres,  g_xres);
    cudaGetSymbolAddress((void**)&ln2b,  g_ln2b);
    cudaGetSymbolAddress((void**)&h1b,   g_h1b);
    cudaGetSymbolAddress((void**)&wqkv,  g_wqkv);
    cudaGetSymbolAddress((void**)&wproj, g_wproj);
    cudaGetSymbolAddress((void**)&wfc1,  g_wfc1);
    cudaGetSymbolAddress((void**)&wfc2,  g_wfc2);
    cudaGetSymbolAddress((void**)&comb,  g_comb);

    cudaFuncSetAttribute(attn_tc_kernel, cudaFuncAttributeMaxDynamicSharedMemorySize,
                         ATTN_SMEM_BYTES);
    cudaFuncSetAttribute((gemm_mma_kernel<3, true>), cudaFuncAttributeMaxDynamicSharedMemorySize, GEMM_SMEM_BYTES);
    cudaFuncSetAttribute((gemm_mma_kernel<0, true>), cudaFuncAttributeMaxDynamicSharedMemorySize, GEMM_SMEM_BYTES);
    cudaFuncSetAttribute((gemm_mma_kernel<1, true>), cudaFuncAttributeMaxDynamicSharedMemorySize, GEMM_SMEM_BYTES);
    cudaFuncSetAttribute((gemm_mma_kernel<2, false>), cudaFuncAttributeMaxDynamicSharedMemorySize, GEMM_SMEM_BYTES);

    const int n0 = 3 * CDIM * CDIM, n1 = CDIM * CDIM, n2 = HID * CDIM, n3 = CDIM * HID;
    cvt4_kernel<<<(n0 + n1 + n2 + n3 + 255) / 256, 256>>>(
        qkv_w, wqkv, n0, proj_w, wproj, n1, fc1_w, wfc1, n2, fc2_w, wfc2, n3);
    comb_pre_kernel<<<(COMB_ELEMS + 255) / 256, 256>>>(table, comb);

    ln1_kernel<<<TOK / 8, 256>>>(x, n1g, n1b, xwb);
    gemm_mma_kernel<3, true><<<dim3(576 / BN, TOK / BM), 256, GEMM_SMEM_BYTES>>>(
        xwb, wqkv, qkv_b, nullptr, qkvb, CDIM, 3 * CDIM);
    attn_tc_kernel<<<dim3(TOTWIN * HEADS, NCH), 256, ATTN_SMEM_BYTES>>>(qkvb, comb, attnb);
    gemm_mma_kernel<0, true><<<dim3(CDIM / BN, TOK / BM), 256, GEMM_SMEM_BYTES>>>(
        attnb, wproj, proj_b, nullptr, proj, CDIM, CDIM);
    ln2res_kernel<<<TOK / 8, 256>>>(x, proj, n2g, n2b, xres, ln2b);
    gemm_mma_kernel<1, true><<<dim3(HID / BN, TOK / BM), 256, GEMM_SMEM_BYTES>>>(
        ln2b, wfc1, fc1_b, nullptr, h1b, CDIM, HID);
    gemm_mma_kernel<2, false><<<dim3(CDIM / BN, TOK / BM), 256, GEMM_SMEM_BYTES>>>(
        h1b, wfc2, fc2_b, xres, out, HID, CDIM);
}

// round 10
// speedup vs baseline: 1.0696x; 1.0252x over previous
#include <cuda_runtime.h>
#include <cuda_bf16.h>
#include <math.h>
#include <stdint.h>

// ---------------- problem constants ----------------
#define BATCH   2
#define DSZ     28
#define WS      7
#define SHIFT_  3
#define CDIM    192
#define HEADS   6
#define HD      32
#define NTOK    343
#define NWIN    64
#define TOTWIN  128
#define TOK     43904
#define HID     768
#define SCALE   0.17677669529663687f
#define LOG2E   1.4426950408889634f
#define QFOLD   (SCALE * LOG2E)

// GEMM tiling (CTA 128x64, warp 32x32)
#define BM      128
#define BN      64
#define KB      64
#define GEMM_SMEM_BYTES 73728

// attention tiling
#define QT      64
#define NC      64
#define KPAD    384
#define NCH     6
#define QPITCH  80
#define KPITCH  80
#define VPITCH  784
#define PPITCH  144
#define CPITCH  384
// smem offsets (bytes)
#define AOFF_K   0
#define AOFF_V   30720
#define AOFF_Q   55808
#define AOFF_P   60928
#define AOFF_RS  70144
#define ATTN_SMEM_BYTES 70656

#define COMB_ELEMS (48 * CPITCH * CPITCH)   // padded rows AND cols to 384

// ---------------- scratch (device globals) ----------------
__device__ __nv_bfloat16 g_xwb [TOK * CDIM];
__device__ __nv_bfloat16 g_qkvb[TOK * 3 * CDIM];
__device__ __nv_bfloat16 g_attnb[TOK * CDIM];
__device__ float         g_proj[TOK * CDIM];
__device__ float         g_xres[TOK * CDIM];
__device__ __nv_bfloat16 g_ln2b[TOK * CDIM];
__device__ __nv_bfloat16 g_h1b [TOK * HID];
__device__ __nv_bfloat16 g_wqkv[3 * CDIM * CDIM];
__device__ __nv_bfloat16 g_wproj[CDIM * CDIM];
__device__ __nv_bfloat16 g_wfc1[HID * CDIM];
__device__ __nv_bfloat16 g_wfc2[CDIM * HID];
__device__ __nv_bfloat16 g_comb[COMB_ELEMS];   // [head*8+cls][row][col] * log2e, padded
__device__ float         g_qbias[3 * CDIM];    // qkv bias with q-part scaled

// ---------------- helpers ----------------
__device__ __forceinline__ uint32_t s2u(const void* p) {
    uint32_t r;
    asm("{ .reg .u64 t; cvta.to.shared.u64 t, %1; cvt.u32.u64 %0, t; }" : "=r"(r) : "l"(p));
    return r;
}
__device__ __forceinline__ float warpSum(float v) {
#pragma unroll
    for (int o = 16; o; o >>= 1) v += __shfl_xor_sync(0xffffffffu, v, o);
    return v;
}
__device__ __forceinline__ int token_to_winrow(int t) {
    int b   = t / (DSZ * DSZ * DSZ);
    int rem = t - b * (DSZ * DSZ * DSZ);
    int dd  = rem / (DSZ * DSZ);
    int hh  = (rem / DSZ) % DSZ;
    int ww  = rem % DSZ;
    int i = (dd + DSZ - SHIFT_) % DSZ;
    int j = (hh + DSZ - SHIFT_) % DSZ;
    int k = (ww + DSZ - SHIFT_) % DSZ;
    int win = (i / WS) * 16 + (j / WS) * 4 + (k / WS);
    int n   = (i % WS) * 49 + (j % WS) * 7 + (k % WS);
    return (b * NWIN + win) * NTOK + n;
}

#define CP_ASYNC16(dst_u32, src_ptr) \
    asm volatile("cp.async.cg.shared.global [%0], [%1], 16;" :: "r"(dst_u32), "l"(src_ptr))
#define CP_COMMIT() asm volatile("cp.async.commit_group;")
#define CP_WAIT(n)  asm volatile("cp.async.wait_group %0;" :: "n"(n))

#define LDMX4(r0, r1, r2, r3, addr) \
    asm volatile("ldmatrix.sync.aligned.m8n8.x4.shared.b16 {%0,%1,%2,%3}, [%4];" \
                 : "=r"(r0), "=r"(r1), "=r"(r2), "=r"(r3) : "r"(addr))

#define MMA16816(d, a0, a1, a2, a3, b0, b1) \
    asm volatile("mma.sync.aligned.m16n8k16.row.col.f32.bf16.bf16.f32 " \
                 "{%0,%1,%2,%3}, {%4,%5,%6,%7}, {%8,%9}, {%0,%1,%2,%3};" \
                 : "+f"((d)[0]), "+f"((d)[1]), "+f"((d)[2]), "+f"((d)[3]) \
                 : "r"(a0), "r"(a1), "r"(a2), "r"(a3), "r"(b0), "r"(b1))

// ---------------- merged weight conversion (q-rows folded) ----------------
__global__ void cvt4_kernel(const float* __restrict__ s0, __nv_bfloat16* __restrict__ d0, int n0,
                            const float* __restrict__ s1, __nv_bfloat16* __restrict__ d1, int n1,
                            const float* __restrict__ s2, __nv_bfloat16* __restrict__ d2, int n2,
                            const float* __restrict__ s3, __nv_bfloat16* __restrict__ d3, int n3) {
    int i = blockIdx.x * 256 + threadIdx.x;
    if (i < n0) {
        float v = s0[i];
        if (i < CDIM * CDIM) v *= QFOLD;    // q-projection rows
        d0[i] = __float2bfloat16(v);
        return;
    }
    i -= n0;
    if (i < n1) { d1[i] = __float2bfloat16(s1[i]); return; }
    i -= n1;
    if (i < n2) { d2[i] = __float2bfloat16(s2[i]); return; }
    i -= n2;
    if (i < n3) { d3[i] = __float2bfloat16(s3[i]); }
}

// ---------------- qkv bias folding ----------------
__global__ void biasq_kernel(const float* __restrict__ qkv_b, float* __restrict__ qb) {
    int i = blockIdx.x * 192 + threadIdx.x;
    if (i < 3 * CDIM) qb[i] = (i < CDIM) ? qkv_b[i] * QFOLD : qkv_b[i];
}

// ---------------- combined bias+mask precompute (log2e folded, 384x384 padded) ----------------
__global__ void comb_pre_kernel(const float* __restrict__ table,
                                __nv_bfloat16* __restrict__ comb) {
    int idx = blockIdx.x * 256 + threadIdx.x;
    if (idx >= COMB_ELEMS) return;
    int col  = idx % CPITCH;
    int row  = (idx / CPITCH) % CPITCH;
    int hc   = idx / (CPITCH * CPITCH);
    int h = hc >> 3, cls = hc & 7;
    float val = -160.f;
    if (col < NTOK && row < NTOK) {
        int i3 = row / 49, j3 = (row / 7) % 7, k3 = row % 7;
        int ci = col / 49, cj = (col / 7) % 7, ck = col % 7;
        int rel = (i3 - ci + 6) * 169 + (j3 - cj + 6) * 13 + (k3 - ck + 6);
        float v = table[rel * HEADS + h];
        bool diff = ((cls & 4) && ((i3 < 4) != (ci < 4))) ||
                    ((cls & 2) && ((j3 < 4) != (cj < 4))) ||
                    ((cls & 1) && ((k3 < 4) != (ck < 4)));
        if (diff) v -= 100.f;
        val = v * LOG2E;
    }
    comb[idx] = __float2bfloat16(val);
}

// ---------------- LN1 + shift + partition: warp-per-token ----------------
__global__ __launch_bounds__(256) void ln1_kernel(const float* __restrict__ x,
                                                  const float* __restrict__ g,
                                                  const float* __restrict__ b,
                                                  __nv_bfloat16* __restrict__ xw) {
    int t = blockIdx.x * 8 + (threadIdx.x >> 5);
    int lane = threadIdx.x & 31;
    const float* xp = x + (size_t)t * CDIM;
    float v[6];
    float s = 0.f, s2 = 0.f;
#pragma unroll
    for (int i = 0; i < 6; i++) {
        v[i] = xp[lane + i * 32];
        s += v[i]; s2 += v[i] * v[i];
    }
    s = warpSum(s); s2 = warpSum(s2);
    float mean = s * (1.0f / CDIM);
    float rstd = rsqrtf(s2 * (1.0f / CDIM) - mean * mean + 1e-5f);
    int row = token_to_winrow(t);
    __nv_bfloat16* op = xw + (size_t)row * CDIM;
#pragma unroll
    for (int i = 0; i < 6; i++) {
        int c = lane + i * 32;
        op[c] = __float2bfloat16((v[i] - mean) * rstd * g[c] + b[c]);
    }
}

// ---------------- GEMM tile loader ----------------
__device__ __forceinline__ void gemm_issue(const __nv_bfloat16* __restrict__ A,
                                           const __nv_bfloat16* __restrict__ Wt,
                                           int bm, int bn, int Ktot, int lr, int lc8,
                                           char* bA, char* bB, int k0) {
#pragma unroll
    for (int rr = 0; rr < 4; rr++) {
        int r = lr + rr * 32;
        uint32_t off = (uint32_t)(r * 128 + lc8 * 2);
        off ^= (off >> 3) & 0x70;
        CP_ASYNC16(s2u(bA + off), A + (size_t)(bm + r) * Ktot + k0 + lc8);
    }
#pragma unroll
    for (int rr = 0; rr < 2; rr++) {
        int br = lr + rr * 32;
        uint32_t off = (uint32_t)(br * 128 + lc8 * 2);
        off ^= (off >> 3) & 0x70;
        CP_ASYNC16(s2u(bB + off), Wt + (size_t)(bn + br) * Ktot + k0 + lc8);
    }
    CP_COMMIT();
}

// ---------------- HMMA bf16 GEMM ----------------
// EPI: 0 = bias -> fp32; 1 = bias+gelu -> bf16; 2 = bias+resid -> fp32; 3 = bias -> bf16
template <int EPI, bool FULLK>
__global__ __launch_bounds__(256)
void gemm_mma_kernel(const __nv_bfloat16* __restrict__ A,
                     const __nv_bfloat16* __restrict__ Wt,
                     const float* __restrict__ bias,
                     const float* __restrict__ resid,
                     void* __restrict__ Cv, int Ktot, int Ntot)
{
    extern __shared__ __align__(1024) char dsm[];
    char* bufA[3] = {dsm, dsm + 16384, dsm + 32768};
    char* bufB[3] = {dsm + 49152, dsm + 57344, dsm + 65536};

    const int tid = threadIdx.x;
    const int lane = tid & 31;
    const int wid = tid >> 5;
    const int wm = (wid & 3) * 32;
    const int wn = (wid >> 2) * 32;
    const int bm = blockIdx.y * BM;
    const int bn = blockIdx.x * BN;

    float acc[2][4][4];
#pragma unroll
    for (int a = 0; a < 2; a++)
#pragma unroll
        for (int b = 0; b < 4; b++)
#pragma unroll
            for (int c = 0; c < 4; c++) acc[a][b][c] = 0.f;

    const int lr = tid >> 3;
    const int lc8 = (tid & 7) * 8;

    if (FULLK) {
#pragma unroll
        for (int ch = 0; ch < 3; ch++)
            gemm_issue(A, Wt, bm, bn, Ktot, lr, lc8, bufA[ch], bufB[ch], ch * KB);
#pragma unroll
        for (int chunk = 0; chunk < 3; chunk++) {
            if (chunk == 0)      CP_WAIT(2);
            else if (chunk == 1) CP_WAIT(1);
            else                 CP_WAIT(0);
            __syncthreads();
            const uint32_t sA = s2u(bufA[chunk]);
            const uint32_t sB = s2u(bufB[chunk]);
#pragma unroll
            for (int kk = 0; kk < 4; kk++) {
                uint32_t a0[2], a1[2], a2[2], a3[2];
#pragma unroll
                for (int mi = 0; mi < 2; mi++) {
                    uint32_t off = (uint32_t)((wm + mi * 16 + (lane & 15)) * 128 + kk * 32 + (lane >> 4) * 16);
                    off ^= (off >> 3) & 0x70;
                    LDMX4(a0[mi], a1[mi], a2[mi], a3[mi], sA + off);
                }
#pragma unroll
                for (int nj = 0; nj < 2; nj++) {
                    uint32_t off = (uint32_t)((wn + nj * 16 + (lane & 15)) * 128 + kk * 32 + (lane >> 4) * 16);
                    off ^= (off >> 3) & 0x70;
                    uint32_t r0, r1, r2, r3;
                    LDMX4(r0, r1, r2, r3, sB + off);
#pragma unroll
                    for (int mi = 0; mi < 2; mi++) {
                        MMA16816(acc[mi][2 * nj], a0[mi], a1[mi], a2[mi], a3[mi], r0, r2);
                        MMA16816(acc[mi][2 * nj + 1], a0[mi], a1[mi], a2[mi], a3[mi], r1, r3);
                    }
                }
            }
        }
    } else {
        const int nch = Ktot / KB;
        gemm_issue(A, Wt, bm, bn, Ktot, lr, lc8, bufA[0], bufB[0], 0);
        gemm_issue(A, Wt, bm, bn, Ktot, lr, lc8, bufA[1], bufB[1], KB);
        for (int ch = 0; ch < nch; ch++) {
            if (ch + 2 < nch)
                gemm_issue(A, Wt, bm, bn, Ktot, lr, lc8,
                           bufA[(ch + 2) % 3], bufB[(ch + 2) % 3], (ch + 2) * KB);
            const int rem = nch - ch - 1;
            if (rem >= 2)      CP_WAIT(2);
            else if (rem == 1) CP_WAIT(1);
            else               CP_WAIT(0);
            __syncthreads();

            const uint32_t sA = s2u(bufA[ch % 3]);
            const uint32_t sB = s2u(bufB[ch % 3]);
#pragma unroll
            for (int kk = 0; kk < KB / 16; kk++) {
                uint32_t a0[2], a1[2], a2[2], a3[2];
#pragma unroll
                for (int mi = 0; mi < 2; mi++) {
                    uint32_t off = (uint32_t)((wm + mi * 16 + (lane & 15)) * 128 + kk * 32 + (lane >> 4) * 16);
                    off ^= (off >> 3) & 0x70;
                    LDMX4(a0[mi], a1[mi], a2[mi], a3[mi], sA + off);
                }
#pragma unroll
                for (int nj = 0; nj < 2; nj++) {
                    uint32_t off = (uint32_t)((wn + nj * 16 + (lane & 15)) * 128 + kk * 32 + (lane >> 4) * 16);
                    off ^= (off >> 3) & 0x70;
                    uint32_t r0, r1, r2, r3;
                    LDMX4(r0, r1, r2, r3, sB + off);
#pragma unroll
                    for (int mi = 0; mi < 2; mi++) {
                        MMA16816(acc[mi][2 * nj], a0[mi], a1[mi], a2[mi], a3[mi], r0, r2);
                        MMA16816(acc[mi][2 * nj + 1], a0[mi], a1[mi], a2[mi], a3[mi], r1, r3);
                    }
                }
            }
            __syncthreads();
        }
    }

    const int gq = lane >> 2;
    const int tg = lane & 3;
#pragma unroll
    for (int mi = 0; mi < 2; mi++) {
#pragma unroll
        for (int ni = 0; ni < 4; ni++) {
            int col = bn + wn + ni * 8 + tg * 2;
            float bia0 = bias[col], bia1 = bias[col + 1];
#pragma unroll
            for (int half = 0; half < 2; half++) {
                int row = bm + wm + mi * 16 + gq + half * 8;
                float v0 = acc[mi][ni][half * 2 + 0] + bia0;
                float v1 = acc[mi][ni][half * 2 + 1] + bia1;
                size_t oi = (size_t)row * Ntot + col;
                if (EPI == 1) {
                    v0 = 0.5f * v0 * (1.0f + erff(v0 * 0.7071067811865476f));
                    v1 = 0.5f * v1 * (1.0f + erff(v1 * 0.7071067811865476f));
                    __nv_bfloat162 p;
                    p.x = __float2bfloat16(v0); p.y = __float2bfloat16(v1);
                    *(__nv_bfloat162*)((__nv_bfloat16*)Cv + oi) = p;
                } else if (EPI == 2) {
                    float2 rv = *(const float2*)(resid + oi);
                    float2 o; o.x = v0 + rv.x; o.y = v1 + rv.y;
                    *(float2*)((float*)Cv + oi) = o;
                } else if (EPI == 3) {
                    __nv_bfloat162 p;
                    p.x = __float2bfloat16(v0); p.y = __float2bfloat16(v1);
                    *(__nv_bfloat162*)((__nv_bfloat16*)Cv + oi) = p;
                } else {
                    float2 o; o.x = v0; o.y = v1;
                    *(float2*)((float*)Cv + oi) = o;
                }
            }
        }
    }
}

// ---------------- tensor-core attention (exp2, unguarded epilogue) ----------------
__global__ __launch_bounds__(256, 3) void attn_tc_kernel(
    const __nv_bfloat16* __restrict__ qkv, const __nv_bfloat16* __restrict__ comb,
    __nv_bfloat16* __restrict__ out)
{
    extern __shared__ __align__(1024) char sm[];
    const uint32_t uK = s2u(sm + AOFF_K);
    const uint32_t uV = s2u(sm + AOFF_V);
    const uint32_t uQ = s2u(sm + AOFF_Q);
    const uint32_t uP = s2u(sm + AOFF_P);
    float* rs = (float*)(sm + AOFF_RS);

    const int bx = blockIdx.x;
    const int w  = bx / HEADS;
    const int h  = bx - w * HEADS;
    const int mw = w % NWIN;
    const int wd = mw >> 4, wh = (mw >> 2) & 3, ww = mw & 3;
    const int cls = ((wd == 3) << 2) | ((wh == 3) << 1) | (ww == 3);
    const int q0 = blockIdx.y * QT;
    const int tid = threadIdx.x;
    const int lane = tid & 31;
    const int wid = tid >> 5;

    const __nv_bfloat16* base = qkv + (size_t)w * NTOK * (3 * CDIM);

    for (int idx = tid; idx < KPAD * 4; idx += 256) {
        int j = idx >> 2, s = idx & 3;
        uint4 v = make_uint4(0, 0, 0, 0);
        if (j < NTOK) v = *(const uint4*)(base + (size_t)j * (3 * CDIM) + CDIM + h * HD + s * 8);
        *(uint4*)(sm + AOFF_K + j * KPITCH + s * 16) = v;
    }
    for (int idx = tid; idx < QT * 4; idx += 256) {
        int r = idx >> 2, s = idx & 3;
        int gq = q0 + r;
        uint4 v = make_uint4(0, 0, 0, 0);
        if (gq < NTOK) v = *(const uint4*)(base + (size_t)gq * (3 * CDIM) + h * HD + s * 8);
        *(uint4*)(sm + AOFF_Q + r * QPITCH + s * 16) = v;
    }
    for (int jp = tid; jp < KPAD / 2; jp += 256) {
        int j0 = jp * 2;
        __nv_bfloat16 ta[32], tb[32];
        if (j0 < NTOK) {
            const __nv_bfloat16* vp = base + (size_t)j0 * (3 * CDIM) + 2 * CDIM + h * HD;
#pragma unroll
            for (int s = 0; s < 4; s++) *(uint4*)(ta + s * 8) = *(const uint4*)(vp + s * 8);
        } else {
#pragma unroll
            for (int d = 0; d < 32; d++) ta[d] = __float2bfloat16(0.f);
        }
        if (j0 + 1 < NTOK) {
            const __nv_bfloat16* vp = base + (size_t)(j0 + 1) * (3 * CDIM) + 2 * CDIM + h * HD;
#pragma unroll
            for (int s = 0; s < 4; s++) *(uint4*)(tb + s * 8) = *(const uint4*)(vp + s * 8);
        } else {
#pragma unroll
            for (int d = 0; d < 32; d++) tb[d] = __float2bfloat16(0.f);
        }
#pragma unroll
        for (int d = 0; d < 32; d++) {
            __nv_bfloat162 p; p.x = ta[d]; p.y = tb[d];
            *(__nv_bfloat162*)(sm + AOFF_V + d * VPITCH + j0 * 2) = p;
        }
    }
    __syncthreads();

    const int wm = wid & 3, wn = wid >> 2;
    const int vm = wid & 1, vn = wid >> 1;
    const int gq_ = lane >> 2, tg = lane & 3;

    float acc_o[2][4];
#pragma unroll
    for (int t = 0; t < 2; t++)
#pragma unroll
        for (int c = 0; c < 4; c++) acc_o[t][c] = 0.f;
    float rs0 = 0.f, rs1 = 0.f;

    const int r0g = q0 + wm * 16 + gq_;     // <= 383, comb rows padded
    const __nv_bfloat16* cb = comb + (size_t)(h * 8 + cls) * CPITCH * CPITCH;
    const __nv_bfloat16* c0p = cb + (size_t)r0g * CPITCH;
    const __nv_bfloat16* c1p = c0p + 8 * CPITCH;

    for (int ch = 0; ch < NCH; ch++) {
        const int j0 = ch * NC;
        float acc[4][4];
#pragma unroll
        for (int t = 0; t < 4; t++)
#pragma unroll
            for (int c = 0; c < 4; c++) acc[t][c] = 0.f;

#pragma unroll
        for (int ks = 0; ks < 2; ks++) {
            uint32_t a0, a1, a2, a3;
            LDMX4(a0, a1, a2, a3,
                  uQ + (uint32_t)((wm * 16 + (lane & 15)) * QPITCH + ks * 32 + (lane >> 4) * 16));
#pragma unroll
            for (int nj = 0; nj < 2; nj++) {
                uint32_t r0, r1, r2, r3;
                LDMX4(r0, r1, r2, r3,
                      uK + (uint32_t)((j0 + wn * 32 + nj * 16 + (lane & 15)) * KPITCH + ks * 32 + (lane >> 4) * 16));
                MMA16816(acc[2 * nj], a0, a1, a2, a3, r0, r2);
                MMA16816(acc[2 * nj + 1], a0, a1, a2, a3, r1, r3);
            }
        }

        // epilogue: exp2(acc + comb) -> P, rowsums; no guards (padded comb, zero K)
#pragma unroll
        for (int ti = 0; ti < 4; ti++) {
            int jl = wn * 32 + (ti >> 1) * 16 + (ti & 1) * 8 + tg * 2;
            int ja = j0 + jl;
            __nv_bfloat162 b0 = *(const __nv_bfloat162*)(c0p + ja);
            __nv_bfloat162 b1 = *(const __nv_bfloat162*)(c1p + ja);
            float e00 = exp2f(acc[ti][0] + __bfloat162float(b0.x));
            float e01 = exp2f(acc[ti][1] + __bfloat162float(b0.y));
            float e10 = exp2f(acc[ti][2] + __bfloat162float(b1.x));
            float e11 = exp2f(acc[ti][3] + __bfloat162float(b1.y));
            rs0 += e00 + e01;
            rs1 += e10 + e11;
            __nv_bfloat162 p0, p1;
            p0.x = __float2bfloat16(e00); p0.y = __float2bfloat16(e01);
            p1.x = __float2bfloat16(e10); p1.y = __float2bfloat16(e11);
            int rloc0 = wm * 16 + gq_;
            *(__nv_bfloat162*)(sm + AOFF_P + rloc0 * PPITCH + jl * 2) = p0;
            *(__nv_bfloat162*)(sm + AOFF_P + (rloc0 + 8) * PPITCH + jl * 2) = p1;
        }
        __syncthreads();

#pragma unroll
        for (int kk = 0; kk < 4; kk++) {
            uint32_t a0, a1, a2, a3;
            LDMX4(a0, a1, a2, a3,
                  uV + (uint32_t)((vm * 16 + (lane & 15)) * VPITCH + j0 * 2 + kk * 32 + (lane >> 4) * 16));
            uint32_t r0, r1, r2, r3;
            LDMX4(r0, r1, r2, r3,
                  uP + (uint32_t)((vn * 16 + (lane & 15)) * PPITCH + kk * 32 + (lane >> 4) * 16));
            MMA16816(acc_o[0], a0, a1, a2, a3, r0, r2);
            MMA16816(acc_o[1], a0, a1, a2, a3, r1, r3);
        }
        __syncthreads();
    }

    rs0 += __shfl_xor_sync(0xffffffffu, rs0, 1);
    rs0 += __shfl_xor_sync(0xffffffffu, rs0, 2);
    rs1 += __shfl_xor_sync(0xffffffffu, rs1, 1);
    rs1 += __shfl_xor_sync(0xffffffffu, rs1, 2);
    if (tg == 0) {
        rs[(wm * 16 + gq_) * 2 + wn] = rs0;
        rs[(wm * 16 + gq_ + 8) * 2 + wn] = rs1;
    }

    float* Ost = (float*)(sm + AOFF_P);
#pragma unroll
    for (int t = 0; t < 2; t++) {
        int qc = vn * 16 + t * 8 + tg * 2;
        int d0 = vm * 16 + gq_;
        Ost[d0 * 65 + qc]     = acc_o[t][0];
        Ost[d0 * 65 + qc + 1] = acc_o[t][1];
        Ost[(d0 + 8) * 65 + qc]     = acc_o[t][2];
        Ost[(d0 + 8) * 65 + qc + 1] = acc_o[t][3];
    }
    __syncthreads();

    {
        int q = tid >> 2, ds = (tid & 3) * 8;
        int gq = q0 + q;
        if (gq < NTOK) {
            float inv = __frcp_rn(rs[q * 2] + rs[q * 2 + 1]);
            __nv_bfloat16 o[8];
#pragma unroll
            for (int u = 0; u < 8; u++)
                o[u] = __float2bfloat16(Ost[(ds + u) * 65 + q] * inv);
            *(uint4*)(out + (size_t)(w * NTOK + gq) * CDIM + h * HD + ds) = *(uint4*)o;
        }
    }
}

// ---------------- reverse + residual + LN2: warp-per-token ----------------
__global__ __launch_bounds__(256) void ln2res_kernel(const float* __restrict__ x,
                                                     const float* __restrict__ proj,
                                                     const float* __restrict__ g,
                                                     const float* __restrict__ b,
                                                     float* __restrict__ xres,
                                                     __nv_bfloat16* __restrict__ ln2o) {
    int t = blockIdx.x * 8 + (threadIdx.x >> 5);
    int lane = threadIdx.x & 31;
    int row = token_to_winrow(t);
    const float* xp = x + (size_t)t * CDIM;
    const float* pp = proj + (size_t)row * CDIM;
    float* rp = xres + (size_t)t * CDIM;
    float v[6];
    float s = 0.f, s2 = 0.f;
#pragma unroll
    for (int i = 0; i < 6; i++) {
        int c = lane + i * 32;
        v[i] = xp[c] + pp[c];
        rp[c] = v[i];
        s += v[i]; s2 += v[i] * v[i];
    }
    s = warpSum(s); s2 = warpSum(s2);
    float mean = s * (1.0f / CDIM);
    float rstd = rsqrtf(s2 * (1.0f / CDIM) - mean * mean + 1e-5f);
    __nv_bfloat16* op = ln2o + (size_t)t * CDIM;
#pragma unroll
    for (int i = 0; i < 6; i++) {
        int c = lane + i * 32;
        op[c] = __float2bfloat16((v[i] - mean) * rstd * g[c] + b[c]);
    }
}

// ---------------- launch ----------------
extern "C" void kernel_launch(void* const* d_in, const int* in_sizes, int n_in,
                              void* d_out, int out_size) {
    (void)in_sizes; (void)n_in; (void)out_size;
    const float* x       = (const float*)d_in[0];
    const float* table   = (const float*)d_in[3];
    const float* n1g     = (const float*)d_in[4];
    const float* n1b     = (const float*)d_in[5];
    const float* qkv_w   = (const float*)d_in[6];
    const float* qkv_b   = (const float*)d_in[7];
    const float* proj_w  = (const float*)d_in[8];
    const float* proj_b  = (const float*)d_in[9];
    const float* n2g     = (const float*)d_in[10];
    const float* n2b     = (const float*)d_in[11];
    const float* fc1_w   = (const float*)d_in[12];
    const float* fc1_b   = (const float*)d_in[13];
    const float* fc2_w   = (const float*)d_in[14];
    const float* fc2_b   = (const float*)d_in[15];
    float* out = (float*)d_out;

    __nv_bfloat16 *xwb, *qkvb, *attnb, *ln2b, *h1b, *wqkv, *wproj, *wfc1, *wfc2, *comb;
    float *proj, *xres, *qbias;
    cudaGetSymbolAddress((void**)&xwb,   g_xwb);
    cudaGetSymbolAddress((void**)&qkvb,  g_qkvb);
    cudaGetSymbolAddress((void**)&attnb, g_attnb);
    cudaGetSymbolAddress((void**)&proj,  g_proj);
    cudaGetSymbolAddress((void**)&xres,  g_xres);
    cudaGetSymbolAddress((void**)&ln2b,  g_ln2b);
    cudaGetSymbolAddress((void**)&h1b,   g_h1b);
    cudaGetSymbolAddress((void**)&wqkv,  g_wqkv);
    cudaGetSymbolAddress((void**)&wproj, g_wproj);
    cudaGetSymbolAddress((void**)&wfc1,  g_wfc1);
    cudaGetSymbolAddress((void**)&wfc2,  g_wfc2);
    cudaGetSymbolAddress((void**)&comb,  g_comb);
    cudaGetSymbolAddress((void**)&qbias, g_qbias);

    cudaFuncSetAttribute(attn_tc_kernel, cudaFuncAttributeMaxDynamicSharedMemorySize,
                         ATTN_SMEM_BYTES);
    cudaFuncSetAttribute((gemm_mma_kernel<3, true>), cudaFuncAttributeMaxDynamicSharedMemorySize, GEMM_SMEM_BYTES);
    cudaFuncSetAttribute((gemm_mma_kernel<0, true>), cudaFuncAttributeMaxDynamicSharedMemorySize, GEMM_SMEM_BYTES);
    cudaFuncSetAttribute((gemm_mma_kernel<1, true>), cudaFuncAttributeMaxDynamicSharedMemorySize, GEMM_SMEM_BYTES);
    cudaFuncSetAttribute((gemm_mma_kernel<2, false>), cudaFuncAttributeMaxDynamicSharedMemorySize, GEMM_SMEM_BYTES);

    const int n0 = 3 * CDIM * CDIM, n1 = CDIM * CDIM, n2 = HID * CDIM, n3 = CDIM * HID;
    cvt4_kernel<<<(n0 + n1 + n2 + n3 + 255) / 256, 256>>>(
        qkv_w, wqkv, n0, proj_w, wproj, n1, fc1_w, wfc1, n2, fc2_w, wfc2, n3);
    biasq_kernel<<<3, 192>>>(qkv_b, qbias);
    comb_pre_kernel<<<(COMB_ELEMS + 255) / 256, 256>>>(table, comb);

    ln1_kernel<<<TOK / 8, 256>>>(x, n1g, n1b, xwb);
    gemm_mma_kernel<3, true><<<dim3(576 / BN, TOK / BM), 256, GEMM_SMEM_BYTES>>>(
        xwb, wqkv, qbias, nullptr, qkvb, CDIM, 3 * CDIM);
    attn_tc_kernel<<<dim3(TOTWIN * HEADS, NCH), 256, ATTN_SMEM_BYTES>>>(qkvb, comb, attnb);
    gemm_mma_kernel<0, true><<<dim3(CDIM / BN, TOK / BM), 256, GEMM_SMEM_BYTES>>>(
        attnb, wproj, proj_b, nullptr, proj, CDIM, CDIM);
    ln2res_kernel<<<TOK / 8, 256>>>(x, proj, n2g, n2b, xres, ln2b);
    gemm_mma_kernel<1, true><<<dim3(HID / BN, TOK / BM), 256, GEMM_SMEM_BYTES>>>(
        ln2b, wfc1, fc1_b, nullptr, h1b, CDIM, HID);
    gemm_mma_kernel<2, false><<<dim3(CDIM / BN, TOK / BM), 256, GEMM_SMEM_BYTES>>>(
        h1b, wfc2, fc2_b, xres, out, HID, CDIM);
}

// round 11
// speedup vs baseline: 1.0708x; 1.0011x over previous
#include <cuda_runtime.h>
#include <cuda_bf16.h>
#include <math.h>
#include <stdint.h>

// ---------------- problem constants ----------------
#define BATCH   2
#define DSZ     28
#define WS      7
#define SHIFT_  3
#define CDIM    192
#define HEADS   6
#define HD      32
#define NTOK    343
#define NWIN    64
#define TOTWIN  128
#define TOK     43904
#define HID     768
#define SCALE   0.17677669529663687f
#define LOG2E   1.4426950408889634f
#define QFOLD   (SCALE * LOG2E)

// GEMM tiling (CTA 128x64, warp 32x32)
#define BM      128
#define BN      64
#define KB      64
#define GEMM_SMEM_BYTES 73728

// attention tiling
#define QT      64
#define NC      64
#define KPAD    384
#define NCH     6
#define QPITCH  80
#define KPITCH  80
#define VPITCH  784
#define PPITCH  144
#define CPITCH  384
// smem offsets (bytes)
#define AOFF_K   0
#define AOFF_V   30720
#define AOFF_Q   55808
#define AOFF_P   60928
#define AOFF_RS  70144
#define ATTN_SMEM_BYTES 70656

#define COMB_ELEMS (48 * CPITCH * CPITCH)

// ---------------- scratch (device globals) ----------------
__device__ __nv_bfloat16 g_xwb [TOK * CDIM];
__device__ __nv_bfloat16 g_qkvb[TOK * 3 * CDIM];
__device__ __nv_bfloat16 g_attnb[TOK * CDIM];
__device__ float         g_xres[TOK * CDIM];
__device__ __nv_bfloat16 g_ln2b[TOK * CDIM];
__device__ __nv_bfloat16 g_h1b [TOK * HID];
__device__ __nv_bfloat16 g_wqkv[3 * CDIM * CDIM];
__device__ __nv_bfloat16 g_wproj[CDIM * CDIM];
__device__ __nv_bfloat16 g_wfc1[HID * CDIM];
__device__ __nv_bfloat16 g_wfc2[CDIM * HID];
__device__ __nv_bfloat16 g_comb[COMB_ELEMS];
__device__ float         g_qbias[3 * CDIM];

// ---------------- helpers ----------------
__device__ __forceinline__ uint32_t s2u(const void* p) {
    uint32_t r;
    asm("{ .reg .u64 t; cvta.to.shared.u64 t, %1; cvt.u32.u64 %0, t; }" : "=r"(r) : "l"(p));
    return r;
}
__device__ __forceinline__ float warpSum(float v) {
#pragma unroll
    for (int o = 16; o; o >>= 1) v += __shfl_xor_sync(0xffffffffu, v, o);
    return v;
}
__device__ __forceinline__ int token_to_winrow(int t) {
    int b   = t / (DSZ * DSZ * DSZ);
    int rem = t - b * (DSZ * DSZ * DSZ);
    int dd  = rem / (DSZ * DSZ);
    int hh  = (rem / DSZ) % DSZ;
    int ww  = rem % DSZ;
    int i = (dd + DSZ - SHIFT_) % DSZ;
    int j = (hh + DSZ - SHIFT_) % DSZ;
    int k = (ww + DSZ - SHIFT_) % DSZ;
    int win = (i / WS) * 16 + (j / WS) * 4 + (k / WS);
    int n   = (i % WS) * 49 + (j % WS) * 7 + (k % WS);
    return (b * NWIN + win) * NTOK + n;
}
// inverse: windowed row -> token index
__device__ __forceinline__ int winrow_to_token(int r) {
    int win = r / NTOK;
    int n   = r - win * NTOK;
    int b   = win >> 6;
    int w64 = win & 63;
    int ni = n / 49, rem = n - ni * 49;
    int nj = rem / 7, nk = rem - nj * 7;
    int i = (w64 >> 4) * 7 + ni;
    int j = ((w64 >> 2) & 3) * 7 + nj;
    int k = (w64 & 3) * 7 + nk;
    int dd = i + SHIFT_; if (dd >= DSZ) dd -= DSZ;
    int hh = j + SHIFT_; if (hh >= DSZ) hh -= DSZ;
    int ww = k + SHIFT_; if (ww >= DSZ) ww -= DSZ;
    return b * (DSZ * DSZ * DSZ) + dd * (DSZ * DSZ) + hh * DSZ + ww;
}

#define CP_ASYNC16(dst_u32, src_ptr) \
    asm volatile("cp.async.cg.shared.global [%0], [%1], 16;" :: "r"(dst_u32), "l"(src_ptr))
#define CP_COMMIT() asm volatile("cp.async.commit_group;")
#define CP_WAIT(n)  asm volatile("cp.async.wait_group %0;" :: "n"(n))

#define LDMX4(r0, r1, r2, r3, addr) \
    asm volatile("ldmatrix.sync.aligned.m8n8.x4.shared.b16 {%0,%1,%2,%3}, [%4];" \
                 : "=r"(r0), "=r"(r1), "=r"(r2), "=r"(r3) : "r"(addr))

#define MMA16816(d, a0, a1, a2, a3, b0, b1) \
    asm volatile("mma.sync.aligned.m16n8k16.row.col.f32.bf16.bf16.f32 " \
                 "{%0,%1,%2,%3}, {%4,%5,%6,%7}, {%8,%9}, {%0,%1,%2,%3};" \
                 : "+f"((d)[0]), "+f"((d)[1]), "+f"((d)[2]), "+f"((d)[3]) \
                 : "r"(a0), "r"(a1), "r"(a2), "r"(a3), "r"(b0), "r"(b1))

// ---------------- merged weight conversion (q-rows folded) ----------------
__global__ void cvt4_kernel(const float* __restrict__ s0, __nv_bfloat16* __restrict__ d0, int n0,
                            const float* __restrict__ s1, __nv_bfloat16* __restrict__ d1, int n1,
                            const float* __restrict__ s2, __nv_bfloat16* __restrict__ d2, int n2,
                            const float* __restrict__ s3, __nv_bfloat16* __restrict__ d3, int n3) {
    int i = blockIdx.x * 256 + threadIdx.x;
    if (i < n0) {
        float v = s0[i];
        if (i < CDIM * CDIM) v *= QFOLD;
        d0[i] = __float2bfloat16(v);
        return;
    }
    i -= n0;
    if (i < n1) { d1[i] = __float2bfloat16(s1[i]); return; }
    i -= n1;
    if (i < n2) { d2[i] = __float2bfloat16(s2[i]); return; }
    i -= n2;
    if (i < n3) { d3[i] = __float2bfloat16(s3[i]); }
}

__global__ void biasq_kernel(const float* __restrict__ qkv_b, float* __restrict__ qb) {
    int i = blockIdx.x * 192 + threadIdx.x;
    if (i < 3 * CDIM) qb[i] = (i < CDIM) ? qkv_b[i] * QFOLD : qkv_b[i];
}

// ---------------- combined bias+mask precompute ----------------
__global__ void comb_pre_kernel(const float* __restrict__ table,
                                __nv_bfloat16* __restrict__ comb) {
    int idx = blockIdx.x * 256 + threadIdx.x;
    if (idx >= COMB_ELEMS) return;
    int col  = idx % CPITCH;
    int row  = (idx / CPITCH) % CPITCH;
    int hc   = idx / (CPITCH * CPITCH);
    int h = hc >> 3, cls = hc & 7;
    float val = -160.f;
    if (col < NTOK && row < NTOK) {
        int i3 = row / 49, j3 = (row / 7) % 7, k3 = row % 7;
        int ci = col / 49, cj = (col / 7) % 7, ck = col % 7;
        int rel = (i3 - ci + 6) * 169 + (j3 - cj + 6) * 13 + (k3 - ck + 6);
        float v = table[rel * HEADS + h];
        bool diff = ((cls & 4) && ((i3 < 4) != (ci < 4))) ||
                    ((cls & 2) && ((j3 < 4) != (cj < 4))) ||
                    ((cls & 1) && ((k3 < 4) != (ck < 4)));
        if (diff) v -= 100.f;
        val = v * LOG2E;
    }
    comb[idx] = __float2bfloat16(val);
}

// ---------------- LN1 + shift + partition: warp-per-token, float2 ----------------
__global__ __launch_bounds__(256) void ln1_kernel(const float* __restrict__ x,
                                                  const float* __restrict__ g,
                                                  const float* __restrict__ b,
                                                  __nv_bfloat16* __restrict__ xw) {
    int t = blockIdx.x * 8 + (threadIdx.x >> 5);
    int lane = threadIdx.x & 31;
    const float2* xp = (const float2*)(x + (size_t)t * CDIM);
    const float2* gp = (const float2*)g;
    const float2* bp = (const float2*)b;
    float2 v[3];
    float s = 0.f, s2 = 0.f;
#pragma unroll
    for (int i = 0; i < 3; i++) {
        v[i] = xp[lane + i * 32];
        s += v[i].x + v[i].y;
        s2 += v[i].x * v[i].x + v[i].y * v[i].y;
    }
    s = warpSum(s); s2 = warpSum(s2);
    float mean = s * (1.0f / CDIM);
    float rstd = rsqrtf(s2 * (1.0f / CDIM) - mean * mean + 1e-5f);
    int row = token_to_winrow(t);
    __nv_bfloat162* op = (__nv_bfloat162*)(xw + (size_t)row * CDIM);
#pragma unroll
    for (int i = 0; i < 3; i++) {
        int c = lane + i * 32;
        float2 gg = gp[c], bb = bp[c];
        __nv_bfloat162 o;
        o.x = __float2bfloat16((v[i].x - mean) * rstd * gg.x + bb.x);
        o.y = __float2bfloat16((v[i].y - mean) * rstd * gg.y + bb.y);
        op[c] = o;
    }
}

// ---------------- GEMM tile loader ----------------
__device__ __forceinline__ void gemm_issue(const __nv_bfloat16* __restrict__ A,
                                           const __nv_bfloat16* __restrict__ Wt,
                                           int bm, int bn, int Ktot, int lr, int lc8,
                                           char* bA, char* bB, int k0) {
#pragma unroll
    for (int rr = 0; rr < 4; rr++) {
        int r = lr + rr * 32;
        uint32_t off = (uint32_t)(r * 128 + lc8 * 2);
        off ^= (off >> 3) & 0x70;
        CP_ASYNC16(s2u(bA + off), A + (size_t)(bm + r) * Ktot + k0 + lc8);
    }
#pragma unroll
    for (int rr = 0; rr < 2; rr++) {
        int br = lr + rr * 32;
        uint32_t off = (uint32_t)(br * 128 + lc8 * 2);
        off ^= (off >> 3) & 0x70;
        CP_ASYNC16(s2u(bB + off), Wt + (size_t)(bn + br) * Ktot + k0 + lc8);
    }
    CP_COMMIT();
}

// ---------------- HMMA bf16 GEMM ----------------
// EPI: 0 = bias -> fp32; 1 = bias+gelu -> bf16; 2 = bias+resid -> fp32;
//      3 = bias -> bf16;  4 = bias + x[token] -> xres[token] (row-permuted)
template <int EPI, bool FULLK>
__global__ __launch_bounds__(256)
void gemm_mma_kernel(const __nv_bfloat16* __restrict__ A,
                     const __nv_bfloat16* __restrict__ Wt,
                     const float* __restrict__ bias,
                     const float* __restrict__ resid,
                     void* __restrict__ Cv, int Ktot, int Ntot)
{
    extern __shared__ __align__(1024) char dsm[];
    char* bufA[3] = {dsm, dsm + 16384, dsm + 32768};
    char* bufB[3] = {dsm + 49152, dsm + 57344, dsm + 65536};

    const int tid = threadIdx.x;
    const int lane = tid & 31;
    const int wid = tid >> 5;
    const int wm = (wid & 3) * 32;
    const int wn = (wid >> 2) * 32;
    const int bm = blockIdx.y * BM;
    const int bn = blockIdx.x * BN;

    float acc[2][4][4];
#pragma unroll
    for (int a = 0; a < 2; a++)
#pragma unroll
        for (int b = 0; b < 4; b++)
#pragma unroll
            for (int c = 0; c < 4; c++) acc[a][b][c] = 0.f;

    const int lr = tid >> 3;
    const int lc8 = (tid & 7) * 8;

    if (FULLK) {
#pragma unroll
        for (int ch = 0; ch < 3; ch++)
            gemm_issue(A, Wt, bm, bn, Ktot, lr, lc8, bufA[ch], bufB[ch], ch * KB);
#pragma unroll
        for (int chunk = 0; chunk < 3; chunk++) {
            if (chunk == 0)      CP_WAIT(2);
            else if (chunk == 1) CP_WAIT(1);
            else                 CP_WAIT(0);
            __syncthreads();
            const uint32_t sA = s2u(bufA[chunk]);
            const uint32_t sB = s2u(bufB[chunk]);
#pragma unroll
            for (int kk = 0; kk < 4; kk++) {
                uint32_t a0[2], a1[2], a2[2], a3[2];
#pragma unroll
                for (int mi = 0; mi < 2; mi++) {
                    uint32_t off = (uint32_t)((wm + mi * 16 + (lane & 15)) * 128 + kk * 32 + (lane >> 4) * 16);
                    off ^= (off >> 3) & 0x70;
                    LDMX4(a0[mi], a1[mi], a2[mi], a3[mi], sA + off);
                }
#pragma unroll
                for (int nj = 0; nj < 2; nj++) {
                    uint32_t off = (uint32_t)((wn + nj * 16 + (lane & 15)) * 128 + kk * 32 + (lane >> 4) * 16);
                    off ^= (off >> 3) & 0x70;
                    uint32_t r0, r1, r2, r3;
                    LDMX4(r0, r1, r2, r3, sB + off);
#pragma unroll
                    for (int mi = 0; mi < 2; mi++) {
                        MMA16816(acc[mi][2 * nj], a0[mi], a1[mi], a2[mi], a3[mi], r0, r2);
                        MMA16816(acc[mi][2 * nj + 1], a0[mi], a1[mi], a2[mi], a3[mi], r1, r3);
                    }
                }
            }
        }
    } else {
        const int nch = Ktot / KB;
        gemm_issue(A, Wt, bm, bn, Ktot, lr, lc8, bufA[0], bufB[0], 0);
        gemm_issue(A, Wt, bm, bn, Ktot, lr, lc8, bufA[1], bufB[1], KB);
        for (int ch = 0; ch < nch; ch++) {
            if (ch + 2 < nch)
                gemm_issue(A, Wt, bm, bn, Ktot, lr, lc8,
                           bufA[(ch + 2) % 3], bufB[(ch + 2) % 3], (ch + 2) * KB);
            const int rem = nch - ch - 1;
            if (rem >= 2)      CP_WAIT(2);
            else if (rem == 1) CP_WAIT(1);
            else               CP_WAIT(0);
            __syncthreads();

            const uint32_t sA = s2u(bufA[ch % 3]);
            const uint32_t sB = s2u(bufB[ch % 3]);
#pragma unroll
            for (int kk = 0; kk < KB / 16; kk++) {
                uint32_t a0[2], a1[2], a2[2], a3[2];
#pragma unroll
                for (int mi = 0; mi < 2; mi++) {
                    uint32_t off = (uint32_t)((wm + mi * 16 + (lane & 15)) * 128 + kk * 32 + (lane >> 4) * 16);
                    off ^= (off >> 3) & 0x70;
                    LDMX4(a0[mi], a1[mi], a2[mi], a3[mi], sA + off);
                }
#pragma unroll
                for (int nj = 0; nj < 2; nj++) {
                    uint32_t off = (uint32_t)((wn + nj * 16 + (lane & 15)) * 128 + kk * 32 + (lane >> 4) * 16);
                    off ^= (off >> 3) & 0x70;
                    uint32_t r0, r1, r2, r3;
                    LDMX4(r0, r1, r2, r3, sB + off);
#pragma unroll
                    for (int mi = 0; mi < 2; mi++) {
                        MMA16816(acc[mi][2 * nj], a0[mi], a1[mi], a2[mi], a3[mi], r0, r2);
                        MMA16816(acc[mi][2 * nj + 1], a0[mi], a1[mi], a2[mi], a3[mi], r1, r3);
                    }
                }
            }
            __syncthreads();
        }
    }

    const int gq = lane >> 2;
    const int tg = lane & 3;
#pragma unroll
    for (int mi = 0; mi < 2; mi++) {
#pragma unroll
        for (int half = 0; half < 2; half++) {
            int row = bm + wm + mi * 16 + gq + half * 8;
            int orow = row;
            if (EPI == 4) orow = winrow_to_token(row);
#pragma unroll
            for (int ni = 0; ni < 4; ni++) {
                int col = bn + wn + ni * 8 + tg * 2;
                float bia0 = bias[col], bia1 = bias[col + 1];
                float v0 = acc[mi][ni][half * 2 + 0] + bia0;
                float v1 = acc[mi][ni][half * 2 + 1] + bia1;
                size_t oi = (size_t)orow * Ntot + col;
                if (EPI == 1) {
                    v0 = 0.5f * v0 * (1.0f + erff(v0 * 0.7071067811865476f));
                    v1 = 0.5f * v1 * (1.0f + erff(v1 * 0.7071067811865476f));
                    __nv_bfloat162 p;
                    p.x = __float2bfloat16(v0); p.y = __float2bfloat16(v1);
                    *(__nv_bfloat162*)((__nv_bfloat16*)Cv + oi) = p;
                } else if (EPI == 2 || EPI == 4) {
                    float2 rv = *(const float2*)(resid + oi);
                    float2 o; o.x = v0 + rv.x; o.y = v1 + rv.y;
                    *(float2*)((float*)Cv + oi) = o;
                } else if (EPI == 3) {
                    __nv_bfloat162 p;
                    p.x = __float2bfloat16(v0); p.y = __float2bfloat16(v1);
                    *(__nv_bfloat162*)((__nv_bfloat16*)Cv + oi) = p;
                } else {
                    float2 o; o.x = v0; o.y = v1;
                    *(float2*)((float*)Cv + oi) = o;
                }
            }
        }
    }
}

// ---------------- tensor-core attention (exp2, unguarded epilogue) ----------------
__global__ __launch_bounds__(256, 3) void attn_tc_kernel(
    const __nv_bfloat16* __restrict__ qkv, const __nv_bfloat16* __restrict__ comb,
    __nv_bfloat16* __restrict__ out)
{
    extern __shared__ __align__(1024) char sm[];
    const uint32_t uK = s2u(sm + AOFF_K);
    const uint32_t uV = s2u(sm + AOFF_V);
    const uint32_t uQ = s2u(sm + AOFF_Q);
    const uint32_t uP = s2u(sm + AOFF_P);
    float* rs = (float*)(sm + AOFF_RS);

    const int bx = blockIdx.x;
    const int w  = bx / HEADS;
    const int h  = bx - w * HEADS;
    const int mw = w % NWIN;
    const int wd = mw >> 4, wh = (mw >> 2) & 3, ww = mw & 3;
    const int cls = ((wd == 3) << 2) | ((wh == 3) << 1) | (ww == 3);
    const int q0 = blockIdx.y * QT;
    const int tid = threadIdx.x;
    const int lane = tid & 31;
    const int wid = tid >> 5;

    const __nv_bfloat16* base = qkv + (size_t)w * NTOK * (3 * CDIM);

    for (int idx = tid; idx < KPAD * 4; idx += 256) {
        int j = idx >> 2, s = idx & 3;
        uint4 v = make_uint4(0, 0, 0, 0);
        if (j < NTOK) v = *(const uint4*)(base + (size_t)j * (3 * CDIM) + CDIM + h * HD + s * 8);
        *(uint4*)(sm + AOFF_K + j * KPITCH + s * 16) = v;
    }
    for (int idx = tid; idx < QT * 4; idx += 256) {
        int r = idx >> 2, s = idx & 3;
        int gq = q0 + r;
        uint4 v = make_uint4(0, 0, 0, 0);
        if (gq < NTOK) v = *(const uint4*)(base + (size_t)gq * (3 * CDIM) + h * HD + s * 8);
        *(uint4*)(sm + AOFF_Q + r * QPITCH + s * 16) = v;
    }
    for (int jp = tid; jp < KPAD / 2; jp += 256) {
        int j0 = jp * 2;
        __nv_bfloat16 ta[32], tb[32];
        if (j0 < NTOK) {
            const __nv_bfloat16* vp = base + (size_t)j0 * (3 * CDIM) + 2 * CDIM + h * HD;
#pragma unroll
            for (int s = 0; s < 4; s++) *(uint4*)(ta + s * 8) = *(const uint4*)(vp + s * 8);
        } else {
#pragma unroll
            for (int d = 0; d < 32; d++) ta[d] = __float2bfloat16(0.f);
        }
        if (j0 + 1 < NTOK) {
            const __nv_bfloat16* vp = base + (size_t)(j0 + 1) * (3 * CDIM) + 2 * CDIM + h * HD;
#pragma unroll
            for (int s = 0; s < 4; s++) *(uint4*)(tb + s * 8) = *(const uint4*)(vp + s * 8);
        } else {
#pragma unroll
            for (int d = 0; d < 32; d++) tb[d] = __float2bfloat16(0.f);
        }
#pragma unroll
        for (int d = 0; d < 32; d++) {
            __nv_bfloat162 p; p.x = ta[d]; p.y = tb[d];
            *(__nv_bfloat162*)(sm + AOFF_V + d * VPITCH + j0 * 2) = p;
        }
    }
    __syncthreads();

    const int wm = wid & 3, wn = wid >> 2;
    const int vm = wid & 1, vn = wid >> 1;
    const int gq_ = lane >> 2, tg = lane & 3;

    float acc_o[2][4];
#pragma unroll
    for (int t = 0; t < 2; t++)
#pragma unroll
        for (int c = 0; c < 4; c++) acc_o[t][c] = 0.f;
    float rs0 = 0.f, rs1 = 0.f;

    const int r0g = q0 + wm * 16 + gq_;
    const __nv_bfloat16* cb = comb + (size_t)(h * 8 + cls) * CPITCH * CPITCH;
    const __nv_bfloat16* c0p = cb + (size_t)r0g * CPITCH;
    const __nv_bfloat16* c1p = c0p + 8 * CPITCH;

    for (int ch = 0; ch < NCH; ch++) {
        const int j0 = ch * NC;
        float acc[4][4];
#pragma unroll
        for (int t = 0; t < 4; t++)
#pragma unroll
            for (int c = 0; c < 4; c++) acc[t][c] = 0.f;

#pragma unroll
        for (int ks = 0; ks < 2; ks++) {
            uint32_t a0, a1, a2, a3;
            LDMX4(a0, a1, a2, a3,
                  uQ + (uint32_t)((wm * 16 + (lane & 15)) * QPITCH + ks * 32 + (lane >> 4) * 16));
#pragma unroll
            for (int nj = 0; nj < 2; nj++) {
                uint32_t r0, r1, r2, r3;
                LDMX4(r0, r1, r2, r3,
                      uK + (uint32_t)((j0 + wn * 32 + nj * 16 + (lane & 15)) * KPITCH + ks * 32 + (lane >> 4) * 16));
                MMA16816(acc[2 * nj], a0, a1, a2, a3, r0, r2);
                MMA16816(acc[2 * nj + 1], a0, a1, a2, a3, r1, r3);
            }
        }

#pragma unroll
        for (int ti = 0; ti < 4; ti++) {
            int jl = wn * 32 + (ti >> 1) * 16 + (ti & 1) * 8 + tg * 2;
            int ja = j0 + jl;
            __nv_bfloat162 b0 = *(const __nv_bfloat162*)(c0p + ja);
            __nv_bfloat162 b1 = *(const __nv_bfloat162*)(c1p + ja);
            float e00 = exp2f(acc[ti][0] + __bfloat162float(b0.x));
            float e01 = exp2f(acc[ti][1] + __bfloat162float(b0.y));
            float e10 = exp2f(acc[ti][2] + __bfloat162float(b1.x));
            float e11 = exp2f(acc[ti][3] + __bfloat162float(b1.y));
            rs0 += e00 + e01;
            rs1 += e10 + e11;
            __nv_bfloat162 p0, p1;
            p0.x = __float2bfloat16(e00); p0.y = __float2bfloat16(e01);
            p1.x = __float2bfloat16(e10); p1.y = __float2bfloat16(e11);
            int rloc0 = wm * 16 + gq_;
            *(__nv_bfloat162*)(sm + AOFF_P + rloc0 * PPITCH + jl * 2) = p0;
            *(__nv_bfloat162*)(sm + AOFF_P + (rloc0 + 8) * PPITCH + jl * 2) = p1;
        }
        __syncthreads();

#pragma unroll
        for (int kk = 0; kk < 4; kk++) {
            uint32_t a0, a1, a2, a3;
            LDMX4(a0, a1, a2, a3,
                  uV + (uint32_t)((vm * 16 + (lane & 15)) * VPITCH + j0 * 2 + kk * 32 + (lane >> 4) * 16));
            uint32_t r0, r1, r2, r3;
            LDMX4(r0, r1, r2, r3,
                  uP + (uint32_t)((vn * 16 + (lane & 15)) * PPITCH + kk * 32 + (lane >> 4) * 16));
            MMA16816(acc_o[0], a0, a1, a2, a3, r0, r2);
            MMA16816(acc_o[1], a0, a1, a2, a3, r1, r3);
        }
        __syncthreads();
    }

    rs0 += __shfl_xor_sync(0xffffffffu, rs0, 1);
    rs0 += __shfl_xor_sync(0xffffffffu, rs0, 2);
    rs1 += __shfl_xor_sync(0xffffffffu, rs1, 1);
    rs1 += __shfl_xor_sync(0xffffffffu, rs1, 2);
    if (tg == 0) {
        rs[(wm * 16 + gq_) * 2 + wn] = rs0;
        rs[(wm * 16 + gq_ + 8) * 2 + wn] = rs1;
    }

    float* Ost = (float*)(sm + AOFF_P);
#pragma unroll
    for (int t = 0; t < 2; t++) {
        int qc = vn * 16 + t * 8 + tg * 2;
        int d0 = vm * 16 + gq_;
        Ost[d0 * 65 + qc]     = acc_o[t][0];
        Ost[d0 * 65 + qc + 1] = acc_o[t][1];
        Ost[(d0 + 8) * 65 + qc]     = acc_o[t][2];
        Ost[(d0 + 8) * 65 + qc + 1] = acc_o[t][3];
    }
    __syncthreads();

    {
        int q = tid >> 2, ds = (tid & 3) * 8;
        int gq = q0 + q;
        if (gq < NTOK) {
            float inv = __frcp_rn(rs[q * 2] + rs[q * 2 + 1]);
            __nv_bfloat16 o[8];
#pragma unroll
            for (int u = 0; u < 8; u++)
                o[u] = __float2bfloat16(Ost[(ds + u) * 65 + q] * inv);
            *(uint4*)(out + (size_t)(w * NTOK + gq) * CDIM + h * HD + ds) = *(uint4*)o;
        }
    }
}

// ---------------- pure LN2 (xres -> ln2b), warp-per-token, float2 ----------------
__global__ __launch_bounds__(256) void ln2_kernel(const float* __restrict__ xres,
                                                  const float* __restrict__ g,
                                                  const float* __restrict__ b,
                                                  __nv_bfloat16* __restrict__ ln2o) {
    int t = blockIdx.x * 8 + (threadIdx.x >> 5);
    int lane = threadIdx.x & 31;
    const float2* xp = (const float2*)(xres + (size_t)t * CDIM);
    const float2* gp = (const float2*)g;
    const float2* bp = (const float2*)b;
    float2 v[3];
    float s = 0.f, s2 = 0.f;
#pragma unroll
    for (int i = 0; i < 3; i++) {
        v[i] = xp[lane + i * 32];
        s += v[i].x + v[i].y;
        s2 += v[i].x * v[i].x + v[i].y * v[i].y;
    }
    s = warpSum(s); s2 = warpSum(s2);
    float mean = s * (1.0f / CDIM);
    float rstd = rsqrtf(s2 * (1.0f / CDIM) - mean * mean + 1e-5f);
    __nv_bfloat162* op = (__nv_bfloat162*)(ln2o + (size_t)t * CDIM);
#pragma unroll
    for (int i = 0; i < 3; i++) {
        int c = lane + i * 32;
        float2 gg = gp[c], bb = bp[c];
        __nv_bfloat162 o;
        o.x = __float2bfloat16((v[i].x - mean) * rstd * gg.x + bb.x);
        o.y = __float2bfloat16((v[i].y - mean) * rstd * gg.y + bb.y);
        op[c] = o;
    }
}

// ---------------- launch ----------------
extern "C" void kernel_launch(void* const* d_in, const int* in_sizes, int n_in,
                              void* d_out, int out_size) {
    (void)in_sizes; (void)n_in; (void)out_size;
    const float* x       = (const float*)d_in[0];
    const float* table   = (const float*)d_in[3];
    const float* n1g     = (const float*)d_in[4];
    const float* n1b     = (const float*)d_in[5];
    const float* qkv_w   = (const float*)d_in[6];
    const float* qkv_b   = (const float*)d_in[7];
    const float* proj_w  = (const float*)d_in[8];
    const float* proj_b  = (const float*)d_in[9];
    const float* n2g     = (const float*)d_in[10];
    const float* n2b     = (const float*)d_in[11];
    const float* fc1_w   = (const float*)d_in[12];
    const float* fc1_b   = (const float*)d_in[13];
    const float* fc2_w   = (const float*)d_in[14];
    const float* fc2_b   = (const float*)d_in[15];
    float* out = (float*)d_out;

    __nv_bfloat16 *xwb, *qkvb, *attnb, *ln2b, *h1b, *wqkv, *wproj, *wfc1, *wfc2, *comb;
    float *xres, *qbias;
    cudaGetSymbolAddress((void**)&xwb,   g_xwb);
    cudaGetSymbolAddress((void**)&qkvb,  g_qkvb);
    cudaGetSymbolAddress((void**)&attnb, g_attnb);
    cudaGetSymbolAddress((void**)&xres,  g_xres);
    cudaGetSymbolAddress((void**)&ln2b,  g_ln2b);
    cudaGetSymbolAddress((void**)&h1b,   g_h1b);
    cudaGetSymbolAddress((void**)&wqkv,  g_wqkv);
    cudaGetSymbolAddress((void**)&wproj, g_wproj);
    cudaGetSymbolAddress((void**)&wfc1,  g_wfc1);
    cudaGetSymbolAddress((void**)&wfc2,  g_wfc2);
    cudaGetSymbolAddress((void**)&comb,  g_comb);
    cudaGetSymbolAddress((void**)&qbias, g_qbias);

    cudaFuncSetAttribute(attn_tc_kernel, cudaFuncAttributeMaxDynamicSharedMemorySize,
                         ATTN_SMEM_BYTES);
    cudaFuncSetAttribute((gemm_mma_kernel<3, true>), cudaFuncAttributeMaxDynamicSharedMemorySize, GEMM_SMEM_BYTES);
    cudaFuncSetAttribute((gemm_mma_kernel<4, true>), cudaFuncAttributeMaxDynamicSharedMemorySize, GEMM_SMEM_BYTES);
    cudaFuncSetAttribute((gemm_mma_kernel<1, true>), cudaFuncAttributeMaxDynamicSharedMemorySize, GEMM_SMEM_BYTES);
    cudaFuncSetAttribute((gemm_mma_kernel<2, false>), cudaFuncAttributeMaxDynamicSharedMemorySize, GEMM_SMEM_BYTES);

    const int n0 = 3 * CDIM * CDIM, n1 = CDIM * CDIM, n2 = HID * CDIM, n3 = CDIM * HID;
    cvt4_kernel<<<(n0 + n1 + n2 + n3 + 255) / 256, 256>>>(
        qkv_w, wqkv, n0, proj_w, wproj, n1, fc1_w, wfc1, n2, fc2_w, wfc2, n3);
    biasq_kernel<<<3, 192>>>(qkv_b, qbias);
    comb_pre_kernel<<<(COMB_ELEMS + 255) / 256, 256>>>(table, comb);

    ln1_kernel<<<TOK / 8, 256>>>(x, n1g, n1b, xwb);
    // QKV (folded q-scale)
    gemm_mma_kernel<3, true><<<dim3(576 / BN, TOK / BM), 256, GEMM_SMEM_BYTES>>>(
        xwb, wqkv, qbias, nullptr, qkvb, CDIM, 3 * CDIM);
    attn_tc_kernel<<<dim3(TOTWIN * HEADS, NCH), 256, ATTN_SMEM_BYTES>>>(qkvb, comb, attnb);
    // proj + reverse-permute + residual -> xres (token order)
    gemm_mma_kernel<4, true><<<dim3(CDIM / BN, TOK / BM), 256, GEMM_SMEM_BYTES>>>(
        attnb, wproj, proj_b, x, xres, CDIM, CDIM);
    ln2_kernel<<<TOK / 8, 256>>>(xres, n2g, n2b, ln2b);
    // FC1 + GELU
    gemm_mma_kernel<1, true><<<dim3(HID / BN, TOK / BM), 256, GEMM_SMEM_BYTES>>>(
        ln2b, wfc1, fc1_b, nullptr, h1b, CDIM, HID);
    // FC2 + residual -> out
    gemm_mma_kernel<2, false><<<dim3(CDIM / BN, TOK / BM), 256, GEMM_SMEM_BYTES>>>(
        h1b, wfc2, fc2_b, xres, out, HID, CDIM);
}

// round 12
// speedup vs baseline: 1.1089x; 1.0356x over previous
#include <cuda_runtime.h>
#include <cuda_bf16.h>
#include <math.h>
#include <stdint.h>

// ---------------- problem constants ----------------
#define BATCH   2
#define DSZ     28
#define WS      7
#define SHIFT_  3
#define CDIM    192
#define HEADS   6
#define HD      32
#define NTOK    343
#define NWIN    64
#define TOTWIN  128
#define TOK     43904
#define HID     768
#define SCALE   0.17677669529663687f
#define LOG2E   1.4426950408889634f
#define QFOLD   (SCALE * LOG2E)

// GEMM tiling (CTA 128x64, warp 32x32)
#define BM      128
#define BN      64
#define KB      64
#define GEMM_SMEM_BYTES 73728

// attention tiling
#define QT      64
#define NC      64
#define KPAD    384
#define NCH     6
#define QPITCH  80
#define KPITCH  80
#define VPITCH  784
#define PPITCH  144
#define CPITCH  384
// smem offsets (bytes)
#define AOFF_K   0
#define AOFF_V   30720
#define AOFF_Q   55808
#define AOFF_P   60928
#define AOFF_RS  70144
#define ATTN_SMEM_BYTES 70656

#define COMB_ELEMS (48 * CPITCH * CPITCH)

// ---------------- scratch (device globals) ----------------
__device__ __nv_bfloat16 g_xwb [TOK * CDIM];
__device__ __nv_bfloat16 g_qkvb[TOK * 3 * CDIM];
__device__ __nv_bfloat16 g_attnb[TOK * CDIM];
__device__ float         g_xres[TOK * CDIM];
__device__ __nv_bfloat16 g_ln2b[TOK * CDIM];
__device__ __nv_bfloat16 g_h1b [TOK * HID];
__device__ __nv_bfloat16 g_wqkv[3 * CDIM * CDIM];
__device__ __nv_bfloat16 g_wproj[CDIM * CDIM];
__device__ __nv_bfloat16 g_wfc1[HID * CDIM];
__device__ __nv_bfloat16 g_wfc2[CDIM * HID];
__device__ __nv_bfloat16 g_comb[COMB_ELEMS];
__device__ float         g_qbias[3 * CDIM];

// ---------------- helpers ----------------
__device__ __forceinline__ uint32_t s2u(const void* p) {
    uint32_t r;
    asm("{ .reg .u64 t; cvta.to.shared.u64 t, %1; cvt.u32.u64 %0, t; }" : "=r"(r) : "l"(p));
    return r;
}
__device__ __forceinline__ float warpSum(float v) {
#pragma unroll
    for (int o = 16; o; o >>= 1) v += __shfl_xor_sync(0xffffffffu, v, o);
    return v;
}
__device__ __forceinline__ int token_to_winrow(int t) {
    int b   = t / (DSZ * DSZ * DSZ);
    int rem = t - b * (DSZ * DSZ * DSZ);
    int dd  = rem / (DSZ * DSZ);
    int hh  = (rem / DSZ) % DSZ;
    int ww  = rem % DSZ;
    int i = (dd + DSZ - SHIFT_) % DSZ;
    int j = (hh + DSZ - SHIFT_) % DSZ;
    int k = (ww + DSZ - SHIFT_) % DSZ;
    int win = (i / WS) * 16 + (j / WS) * 4 + (k / WS);
    int n   = (i % WS) * 49 + (j % WS) * 7 + (k % WS);
    return (b * NWIN + win) * NTOK + n;
}
__device__ __forceinline__ int winrow_to_token(int r) {
    int win = r / NTOK;
    int n   = r - win * NTOK;
    int b   = win >> 6;
    int w64 = win & 63;
    int ni = n / 49, rem = n - ni * 49;
    int nj = rem / 7, nk = rem - nj * 7;
    int i = (w64 >> 4) * 7 + ni;
    int j = ((w64 >> 2) & 3) * 7 + nj;
    int k = (w64 & 3) * 7 + nk;
    int dd = i + SHIFT_; if (dd >= DSZ) dd -= DSZ;
    int hh = j + SHIFT_; if (hh >= DSZ) hh -= DSZ;
    int ww = k + SHIFT_; if (ww >= DSZ) ww -= DSZ;
    return b * (DSZ * DSZ * DSZ) + dd * (DSZ * DSZ) + hh * DSZ + ww;
}

#define CP_ASYNC16(dst_u32, src_ptr) \
    asm volatile("cp.async.cg.shared.global [%0], [%1], 16;" :: "r"(dst_u32), "l"(src_ptr))
#define CP_COMMIT() asm volatile("cp.async.commit_group;")
#define CP_WAIT(n)  asm volatile("cp.async.wait_group %0;" :: "n"(n))

#define LDMX4(r0, r1, r2, r3, addr) \
    asm volatile("ldmatrix.sync.aligned.m8n8.x4.shared.b16 {%0,%1,%2,%3}, [%4];" \
                 : "=r"(r0), "=r"(r1), "=r"(r2), "=r"(r3) : "r"(addr))

#define MMA16816(d, a0, a1, a2, a3, b0, b1) \
    asm volatile("mma.sync.aligned.m16n8k16.row.col.f32.bf16.bf16.f32 " \
                 "{%0,%1,%2,%3}, {%4,%5,%6,%7}, {%8,%9}, {%0,%1,%2,%3};" \
                 : "+f"((d)[0]), "+f"((d)[1]), "+f"((d)[2]), "+f"((d)[3]) \
                 : "r"(a0), "r"(a1), "r"(a2), "r"(a3), "r"(b0), "r"(b1))

// ---------------- merged weight conversion (q-rows folded) ----------------
__global__ void cvt4_kernel(const float* __restrict__ s0, __nv_bfloat16* __restrict__ d0, int n0,
                            const float* __restrict__ s1, __nv_bfloat16* __restrict__ d1, int n1,
                            const float* __restrict__ s2, __nv_bfloat16* __restrict__ d2, int n2,
                            const float* __restrict__ s3, __nv_bfloat16* __restrict__ d3, int n3) {
    int i = blockIdx.x * 256 + threadIdx.x;
    if (i < n0) {
        float v = s0[i];
        if (i < CDIM * CDIM) v *= QFOLD;
        d0[i] = __float2bfloat16(v);
        return;
    }
    i -= n0;
    if (i < n1) { d1[i] = __float2bfloat16(s1[i]); return; }
    i -= n1;
    if (i < n2) { d2[i] = __float2bfloat16(s2[i]); return; }
    i -= n2;
    if (i < n3) { d3[i] = __float2bfloat16(s3[i]); }
}

__global__ void biasq_kernel(const float* __restrict__ qkv_b, float* __restrict__ qb) {
    int i = blockIdx.x * 192 + threadIdx.x;
    if (i < 3 * CDIM) qb[i] = (i < CDIM) ? qkv_b[i] * QFOLD : qkv_b[i];
}

// ---------------- combined bias+mask precompute ----------------
__global__ void comb_pre_kernel(const float* __restrict__ table,
                                __nv_bfloat16* __restrict__ comb) {
    int idx = blockIdx.x * 256 + threadIdx.x;
    if (idx >= COMB_ELEMS) return;
    int col  = idx % CPITCH;
    int row  = (idx / CPITCH) % CPITCH;
    int hc   = idx / (CPITCH * CPITCH);
    int h = hc >> 3, cls = hc & 7;
    float val = -160.f;
    if (col < NTOK && row < NTOK) {
        int i3 = row / 49, j3 = (row / 7) % 7, k3 = row % 7;
        int ci = col / 49, cj = (col / 7) % 7, ck = col % 7;
        int rel = (i3 - ci + 6) * 169 + (j3 - cj + 6) * 13 + (k3 - ck + 6);
        float v = table[rel * HEADS + h];
        bool diff = ((cls & 4) && ((i3 < 4) != (ci < 4))) ||
                    ((cls & 2) && ((j3 < 4) != (cj < 4))) ||
                    ((cls & 1) && ((k3 < 4) != (ck < 4)));
        if (diff) v -= 100.f;
        val = v * LOG2E;
    }
    comb[idx] = __float2bfloat16(val);
}

// ---------------- LN1 + shift + partition ----------------
__global__ __launch_bounds__(256) void ln1_kernel(const float* __restrict__ x,
                                                  const float* __restrict__ g,
                                                  const float* __restrict__ b,
                                                  __nv_bfloat16* __restrict__ xw) {
    int t = blockIdx.x * 8 + (threadIdx.x >> 5);
    int lane = threadIdx.x & 31;
    const float2* xp = (const float2*)(x + (size_t)t * CDIM);
    const float2* gp = (const float2*)g;
    const float2* bp = (const float2*)b;
    float2 v[3];
    float s = 0.f, s2 = 0.f;
#pragma unroll
    for (int i = 0; i < 3; i++) {
        v[i] = xp[lane + i * 32];
        s += v[i].x + v[i].y;
        s2 += v[i].x * v[i].x + v[i].y * v[i].y;
    }
    s = warpSum(s); s2 = warpSum(s2);
    float mean = s * (1.0f / CDIM);
    float rstd = rsqrtf(s2 * (1.0f / CDIM) - mean * mean + 1e-5f);
    int row = token_to_winrow(t);
    __nv_bfloat162* op = (__nv_bfloat162*)(xw + (size_t)row * CDIM);
#pragma unroll
    for (int i = 0; i < 3; i++) {
        int c = lane + i * 32;
        float2 gg = gp[c], bb = bp[c];
        __nv_bfloat162 o;
        o.x = __float2bfloat16((v[i].x - mean) * rstd * gg.x + bb.x);
        o.y = __float2bfloat16((v[i].y - mean) * rstd * gg.y + bb.y);
        op[c] = o;
    }
}

// ---------------- GEMM tile loader ----------------
__device__ __forceinline__ void gemm_issue(const __nv_bfloat16* __restrict__ A,
                                           const __nv_bfloat16* __restrict__ Wt,
                                           int bm, int bn, int Ktot, int lr, int lc8,
                                           char* bA, char* bB, int k0) {
#pragma unroll
    for (int rr = 0; rr < 4; rr++) {
        int r = lr + rr * 32;
        uint32_t off = (uint32_t)(r * 128 + lc8 * 2);
        off ^= (off >> 3) & 0x70;
        CP_ASYNC16(s2u(bA + off), A + (size_t)(bm + r) * Ktot + k0 + lc8);
    }
#pragma unroll
    for (int rr = 0; rr < 2; rr++) {
        int br = lr + rr * 32;
        uint32_t off = (uint32_t)(br * 128 + lc8 * 2);
        off ^= (off >> 3) & 0x70;
        CP_ASYNC16(s2u(bB + off), Wt + (size_t)(bn + br) * Ktot + k0 + lc8);
    }
    CP_COMMIT();
}

// ---------------- HMMA bf16 GEMM ----------------
// EPI: 0 = bias -> fp32; 1 = bias+gelu -> bf16; 2 = bias+resid -> fp32;
//      3 = bias -> bf16;  4 = bias + x[token] -> xres[token] (row-permuted)
template <int EPI, bool FULLK>
__global__ __launch_bounds__(256)
void gemm_mma_kernel(const __nv_bfloat16* __restrict__ A,
                     const __nv_bfloat16* __restrict__ Wt,
                     const float* __restrict__ bias,
                     const float* __restrict__ resid,
                     void* __restrict__ Cv, int Ktot, int Ntot)
{
    extern __shared__ __align__(1024) char dsm[];
    char* bufA[3] = {dsm, dsm + 16384, dsm + 32768};
    char* bufB[3] = {dsm + 49152, dsm + 57344, dsm + 65536};

    const int tid = threadIdx.x;
    const int lane = tid & 31;
    const int wid = tid >> 5;
    const int wm = (wid & 3) * 32;
    const int wn = (wid >> 2) * 32;
    const int bm = blockIdx.y * BM;
    const int bn = blockIdx.x * BN;

    float acc[2][4][4];
#pragma unroll
    for (int a = 0; a < 2; a++)
#pragma unroll
        for (int b = 0; b < 4; b++)
#pragma unroll
            for (int c = 0; c < 4; c++) acc[a][b][c] = 0.f;

    const int lr = tid >> 3;
    const int lc8 = (tid & 7) * 8;

    if (FULLK) {
#pragma unroll
        for (int ch = 0; ch < 3; ch++)
            gemm_issue(A, Wt, bm, bn, Ktot, lr, lc8, bufA[ch], bufB[ch], ch * KB);
#pragma unroll
        for (int chunk = 0; chunk < 3; chunk++) {
            if (chunk == 0)      CP_WAIT(2);
            else if (chunk == 1) CP_WAIT(1);
            else                 CP_WAIT(0);
            __syncthreads();
            const uint32_t sA = s2u(bufA[chunk]);
            const uint32_t sB = s2u(bufB[chunk]);
#pragma unroll
            for (int kk = 0; kk < 4; kk++) {
                uint32_t a0[2], a1[2], a2[2], a3[2];
#pragma unroll
                for (int mi = 0; mi < 2; mi++) {
                    uint32_t off = (uint32_t)((wm + mi * 16 + (lane & 15)) * 128 + kk * 32 + (lane >> 4) * 16);
                    off ^= (off >> 3) & 0x70;
                    LDMX4(a0[mi], a1[mi], a2[mi], a3[mi], sA + off);
                }
#pragma unroll
                for (int nj = 0; nj < 2; nj++) {
                    uint32_t off = (uint32_t)((wn + nj * 16 + (lane & 15)) * 128 + kk * 32 + (lane >> 4) * 16);
                    off ^= (off >> 3) & 0x70;
                    uint32_t r0, r1, r2, r3;
                    LDMX4(r0, r1, r2, r3, sB + off);
#pragma unroll
                    for (int mi = 0; mi < 2; mi++) {
                        MMA16816(acc[mi][2 * nj], a0[mi], a1[mi], a2[mi], a3[mi], r0, r2);
                        MMA16816(acc[mi][2 * nj + 1], a0[mi], a1[mi], a2[mi], a3[mi], r1, r3);
                    }
                }
            }
        }
    } else {
        const int nch = Ktot / KB;
        gemm_issue(A, Wt, bm, bn, Ktot, lr, lc8, bufA[0], bufB[0], 0);
        gemm_issue(A, Wt, bm, bn, Ktot, lr, lc8, bufA[1], bufB[1], KB);
        for (int ch = 0; ch < nch; ch++) {
            if (ch + 2 < nch)
                gemm_issue(A, Wt, bm, bn, Ktot, lr, lc8,
                           bufA[(ch + 2) % 3], bufB[(ch + 2) % 3], (ch + 2) * KB);
            const int rem = nch - ch - 1;
            if (rem >= 2)      CP_WAIT(2);
            else if (rem == 1) CP_WAIT(1);
            else               CP_WAIT(0);
            __syncthreads();

            const uint32_t sA = s2u(bufA[ch % 3]);
            const uint32_t sB = s2u(bufB[ch % 3]);
#pragma unroll
            for (int kk = 0; kk < KB / 16; kk++) {
                uint32_t a0[2], a1[2], a2[2], a3[2];
#pragma unroll
                for (int mi = 0; mi < 2; mi++) {
                    uint32_t off = (uint32_t)((wm + mi * 16 + (lane & 15)) * 128 + kk * 32 + (lane >> 4) * 16);
                    off ^= (off >> 3) & 0x70;
                    LDMX4(a0[mi], a1[mi], a2[mi], a3[mi], sA + off);
                }
#pragma unroll
                for (int nj = 0; nj < 2; nj++) {
                    uint32_t off = (uint32_t)((wn + nj * 16 + (lane & 15)) * 128 + kk * 32 + (lane >> 4) * 16);
                    off ^= (off >> 3) & 0x70;
                    uint32_t r0, r1, r2, r3;
                    LDMX4(r0, r1, r2, r3, sB + off);
#pragma unroll
                    for (int mi = 0; mi < 2; mi++) {
                        MMA16816(acc[mi][2 * nj], a0[mi], a1[mi], a2[mi], a3[mi], r0, r2);
                        MMA16816(acc[mi][2 * nj + 1], a0[mi], a1[mi], a2[mi], a3[mi], r1, r3);
                    }
                }
            }
            __syncthreads();
        }
    }

    const int gq = lane >> 2;
    const int tg = lane & 3;
#pragma unroll
    for (int mi = 0; mi < 2; mi++) {
#pragma unroll
        for (int half = 0; half < 2; half++) {
            int row = bm + wm + mi * 16 + gq + half * 8;
            int orow = row;
            if (EPI == 4) orow = winrow_to_token(row);
#pragma unroll
            for (int ni = 0; ni < 4; ni++) {
                int col = bn + wn + ni * 8 + tg * 2;
                float bia0 = bias[col], bia1 = bias[col + 1];
                float v0 = acc[mi][ni][half * 2 + 0] + bia0;
                float v1 = acc[mi][ni][half * 2 + 1] + bia1;
                size_t oi = (size_t)orow * Ntot + col;
                if (EPI == 1) {
                    v0 = 0.5f * v0 * (1.0f + erff(v0 * 0.7071067811865476f));
                    v1 = 0.5f * v1 * (1.0f + erff(v1 * 0.7071067811865476f));
                    __nv_bfloat162 p;
                    p.x = __float2bfloat16(v0); p.y = __float2bfloat16(v1);
                    *(__nv_bfloat162*)((__nv_bfloat16*)Cv + oi) = p;
                } else if (EPI == 2 || EPI == 4) {
                    float2 rv = *(const float2*)(resid + oi);
                    float2 o; o.x = v0 + rv.x; o.y = v1 + rv.y;
                    *(float2*)((float*)Cv + oi) = o;
                } else if (EPI == 3) {
                    __nv_bfloat162 p;
                    p.x = __float2bfloat16(v0); p.y = __float2bfloat16(v1);
                    *(__nv_bfloat162*)((__nv_bfloat16*)Cv + oi) = p;
                } else {
                    float2 o; o.x = v0; o.y = v1;
                    *(float2*)((float*)Cv + oi) = o;
                }
            }
        }
    }
}

// ---------------- tensor-core attention: persistent K/V, loop q-tiles ----------------
// grid (TOTWIN*HEADS); block 256, 3 CTAs/SM.
__global__ __launch_bounds__(256, 3) void attn_tc_kernel(
    const __nv_bfloat16* __restrict__ qkv, const __nv_bfloat16* __restrict__ comb,
    __nv_bfloat16* __restrict__ out)
{
    extern __shared__ __align__(1024) char sm[];
    const uint32_t uK = s2u(sm + AOFF_K);
    const uint32_t uV = s2u(sm + AOFF_V);
    const uint32_t uQ = s2u(sm + AOFF_Q);
    const uint32_t uP = s2u(sm + AOFF_P);
    float* rs = (float*)(sm + AOFF_RS);

    const int bx = blockIdx.x;
    const int w  = bx / HEADS;
    const int h  = bx - w * HEADS;
    const int mw = w % NWIN;
    const int wd = mw >> 4, wh = (mw >> 2) & 3, ww = mw & 3;
    const int cls = ((wd == 3) << 2) | ((wh == 3) << 1) | (ww == 3);
    const int tid = threadIdx.x;
    const int lane = tid & 31;
    const int wid = tid >> 5;

    const __nv_bfloat16* base = qkv + (size_t)w * NTOK * (3 * CDIM);

    // K (once per block)
    for (int idx = tid; idx < KPAD * 4; idx += 256) {
        int j = idx >> 2, s = idx & 3;
        uint4 v = make_uint4(0, 0, 0, 0);
        if (j < NTOK) v = *(const uint4*)(base + (size_t)j * (3 * CDIM) + CDIM + h * HD + s * 8);
        *(uint4*)(sm + AOFF_K + j * KPITCH + s * 16) = v;
    }
    // V transposed, packed pair stores (once per block)
    for (int jp = tid; jp < KPAD / 2; jp += 256) {
        int j0 = jp * 2;
        __nv_bfloat16 ta[32], tb[32];
        if (j0 < NTOK) {
            const __nv_bfloat16* vp = base + (size_t)j0 * (3 * CDIM) + 2 * CDIM + h * HD;
#pragma unroll
            for (int s = 0; s < 4; s++) *(uint4*)(ta + s * 8) = *(const uint4*)(vp + s * 8);
        } else {
#pragma unroll
            for (int d = 0; d < 32; d++) ta[d] = __float2bfloat16(0.f);
        }
        if (j0 + 1 < NTOK) {
            const __nv_bfloat16* vp = base + (size_t)(j0 + 1) * (3 * CDIM) + 2 * CDIM + h * HD;
#pragma unroll
            for (int s = 0; s < 4; s++) *(uint4*)(tb + s * 8) = *(const uint4*)(vp + s * 8);
        } else {
#pragma unroll
            for (int d = 0; d < 32; d++) tb[d] = __float2bfloat16(0.f);
        }
#pragma unroll
        for (int d = 0; d < 32; d++) {
            __nv_bfloat162 p; p.x = ta[d]; p.y = tb[d];
            *(__nv_bfloat162*)(sm + AOFF_V + d * VPITCH + j0 * 2) = p;
        }
    }

    const int wm = wid & 3, wn = wid >> 2;
    const int vm = wid & 1, vn = wid >> 1;
    const int gq_ = lane >> 2, tg = lane & 3;
    const __nv_bfloat16* cb = comb + (size_t)(h * 8 + cls) * CPITCH * CPITCH;

    for (int qt = 0; qt < NCH; qt++) {
        const int q0 = qt * QT;
        // Q tile (safe: previous iteration ended with __syncthreads)
        for (int idx = tid; idx < QT * 4; idx += 256) {
            int r = idx >> 2, s = idx & 3;
            int gq = q0 + r;
            uint4 v = make_uint4(0, 0, 0, 0);
            if (gq < NTOK) v = *(const uint4*)(base + (size_t)gq * (3 * CDIM) + h * HD + s * 8);
            *(uint4*)(sm + AOFF_Q + r * QPITCH + s * 16) = v;
        }
        __syncthreads();

        float acc_o[2][4];
#pragma unroll
        for (int t = 0; t < 2; t++)
#pragma unroll
            for (int c = 0; c < 4; c++) acc_o[t][c] = 0.f;
        float rs0 = 0.f, rs1 = 0.f;

        const int r0g = q0 + wm * 16 + gq_;
        const __nv_bfloat16* c0p = cb + (size_t)r0g * CPITCH;
        const __nv_bfloat16* c1p = c0p + 8 * CPITCH;

        for (int ch = 0; ch < NCH; ch++) {
            const int j0 = ch * NC;
            float acc[4][4];
#pragma unroll
            for (int t = 0; t < 4; t++)
#pragma unroll
                for (int c = 0; c < 4; c++) acc[t][c] = 0.f;

#pragma unroll
            for (int ks = 0; ks < 2; ks++) {
                uint32_t a0, a1, a2, a3;
                LDMX4(a0, a1, a2, a3,
                      uQ + (uint32_t)((wm * 16 + (lane & 15)) * QPITCH + ks * 32 + (lane >> 4) * 16));
#pragma unroll
                for (int nj = 0; nj < 2; nj++) {
                    uint32_t r0, r1, r2, r3;
                    LDMX4(r0, r1, r2, r3,
                          uK + (uint32_t)((j0 + wn * 32 + nj * 16 + (lane & 15)) * KPITCH + ks * 32 + (lane >> 4) * 16));
                    MMA16816(acc[2 * nj], a0, a1, a2, a3, r0, r2);
                    MMA16816(acc[2 * nj + 1], a0, a1, a2, a3, r1, r3);
                }
            }

            // epilogue: exp2(acc + comb) -> P, rowsums (unguarded; padded comb, zero K)
#pragma unroll
            for (int ti = 0; ti < 4; ti++) {
                int jl = wn * 32 + (ti >> 1) * 16 + (ti & 1) * 8 + tg * 2;
                int ja = j0 + jl;
                __nv_bfloat162 b0 = *(const __nv_bfloat162*)(c0p + ja);
                __nv_bfloat162 b1 = *(const __nv_bfloat162*)(c1p + ja);
                float e00 = exp2f(acc[ti][0] + __bfloat162float(b0.x));
                float e01 = exp2f(acc[ti][1] + __bfloat162float(b0.y));
                float e10 = exp2f(acc[ti][2] + __bfloat162float(b1.x));
                float e11 = exp2f(acc[ti][3] + __bfloat162float(b1.y));
                rs0 += e00 + e01;
                rs1 += e10 + e11;
                __nv_bfloat162 p0, p1;
                p0.x = __float2bfloat16(e00); p0.y = __float2bfloat16(e01);
                p1.x = __float2bfloat16(e10); p1.y = __float2bfloat16(e11);
                int rloc0 = wm * 16 + gq_;
                *(__nv_bfloat162*)(sm + AOFF_P + rloc0 * PPITCH + jl * 2) = p0;
                *(__nv_bfloat162*)(sm + AOFF_P + (rloc0 + 8) * PPITCH + jl * 2) = p1;
            }
            __syncthreads();

#pragma unroll
            for (int kk = 0; kk < 4; kk++) {
                uint32_t a0, a1, a2, a3;
                LDMX4(a0, a1, a2, a3,
                      uV + (uint32_t)((vm * 16 + (lane & 15)) * VPITCH + j0 * 2 + kk * 32 + (lane >> 4) * 16));
                uint32_t r0, r1, r2, r3;
                LDMX4(r0, r1, r2, r3,
                      uP + (uint32_t)((vn * 16 + (lane & 15)) * PPITCH + kk * 32 + (lane >> 4) * 16));
                MMA16816(acc_o[0], a0, a1, a2, a3, r0, r2);
                MMA16816(acc_o[1], a0, a1, a2, a3, r1, r3);
            }
            __syncthreads();
        }

        rs0 += __shfl_xor_sync(0xffffffffu, rs0, 1);
        rs0 += __shfl_xor_sync(0xffffffffu, rs0, 2);
        rs1 += __shfl_xor_sync(0xffffffffu, rs1, 1);
        rs1 += __shfl_xor_sync(0xffffffffu, rs1, 2);
        if (tg == 0) {
            rs[(wm * 16 + gq_) * 2 + wn] = rs0;
            rs[(wm * 16 + gq_ + 8) * 2 + wn] = rs1;
        }

        float* Ost = (float*)(sm + AOFF_P);
#pragma unroll
        for (int t = 0; t < 2; t++) {
            int qc = vn * 16 + t * 8 + tg * 2;
            int d0 = vm * 16 + gq_;
            Ost[d0 * 65 + qc]     = acc_o[t][0];
            Ost[d0 * 65 + qc + 1] = acc_o[t][1];
            Ost[(d0 + 8) * 65 + qc]     = acc_o[t][2];
            Ost[(d0 + 8) * 65 + qc + 1] = acc_o[t][3];
        }
        __syncthreads();

        {
            int q = tid >> 2, ds = (tid & 3) * 8;
            int gq = q0 + q;
            if (gq < NTOK) {
                float inv = __frcp_rn(rs[q * 2] + rs[q * 2 + 1]);
                __nv_bfloat16 o[8];
#pragma unroll
                for (int u = 0; u < 8; u++)
                    o[u] = __float2bfloat16(Ost[(ds + u) * 65 + q] * inv);
                *(uint4*)(out + (size_t)(w * NTOK + gq) * CDIM + h * HD + ds) = *(uint4*)o;
            }
        }
        __syncthreads();   // protect P/rs/Q before next q-tile
    }
}

// ---------------- pure LN2 ----------------
__global__ __launch_bounds__(256) void ln2_kernel(const float* __restrict__ xres,
                                                  const float* __restrict__ g,
                                                  const float* __restrict__ b,
                                                  __nv_bfloat16* __restrict__ ln2o) {
    int t = blockIdx.x * 8 + (threadIdx.x >> 5);
    int lane = threadIdx.x & 31;
    const float2* xp = (const float2*)(xres + (size_t)t * CDIM);
    const float2* gp = (const float2*)g;
    const float2* bp = (const float2*)b;
    float2 v[3];
    float s = 0.f, s2 = 0.f;
#pragma unroll
    for (int i = 0; i < 3; i++) {
        v[i] = xp[lane + i * 32];
        s += v[i].x + v[i].y;
        s2 += v[i].x * v[i].x + v[i].y * v[i].y;
    }
    s = warpSum(s); s2 = warpSum(s2);
    float mean = s * (1.0f / CDIM);
    float rstd = rsqrtf(s2 * (1.0f / CDIM) - mean * mean + 1e-5f);
    __nv_bfloat162* op = (__nv_bfloat162*)(ln2o + (size_t)t * CDIM);
#pragma unroll
    for (int i = 0; i < 3; i++) {
        int c = lane + i * 32;
        float2 gg = gp[c], bb = bp[c];
        __nv_bfloat162 o;
        o.x = __float2bfloat16((v[i].x - mean) * rstd * gg.x + bb.x);
        o.y = __float2bfloat16((v[i].y - mean) * rstd * gg.y + bb.y);
        op[c] = o;
    }
}

// ---------------- launch ----------------
extern "C" void kernel_launch(void* const* d_in, const int* in_sizes, int n_in,
                              void* d_out, int out_size) {
    (void)in_sizes; (void)n_in; (void)out_size;
    const float* x       = (const float*)d_in[0];
    const float* table   = (const float*)d_in[3];
    const float* n1g     = (const float*)d_in[4];
    const float* n1b     = (const float*)d_in[5];
    const float* qkv_w   = (const float*)d_in[6];
    const float* qkv_b   = (const float*)d_in[7];
    const float* proj_w  = (const float*)d_in[8];
    const float* proj_b  = (const float*)d_in[9];
    const float* n2g     = (const float*)d_in[10];
    const float* n2b     = (const float*)d_in[11];
    const float* fc1_w   = (const float*)d_in[12];
    const float* fc1_b   = (const float*)d_in[13];
    const float* fc2_w   = (const float*)d_in[14];
    const float* fc2_b   = (const float*)d_in[15];
    float* out = (float*)d_out;

    __nv_bfloat16 *xwb, *qkvb, *attnb, *ln2b, *h1b, *wqkv, *wproj, *wfc1, *wfc2, *comb;
    float *xres, *qbias;
    cudaGetSymbolAddress((void**)&xwb,   g_xwb);
    cudaGetSymbolAddress((void**)&qkvb,  g_qkvb);
    cudaGetSymbolAddress((void**)&attnb, g_attnb);
    cudaGetSymbolAddress((void**)&xres,  g_xres);
    cudaGetSymbolAddress((void**)&ln2b,  g_ln2b);
    cudaGetSymbolAddress((void**)&h1b,   g_h1b);
    cudaGetSymbolAddress((void**)&wqkv,  g_wqkv);
    cudaGetSymbolAddress((void**)&wproj, g_wproj);
    cudaGetSymbolAddress((void**)&wfc1,  g_wfc1);
    cudaGetSymbolAddress((void**)&wfc2,  g_wfc2);
    cudaGetSymbolAddress((void**)&comb,  g_comb);
    cudaGetSymbolAddress((void**)&qbias, g_qbias);

    cudaFuncSetAttribute(attn_tc_kernel, cudaFuncAttributeMaxDynamicSharedMemorySize,
                         ATTN_SMEM_BYTES);
    cudaFuncSetAttribute((gemm_mma_kernel<3, true>), cudaFuncAttributeMaxDynamicSharedMemorySize, GEMM_SMEM_BYTES);
    cudaFuncSetAttribute((gemm_mma_kernel<4, true>), cudaFuncAttributeMaxDynamicSharedMemorySize, GEMM_SMEM_BYTES);
    cudaFuncSetAttribute((gemm_mma_kernel<1, true>), cudaFuncAttributeMaxDynamicSharedMemorySize, GEMM_SMEM_BYTES);
    cudaFuncSetAttribute((gemm_mma_kernel<2, false>), cudaFuncAttributeMaxDynamicSharedMemorySize, GEMM_SMEM_BYTES);

    const int n0 = 3 * CDIM * CDIM, n1 = CDIM * CDIM, n2 = HID * CDIM, n3 = CDIM * HID;
    cvt4_kernel<<<(n0 + n1 + n2 + n3 + 255) / 256, 256>>>(
        qkv_w, wqkv, n0, proj_w, wproj, n1, fc1_w, wfc1, n2, fc2_w, wfc2, n3);
    biasq_kernel<<<3, 192>>>(qkv_b, qbias);
    comb_pre_kernel<<<(COMB_ELEMS + 255) / 256, 256>>>(table, comb);

    ln1_kernel<<<TOK / 8, 256>>>(x, n1g, n1b, xwb);
    gemm_mma_kernel<3, true><<<dim3(576 / BN, TOK / BM), 256, GEMM_SMEM_BYTES>>>(
        xwb, wqkv, qbias, nullptr, qkvb, CDIM, 3 * CDIM);
    // persistent-KV attention: 768 blocks
    attn_tc_kernel<<<TOTWIN * HEADS, 256, ATTN_SMEM_BYTES>>>(qkvb, comb, attnb);
    gemm_mma_kernel<4, true><<<dim3(CDIM / BN, TOK / BM), 256, GEMM_SMEM_BYTES>>>(
        attnb, wproj, proj_b, x, xres, CDIM, CDIM);
    ln2_kernel<<<TOK / 8, 256>>>(xres, n2g, n2b, ln2b);
    gemm_mma_kernel<1, true><<<dim3(HID / BN, TOK / BM), 256, GEMM_SMEM_BYTES>>>(
        ln2b, wfc1, fc1_b, nullptr, h1b, CDIM, HID);
    gemm_mma_kernel<2, false><<<dim3(CDIM / BN, TOK / BM), 256, GEMM_SMEM_BYTES>>>(
        h1b, wfc2, fc2_b, xres, out, HID, CDIM);
}

// round 13
// speedup vs baseline: 1.1220x; 1.0118x over previous
#include <cuda_runtime.h>
#include <cuda_bf16.h>
#include <math.h>
#include <stdint.h>

// ---------------- problem constants ----------------
#define BATCH   2
#define DSZ     28
#define WS      7
#define SHIFT_  3
#define CDIM    192
#define HEADS   6
#define HD      32
#define NTOK    343
#define NWIN    64
#define TOTWIN  128
#define TOK     43904
#define HID     768
#define SCALE   0.17677669529663687f
#define LOG2E   1.4426950408889634f
#define QFOLD   (SCALE * LOG2E)

// GEMM tiling (CTA 128x64, warp 32x32)
#define BM      128
#define BN      64
#define KB      64
#define GEMM_SMEM_BYTES 73728

// attention tiling
#define QT      64
#define NC      64
#define KPAD    384
#define NCH     6
#define QPITCH  80
#define KPITCH  80
#define VPITCH  784
#define PPITCH  144
#define CPITCH  384
// smem offsets (bytes)
#define AOFF_K   0
#define AOFF_V   30720
#define AOFF_Q   55808
#define AOFF_P   60928
#define AOFF_RS  70144
#define ATTN_SMEM_BYTES 70656

#define COMB_ELEMS (48 * CPITCH * CPITCH)

// ---------------- scratch (device globals) ----------------
__device__ __nv_bfloat16 g_xwb [TOK * CDIM];
__device__ __nv_bfloat16 g_qkvb[TOK * 3 * CDIM];
__device__ __nv_bfloat16 g_attnb[TOK * CDIM];
__device__ float         g_xres[TOK * CDIM];
__device__ __nv_bfloat16 g_ln2b[TOK * CDIM];
__device__ __nv_bfloat16 g_h1b [TOK * HID];
__device__ __nv_bfloat16 g_wqkv[3 * CDIM * CDIM];
__device__ __nv_bfloat16 g_wproj[CDIM * CDIM];
__device__ __nv_bfloat16 g_wfc1[HID * CDIM];
__device__ __nv_bfloat16 g_wfc2[CDIM * HID];
__device__ __nv_bfloat16 g_comb[COMB_ELEMS];
__device__ float         g_qbias[3 * CDIM];

// ---------------- helpers ----------------
__device__ __forceinline__ uint32_t s2u(const void* p) {
    uint32_t r;
    asm("{ .reg .u64 t; cvta.to.shared.u64 t, %1; cvt.u32.u64 %0, t; }" : "=r"(r) : "l"(p));
    return r;
}
__device__ __forceinline__ float warpSum(float v) {
#pragma unroll
    for (int o = 16; o; o >>= 1) v += __shfl_xor_sync(0xffffffffu, v, o);
    return v;
}
__device__ __forceinline__ int token_to_winrow(int t) {
    int b   = t / (DSZ * DSZ * DSZ);
    int rem = t - b * (DSZ * DSZ * DSZ);
    int dd  = rem / (DSZ * DSZ);
    int hh  = (rem / DSZ) % DSZ;
    int ww  = rem % DSZ;
    int i = (dd + DSZ - SHIFT_) % DSZ;
    int j = (hh + DSZ - SHIFT_) % DSZ;
    int k = (ww + DSZ - SHIFT_) % DSZ;
    int win = (i / WS) * 16 + (j / WS) * 4 + (k / WS);
    int n   = (i % WS) * 49 + (j % WS) * 7 + (k % WS);
    return (b * NWIN + win) * NTOK + n;
}
__device__ __forceinline__ int winrow_to_token(int r) {
    int win = r / NTOK;
    int n   = r - win * NTOK;
    int b   = win >> 6;
    int w64 = win & 63;
    int ni = n / 49, rem = n - ni * 49;
    int nj = rem / 7, nk = rem - nj * 7;
    int i = (w64 >> 4) * 7 + ni;
    int j = ((w64 >> 2) & 3) * 7 + nj;
    int k = (w64 & 3) * 7 + nk;
    int dd = i + SHIFT_; if (dd >= DSZ) dd -= DSZ;
    int hh = j + SHIFT_; if (hh >= DSZ) hh -= DSZ;
    int ww = k + SHIFT_; if (ww >= DSZ) ww -= DSZ;
    return b * (DSZ * DSZ * DSZ) + dd * (DSZ * DSZ) + hh * DSZ + ww;
}

#define CP_ASYNC16(dst_u32, src_ptr) \
    asm volatile("cp.async.cg.shared.global [%0], [%1], 16;" :: "r"(dst_u32), "l"(src_ptr))
#define CP_COMMIT() asm volatile("cp.async.commit_group;")
#define CP_WAIT(n)  asm volatile("cp.async.wait_group %0;" :: "n"(n))

#define LDMX4(r0, r1, r2, r3, addr) \
    asm volatile("ldmatrix.sync.aligned.m8n8.x4.shared.b16 {%0,%1,%2,%3}, [%4];" \
                 : "=r"(r0), "=r"(r1), "=r"(r2), "=r"(r3) : "r"(addr))

#define MMA16816(d, a0, a1, a2, a3, b0, b1) \
    asm volatile("mma.sync.aligned.m16n8k16.row.col.f32.bf16.bf16.f32 " \
                 "{%0,%1,%2,%3}, {%4,%5,%6,%7}, {%8,%9}, {%0,%1,%2,%3};" \
                 : "+f"((d)[0]), "+f"((d)[1]), "+f"((d)[2]), "+f"((d)[3]) \
                 : "r"(a0), "r"(a1), "r"(a2), "r"(a3), "r"(b0), "r"(b1))

// ---------------- merged weight conversion (q-rows folded) ----------------
__global__ void cvt4_kernel(const float* __restrict__ s0, __nv_bfloat16* __restrict__ d0, int n0,
                            const float* __restrict__ s1, __nv_bfloat16* __restrict__ d1, int n1,
                            const float* __restrict__ s2, __nv_bfloat16* __restrict__ d2, int n2,
                            const float* __restrict__ s3, __nv_bfloat16* __restrict__ d3, int n3) {
    int i = blockIdx.x * 256 + threadIdx.x;
    if (i < n0) {
        float v = s0[i];
        if (i < CDIM * CDIM) v *= QFOLD;
        d0[i] = __float2bfloat16(v);
        return;
    }
    i -= n0;
    if (i < n1) { d1[i] = __float2bfloat16(s1[i]); return; }
    i -= n1;
    if (i < n2) { d2[i] = __float2bfloat16(s2[i]); return; }
    i -= n2;
    if (i < n3) { d3[i] = __float2bfloat16(s3[i]); }
}

__global__ void biasq_kernel(const float* __restrict__ qkv_b, float* __restrict__ qb) {
    int i = blockIdx.x * 192 + threadIdx.x;
    if (i < 3 * CDIM) qb[i] = (i < CDIM) ? qkv_b[i] * QFOLD : qkv_b[i];
}

// ---------------- combined bias+mask precompute ----------------
__global__ void comb_pre_kernel(const float* __restrict__ table,
                                __nv_bfloat16* __restrict__ comb) {
    int idx = blockIdx.x * 256 + threadIdx.x;
    if (idx >= COMB_ELEMS) return;
    int col  = idx % CPITCH;
    int row  = (idx / CPITCH) % CPITCH;
    int hc   = idx / (CPITCH * CPITCH);
    int h = hc >> 3, cls = hc & 7;
    float val = -160.f;
    if (col < NTOK && row < NTOK) {
        int i3 = row / 49, j3 = (row / 7) % 7, k3 = row % 7;
        int ci = col / 49, cj = (col / 7) % 7, ck = col % 7;
        int rel = (i3 - ci + 6) * 169 + (j3 - cj + 6) * 13 + (k3 - ck + 6);
        float v = table[rel * HEADS + h];
        bool diff = ((cls & 4) && ((i3 < 4) != (ci < 4))) ||
                    ((cls & 2) && ((j3 < 4) != (cj < 4))) ||
                    ((cls & 1) && ((k3 < 4) != (ck < 4)));
        if (diff) v -= 100.f;
        val = v * LOG2E;
    }
    comb[idx] = __float2bfloat16(val);
}

// ---------------- LN1 + shift + partition ----------------
__global__ __launch_bounds__(256) void ln1_kernel(const float* __restrict__ x,
                                                  const float* __restrict__ g,
                                                  const float* __restrict__ b,
                                                  __nv_bfloat16* __restrict__ xw) {
    int t = blockIdx.x * 8 + (threadIdx.x >> 5);
    int lane = threadIdx.x & 31;
    const float2* xp = (const float2*)(x + (size_t)t * CDIM);
    const float2* gp = (const float2*)g;
    const float2* bp = (const float2*)b;
    float2 v[3];
    float s = 0.f, s2 = 0.f;
#pragma unroll
    for (int i = 0; i < 3; i++) {
        v[i] = xp[lane + i * 32];
        s += v[i].x + v[i].y;
        s2 += v[i].x * v[i].x + v[i].y * v[i].y;
    }
    s = warpSum(s); s2 = warpSum(s2);
    float mean = s * (1.0f / CDIM);
    float rstd = rsqrtf(s2 * (1.0f / CDIM) - mean * mean + 1e-5f);
    int row = token_to_winrow(t);
    __nv_bfloat162* op = (__nv_bfloat162*)(xw + (size_t)row * CDIM);
#pragma unroll
    for (int i = 0; i < 3; i++) {
        int c = lane + i * 32;
        float2 gg = gp[c], bb = bp[c];
        __nv_bfloat162 o;
        o.x = __float2bfloat16((v[i].x - mean) * rstd * gg.x + bb.x);
        o.y = __float2bfloat16((v[i].y - mean) * rstd * gg.y + bb.y);
        op[c] = o;
    }
}

// ---------------- GEMM tile loader ----------------
__device__ __forceinline__ void gemm_issue(const __nv_bfloat16* __restrict__ A,
                                           const __nv_bfloat16* __restrict__ Wt,
                                           int bm, int bn, int Ktot, int lr, int lc8,
                                           char* bA, char* bB, int k0) {
#pragma unroll
    for (int rr = 0; rr < 4; rr++) {
        int r = lr + rr * 32;
        uint32_t off = (uint32_t)(r * 128 + lc8 * 2);
        off ^= (off >> 3) & 0x70;
        CP_ASYNC16(s2u(bA + off), A + (size_t)(bm + r) * Ktot + k0 + lc8);
    }
#pragma unroll
    for (int rr = 0; rr < 2; rr++) {
        int br = lr + rr * 32;
        uint32_t off = (uint32_t)(br * 128 + lc8 * 2);
        off ^= (off >> 3) & 0x70;
        CP_ASYNC16(s2u(bB + off), Wt + (size_t)(bn + br) * Ktot + k0 + lc8);
    }
    CP_COMMIT();
}

// ---------------- HMMA bf16 GEMM ----------------
// EPI: 0 = bias -> fp32; 1 = bias+gelu -> bf16; 2 = bias+resid -> fp32;
//      3 = bias -> bf16;  4 = bias + x[token] -> xres[token] (row-permuted)
template <int EPI, bool FULLK>
__global__ __launch_bounds__(256)
void gemm_mma_kernel(const __nv_bfloat16* __restrict__ A,
                     const __nv_bfloat16* __restrict__ Wt,
                     const float* __restrict__ bias,
                     const float* __restrict__ resid,
                     void* __restrict__ Cv, int Ktot, int Ntot)
{
    extern __shared__ __align__(1024) char dsm[];
    char* bufA[3] = {dsm, dsm + 16384, dsm + 32768};
    char* bufB[3] = {dsm + 49152, dsm + 57344, dsm + 65536};

    const int tid = threadIdx.x;
    const int lane = tid & 31;
    const int wid = tid >> 5;
    const int wm = (wid & 3) * 32;
    const int wn = (wid >> 2) * 32;
    const int bm = blockIdx.y * BM;
    const int bn = blockIdx.x * BN;

    float acc[2][4][4];
#pragma unroll
    for (int a = 0; a < 2; a++)
#pragma unroll
        for (int b = 0; b < 4; b++)
#pragma unroll
            for (int c = 0; c < 4; c++) acc[a][b][c] = 0.f;

    const int lr = tid >> 3;
    const int lc8 = (tid & 7) * 8;

    if (FULLK) {
#pragma unroll
        for (int ch = 0; ch < 3; ch++)
            gemm_issue(A, Wt, bm, bn, Ktot, lr, lc8, bufA[ch], bufB[ch], ch * KB);
#pragma unroll
        for (int chunk = 0; chunk < 3; chunk++) {
            if (chunk == 0)      CP_WAIT(2);
            else if (chunk == 1) CP_WAIT(1);
            else                 CP_WAIT(0);
            __syncthreads();
            const uint32_t sA = s2u(bufA[chunk]);
            const uint32_t sB = s2u(bufB[chunk]);
#pragma unroll
            for (int kk = 0; kk < 4; kk++) {
                uint32_t a0[2], a1[2], a2[2], a3[2];
#pragma unroll
                for (int mi = 0; mi < 2; mi++) {
                    uint32_t off = (uint32_t)((wm + mi * 16 + (lane & 15)) * 128 + kk * 32 + (lane >> 4) * 16);
                    off ^= (off >> 3) & 0x70;
                    LDMX4(a0[mi], a1[mi], a2[mi], a3[mi], sA + off);
                }
#pragma unroll
                for (int nj = 0; nj < 2; nj++) {
                    uint32_t off = (uint32_t)((wn + nj * 16 + (lane & 15)) * 128 + kk * 32 + (lane >> 4) * 16);
                    off ^= (off >> 3) & 0x70;
                    uint32_t r0, r1, r2, r3;
                    LDMX4(r0, r1, r2, r3, sB + off);
#pragma unroll
                    for (int mi = 0; mi < 2; mi++) {
                        MMA16816(acc[mi][2 * nj], a0[mi], a1[mi], a2[mi], a3[mi], r0, r2);
                        MMA16816(acc[mi][2 * nj + 1], a0[mi], a1[mi], a2[mi], a3[mi], r1, r3);
                    }
                }
            }
        }
    } else {
        const int nch = Ktot / KB;
        gemm_issue(A, Wt, bm, bn, Ktot, lr, lc8, bufA[0], bufB[0], 0);
        gemm_issue(A, Wt, bm, bn, Ktot, lr, lc8, bufA[1], bufB[1], KB);
        for (int ch = 0; ch < nch; ch++) {
            if (ch + 2 < nch)
                gemm_issue(A, Wt, bm, bn, Ktot, lr, lc8,
                           bufA[(ch + 2) % 3], bufB[(ch + 2) % 3], (ch + 2) * KB);
            const int rem = nch - ch - 1;
            if (rem >= 2)      CP_WAIT(2);
            else if (rem == 1) CP_WAIT(1);
            else               CP_WAIT(0);
            __syncthreads();

            const uint32_t sA = s2u(bufA[ch % 3]);
            const uint32_t sB = s2u(bufB[ch % 3]);
#pragma unroll
            for (int kk = 0; kk < KB / 16; kk++) {
                uint32_t a0[2], a1[2], a2[2], a3[2];
#pragma unroll
                for (int mi = 0; mi < 2; mi++) {
                    uint32_t off = (uint32_t)((wm + mi * 16 + (lane & 15)) * 128 + kk * 32 + (lane >> 4) * 16);
                    off ^= (off >> 3) & 0x70;
                    LDMX4(a0[mi], a1[mi], a2[mi], a3[mi], sA + off);
                }
#pragma unroll
                for (int nj = 0; nj < 2; nj++) {
                    uint32_t off = (uint32_t)((wn + nj * 16 + (lane & 15)) * 128 + kk * 32 + (lane >> 4) * 16);
                    off ^= (off >> 3) & 0x70;
                    uint32_t r0, r1, r2, r3;
                    LDMX4(r0, r1, r2, r3, sB + off);
#pragma unroll
                    for (int mi = 0; mi < 2; mi++) {
                        MMA16816(acc[mi][2 * nj], a0[mi], a1[mi], a2[mi], a3[mi], r0, r2);
                        MMA16816(acc[mi][2 * nj + 1], a0[mi], a1[mi], a2[mi], a3[mi], r1, r3);
                    }
                }
            }
            __syncthreads();
        }
    }

    const int gq = lane >> 2;
    const int tg = lane & 3;
#pragma unroll
    for (int mi = 0; mi < 2; mi++) {
#pragma unroll
        for (int half = 0; half < 2; half++) {
            int row = bm + wm + mi * 16 + gq + half * 8;
            int orow = row;
            if (EPI == 4) orow = winrow_to_token(row);
#pragma unroll
            for (int ni = 0; ni < 4; ni++) {
                int col = bn + wn + ni * 8 + tg * 2;
                float bia0 = bias[col], bia1 = bias[col + 1];
                float v0 = acc[mi][ni][half * 2 + 0] + bia0;
                float v1 = acc[mi][ni][half * 2 + 1] + bia1;
                size_t oi = (size_t)orow * Ntot + col;
                if (EPI == 1) {
                    v0 = 0.5f * v0 * (1.0f + erff(v0 * 0.7071067811865476f));
                    v1 = 0.5f * v1 * (1.0f + erff(v1 * 0.7071067811865476f));
                    __nv_bfloat162 p;
                    p.x = __float2bfloat16(v0); p.y = __float2bfloat16(v1);
                    *(__nv_bfloat162*)((__nv_bfloat16*)Cv + oi) = p;
                } else if (EPI == 2 || EPI == 4) {
                    float2 rv = *(const float2*)(resid + oi);
                    float2 o; o.x = v0 + rv.x; o.y = v1 + rv.y;
                    *(float2*)((float*)Cv + oi) = o;
                } else if (EPI == 3) {
                    __nv_bfloat162 p;
                    p.x = __float2bfloat16(v0); p.y = __float2bfloat16(v1);
                    *(__nv_bfloat162*)((__nv_bfloat16*)Cv + oi) = p;
                } else {
                    float2 o; o.x = v0; o.y = v1;
                    *(float2*)((float*)Cv + oi) = o;
                }
            }
        }
    }
}

// ---------------- tensor-core attention: persistent K/V, loop q-tiles ----------------
__global__ __launch_bounds__(256, 3) void attn_tc_kernel(
    const __nv_bfloat16* __restrict__ qkv, const __nv_bfloat16* __restrict__ comb,
    __nv_bfloat16* __restrict__ out)
{
    extern __shared__ __align__(1024) char sm[];
    const uint32_t uK = s2u(sm + AOFF_K);
    const uint32_t uV = s2u(sm + AOFF_V);
    const uint32_t uQ = s2u(sm + AOFF_Q);
    const uint32_t uP = s2u(sm + AOFF_P);
    float* rs = (float*)(sm + AOFF_RS);

    const int bx = blockIdx.x;
    const int w  = bx / HEADS;
    const int h  = bx - w * HEADS;
    const int mw = w % NWIN;
    const int wd = mw >> 4, wh = (mw >> 2) & 3, ww = mw & 3;
    const int cls = ((wd == 3) << 2) | ((wh == 3) << 1) | (ww == 3);
    const int tid = threadIdx.x;
    const int lane = tid & 31;
    const int wid = tid >> 5;

    const __nv_bfloat16* base = qkv + (size_t)w * NTOK * (3 * CDIM);

    for (int idx = tid; idx < KPAD * 4; idx += 256) {
        int j = idx >> 2, s = idx & 3;
        uint4 v = make_uint4(0, 0, 0, 0);
        if (j < NTOK) v = *(const uint4*)(base + (size_t)j * (3 * CDIM) + CDIM + h * HD + s * 8);
        *(uint4*)(sm + AOFF_K + j * KPITCH + s * 16) = v;
    }
    for (int jp = tid; jp < KPAD / 2; jp += 256) {
        int j0 = jp * 2;
        __nv_bfloat16 ta[32], tb[32];
        if (j0 < NTOK) {
            const __nv_bfloat16* vp = base + (size_t)j0 * (3 * CDIM) + 2 * CDIM + h * HD;
#pragma unroll
            for (int s = 0; s < 4; s++) *(uint4*)(ta + s * 8) = *(const uint4*)(vp + s * 8);
        } else {
#pragma unroll
            for (int d = 0; d < 32; d++) ta[d] = __float2bfloat16(0.f);
        }
        if (j0 + 1 < NTOK) {
            const __nv_bfloat16* vp = base + (size_t)(j0 + 1) * (3 * CDIM) + 2 * CDIM + h * HD;
#pragma unroll
            for (int s = 0; s < 4; s++) *(uint4*)(tb + s * 8) = *(const uint4*)(vp + s * 8);
        } else {
#pragma unroll
            for (int d = 0; d < 32; d++) tb[d] = __float2bfloat16(0.f);
        }
#pragma unroll
        for (int d = 0; d < 32; d++) {
            __nv_bfloat162 p; p.x = ta[d]; p.y = tb[d];
            *(__nv_bfloat162*)(sm + AOFF_V + d * VPITCH + j0 * 2) = p;
        }
    }

    const int wm = wid & 3, wn = wid >> 2;
    const int vm = wid & 1, vn = wid >> 1;
    const int gq_ = lane >> 2, tg = lane & 3;
    const __nv_bfloat16* cb = comb + (size_t)(h * 8 + cls) * CPITCH * CPITCH;

    for (int qt = 0; qt < NCH; qt++) {
        const int q0 = qt * QT;
        for (int idx = tid; idx < QT * 4; idx += 256) {
            int r = idx >> 2, s = idx & 3;
            int gq = q0 + r;
            uint4 v = make_uint4(0, 0, 0, 0);
            if (gq < NTOK) v = *(const uint4*)(base + (size_t)gq * (3 * CDIM) + h * HD + s * 8);
            *(uint4*)(sm + AOFF_Q + r * QPITCH + s * 16) = v;
        }
        __syncthreads();

        float acc_o[2][4];
#pragma unroll
        for (int t = 0; t < 2; t++)
#pragma unroll
            for (int c = 0; c < 4; c++) acc_o[t][c] = 0.f;
        float rs0 = 0.f, rs1 = 0.f;

        const int r0g = q0 + wm * 16 + gq_;
        const __nv_bfloat16* c0p = cb + (size_t)r0g * CPITCH;
        const __nv_bfloat16* c1p = c0p + 8 * CPITCH;

        for (int ch = 0; ch < NCH; ch++) {
            const int j0 = ch * NC;
            float acc[4][4];
#pragma unroll
            for (int t = 0; t < 4; t++)
#pragma unroll
                for (int c = 0; c < 4; c++) acc[t][c] = 0.f;

#pragma unroll
            for (int ks = 0; ks < 2; ks++) {
                uint32_t a0, a1, a2, a3;
                LDMX4(a0, a1, a2, a3,
                      uQ + (uint32_t)((wm * 16 + (lane & 15)) * QPITCH + ks * 32 + (lane >> 4) * 16));
#pragma unroll
                for (int nj = 0; nj < 2; nj++) {
                    uint32_t r0, r1, r2, r3;
                    LDMX4(r0, r1, r2, r3,
                          uK + (uint32_t)((j0 + wn * 32 + nj * 16 + (lane & 15)) * KPITCH + ks * 32 + (lane >> 4) * 16));
                    MMA16816(acc[2 * nj], a0, a1, a2, a3, r0, r2);
                    MMA16816(acc[2 * nj + 1], a0, a1, a2, a3, r1, r3);
                }
            }

#pragma unroll
            for (int ti = 0; ti < 4; ti++) {
                int jl = wn * 32 + (ti >> 1) * 16 + (ti & 1) * 8 + tg * 2;
                int ja = j0 + jl;
                __nv_bfloat162 b0 = *(const __nv_bfloat162*)(c0p + ja);
                __nv_bfloat162 b1 = *(const __nv_bfloat162*)(c1p + ja);
                float e00 = exp2f(acc[ti][0] + __bfloat162float(b0.x));
                float e01 = exp2f(acc[ti][1] + __bfloat162float(b0.y));
                float e10 = exp2f(acc[ti][2] + __bfloat162float(b1.x));
                float e11 = exp2f(acc[ti][3] + __bfloat162float(b1.y));
                rs0 += e00 + e01;
                rs1 += e10 + e11;
                __nv_bfloat162 p0, p1;
                p0.x = __float2bfloat16(e00); p0.y = __float2bfloat16(e01);
                p1.x = __float2bfloat16(e10); p1.y = __float2bfloat16(e11);
                int rloc0 = wm * 16 + gq_;
                *(__nv_bfloat162*)(sm + AOFF_P + rloc0 * PPITCH + jl * 2) = p0;
                *(__nv_bfloat162*)(sm + AOFF_P + (rloc0 + 8) * PPITCH + jl * 2) = p1;
            }
            __syncthreads();

#pragma unroll
            for (int kk = 0; kk < 4; kk++) {
                uint32_t a0, a1, a2, a3;
                LDMX4(a0, a1, a2, a3,
                      uV + (uint32_t)((vm * 16 + (lane & 15)) * VPITCH + j0 * 2 + kk * 32 + (lane >> 4) * 16));
                uint32_t r0, r1, r2, r3;
                LDMX4(r0, r1, r2, r3,
                      uP + (uint32_t)((vn * 16 + (lane & 15)) * PPITCH + kk * 32 + (lane >> 4) * 16));
                MMA16816(acc_o[0], a0, a1, a2, a3, r0, r2);
                MMA16816(acc_o[1], a0, a1, a2, a3, r1, r3);
            }
            __syncthreads();
        }

        rs0 += __shfl_xor_sync(0xffffffffu, rs0, 1);
        rs0 += __shfl_xor_sync(0xffffffffu, rs0, 2);
        rs1 += __shfl_xor_sync(0xffffffffu, rs1, 1);
        rs1 += __shfl_xor_sync(0xffffffffu, rs1, 2);
        if (tg == 0) {
            rs[(wm * 16 + gq_) * 2 + wn] = rs0;
            rs[(wm * 16 + gq_ + 8) * 2 + wn] = rs1;
        }

        float* Ost = (float*)(sm + AOFF_P);
#pragma unroll
        for (int t = 0; t < 2; t++) {
            int qc = vn * 16 + t * 8 + tg * 2;
            int d0 = vm * 16 + gq_;
            Ost[d0 * 65 + qc]     = acc_o[t][0];
            Ost[d0 * 65 + qc + 1] = acc_o[t][1];
            Ost[(d0 + 8) * 65 + qc]     = acc_o[t][2];
            Ost[(d0 + 8) * 65 + qc + 1] = acc_o[t][3];
        }
        __syncthreads();

        {
            int q = tid >> 2, ds = (tid & 3) * 8;
            int gq = q0 + q;
            if (gq < NTOK) {
                float inv = __frcp_rn(rs[q * 2] + rs[q * 2 + 1]);
                __nv_bfloat16 o[8];
#pragma unroll
                for (int u = 0; u < 8; u++)
                    o[u] = __float2bfloat16(Ost[(ds + u) * 65 + q] * inv);
                *(uint4*)(out + (size_t)(w * NTOK + gq) * CDIM + h * HD + ds) = *(uint4*)o;
            }
        }
        __syncthreads();
    }
}

// ---------------- pure LN2 ----------------
__global__ __launch_bounds__(256) void ln2_kernel(const float* __restrict__ xres,
                                                  const float* __restrict__ g,
                                                  const float* __restrict__ b,
                                                  __nv_bfloat16* __restrict__ ln2o) {
    int t = blockIdx.x * 8 + (threadIdx.x >> 5);
    int lane = threadIdx.x & 31;
    const float2* xp = (const float2*)(xres + (size_t)t * CDIM);
    const float2* gp = (const float2*)g;
    const float2* bp = (const float2*)b;
    float2 v[3];
    float s = 0.f, s2 = 0.f;
#pragma unroll
    for (int i = 0; i < 3; i++) {
        v[i] = xp[lane + i * 32];
        s += v[i].x + v[i].y;
        s2 += v[i].x * v[i].x + v[i].y * v[i].y;
    }
    s = warpSum(s); s2 = warpSum(s2);
    float mean = s * (1.0f / CDIM);
    float rstd = rsqrtf(s2 * (1.0f / CDIM) - mean * mean + 1e-5f);
    __nv_bfloat162* op = (__nv_bfloat162*)(ln2o + (size_t)t * CDIM);
#pragma unroll
    for (int i = 0; i < 3; i++) {
        int c = lane + i * 32;
        float2 gg = gp[c], bb = bp[c];
        __nv_bfloat162 o;
        o.x = __float2bfloat16((v[i].x - mean) * rstd * gg.x + bb.x);
        o.y = __float2bfloat16((v[i].y - mean) * rstd * gg.y + bb.y);
        op[c] = o;
    }
}

// ---------------- host-side stream/event singletons (created pre-capture) ----------------
static cudaStream_t make_stream() {
    cudaStream_t s;
    cudaStreamCreateWithFlags(&s, cudaStreamNonBlocking);
    return s;
}
static cudaEvent_t make_event() {
    cudaEvent_t e;
    cudaEventCreateWithFlags(&e, cudaEventDisableTiming);
    return e;
}

// ---------------- launch ----------------
extern "C" void kernel_launch(void* const* d_in, const int* in_sizes, int n_in,
                              void* d_out, int out_size) {
    (void)in_sizes; (void)n_in; (void)out_size;
    const float* x       = (const float*)d_in[0];
    const float* table   = (const float*)d_in[3];
    const float* n1g     = (const float*)d_in[4];
    const float* n1b     = (const float*)d_in[5];
    const float* qkv_w   = (const float*)d_in[6];
    const float* qkv_b   = (const float*)d_in[7];
    const float* proj_w  = (const float*)d_in[8];
    const float* proj_b  = (const float*)d_in[9];
    const float* n2g     = (const float*)d_in[10];
    const float* n2b     = (const float*)d_in[11];
    const float* fc1_w   = (const float*)d_in[12];
    const float* fc1_b   = (const float*)d_in[13];
    const float* fc2_w   = (const float*)d_in[14];
    const float* fc2_b   = (const float*)d_in[15];
    float* out = (float*)d_out;

    __nv_bfloat16 *xwb, *qkvb, *attnb, *ln2b, *h1b, *wqkv, *wproj, *wfc1, *wfc2, *comb;
    float *xres, *qbias;
    cudaGetSymbolAddress((void**)&xwb,   g_xwb);
    cudaGetSymbolAddress((void**)&qkvb,  g_qkvb);
    cudaGetSymbolAddress((void**)&attnb, g_attnb);
    cudaGetSymbolAddress((void**)&xres,  g_xres);
    cudaGetSymbolAddress((void**)&ln2b,  g_ln2b);
    cudaGetSymbolAddress((void**)&h1b,   g_h1b);
    cudaGetSymbolAddress((void**)&wqkv,  g_wqkv);
    cudaGetSymbolAddress((void**)&wproj, g_wproj);
    cudaGetSymbolAddress((void**)&wfc1,  g_wfc1);
    cudaGetSymbolAddress((void**)&wfc2,  g_wfc2);
    cudaGetSymbolAddress((void**)&comb,  g_comb);
    cudaGetSymbolAddress((void**)&qbias, g_qbias);

    cudaFuncSetAttribute(attn_tc_kernel, cudaFuncAttributeMaxDynamicSharedMemorySize,
                         ATTN_SMEM_BYTES);
    cudaFuncSetAttribute((gemm_mma_kernel<3, true>), cudaFuncAttributeMaxDynamicSharedMemorySize, GEMM_SMEM_BYTES);
    cudaFuncSetAttribute((gemm_mma_kernel<4, true>), cudaFuncAttributeMaxDynamicSharedMemorySize, GEMM_SMEM_BYTES);
    cudaFuncSetAttribute((gemm_mma_kernel<1, true>), cudaFuncAttributeMaxDynamicSharedMemorySize, GEMM_SMEM_BYTES);
    cudaFuncSetAttribute((gemm_mma_kernel<2, false>), cudaFuncAttributeMaxDynamicSharedMemorySize, GEMM_SMEM_BYTES);

    // streams/events created once (first call = correctness run, pre-capture)
    static cudaStream_t s1 = make_stream();
    static cudaStream_t s2 = make_stream();
    static cudaEvent_t ev_root = make_event();
    static cudaEvent_t ev_w    = make_event();
    static cudaEvent_t ev_c    = make_event();

    const int n0 = 3 * CDIM * CDIM, n1 = CDIM * CDIM, n2 = HID * CDIM, n3 = CDIM * HID;

    // fork side streams from main stream
    cudaEventRecord(ev_root, 0);
    cudaStreamWaitEvent(s1, ev_root, 0);
    cudaStreamWaitEvent(s2, ev_root, 0);

    // stream s1: weight conversions (needed before QKV GEMM)
    cvt4_kernel<<<(n0 + n1 + n2 + n3 + 255) / 256, 256, 0, s1>>>(
        qkv_w, wqkv, n0, proj_w, wproj, n1, fc1_w, wfc1, n2, fc2_w, wfc2, n3);
    biasq_kernel<<<3, 192, 0, s1>>>(qkv_b, qbias);
    cudaEventRecord(ev_w, s1);

    // stream s2: combined bias+mask (needed before attention)
    comb_pre_kernel<<<(COMB_ELEMS + 255) / 256, 256, 0, s2>>>(table, comb);
    cudaEventRecord(ev_c, s2);

    // main stream: LN1 runs concurrently with the precompute
    ln1_kernel<<<TOK / 8, 256>>>(x, n1g, n1b, xwb);

    cudaStreamWaitEvent(0, ev_w, 0);
    gemm_mma_kernel<3, true><<<dim3(576 / BN, TOK / BM), 256, GEMM_SMEM_BYTES>>>(
        xwb, wqkv, qbias, nullptr, qkvb, CDIM, 3 * CDIM);

    cudaStreamWaitEvent(0, ev_c, 0);
    attn_tc_kernel<<<TOTWIN * HEADS, 256, ATTN_SMEM_BYTES>>>(qkvb, comb, attnb);

    gemm_mma_kernel<4, true><<<dim3(CDIM / BN, TOK / BM), 256, GEMM_SMEM_BYTES>>>(
        attnb, wproj, proj_b, x, xres, CDIM, CDIM);
    ln2_kernel<<<TOK / 8, 256>>>(xres, n2g, n2b, ln2b);
    gemm_mma_kernel<1, true><<<dim3(HID / BN, TOK / BM), 256, GEMM_SMEM_BYTES>>>(
        ln2b, wfc1, fc1_b, nullptr, h1b, CDIM, HID);
    gemm_mma_kernel<2, false><<<dim3(CDIM / BN, TOK / BM), 256, GEMM_SMEM_BYTES>>>(
        h1b, wfc2, fc2_b, xres, out, HID, CDIM);
}

// round 14
// speedup vs baseline: 1.1391x; 1.0153x over previous
#include <cuda_runtime.h>
#include <cuda_bf16.h>
#include <math.h>
#include <stdint.h>

// ---------------- problem constants ----------------
#define BATCH   2
#define DSZ     28
#define WS      7
#define SHIFT_  3
#define CDIM    192
#define HEADS   6
#define HD      32
#define NTOK    343
#define NWIN    64
#define TOTWIN  128
#define TOK     43904
#define HID     768
#define SCALE   0.17677669529663687f
#define LOG2E   1.4426950408889634f
#define QFOLD   (SCALE * LOG2E)

// GEMM tiling (CTA 128x64, warp 32x32)
#define BM      128
#define BN      64
#define KB      64
#define GEMM_SMEM_BYTES 73728

// attention tiling
#define QT      64
#define NC      64
#define KPAD    384
#define NCH     6
#define QPITCH  80
#define KPITCH  80
#define VPITCH  784
#define PPITCH  144
#define CPITCH  384
// smem offsets (bytes)
#define AOFF_K   0
#define AOFF_V   30720
#define AOFF_Q   55808
#define AOFF_P   60928
#define AOFF_RS  70144
#define ATTN_SMEM_BYTES 70656

#define COMB_ELEMS (48 * CPITCH * CPITCH)

// ---------------- scratch (device globals) ----------------
__device__ __nv_bfloat16 g_xwb [TOK * CDIM];
__device__ __nv_bfloat16 g_qkvb[TOK * 3 * CDIM];
__device__ __nv_bfloat16 g_attnb[TOK * CDIM];
__device__ float         g_xres[TOK * CDIM];
__device__ __nv_bfloat16 g_ln2b[TOK * CDIM];
__device__ __nv_bfloat16 g_h1b [TOK * HID];
__device__ __nv_bfloat16 g_wqkv[3 * CDIM * CDIM];
__device__ __nv_bfloat16 g_wproj[CDIM * CDIM];
__device__ __nv_bfloat16 g_wfc1[HID * CDIM];
__device__ __nv_bfloat16 g_wfc2[CDIM * HID];
__device__ __nv_bfloat16 g_comb[COMB_ELEMS];
__device__ float         g_qbias[3 * CDIM];

// ---------------- helpers ----------------
__device__ __forceinline__ uint32_t s2u(const void* p) {
    uint32_t r;
    asm("{ .reg .u64 t; cvta.to.shared.u64 t, %1; cvt.u32.u64 %0, t; }" : "=r"(r) : "l"(p));
    return r;
}
__device__ __forceinline__ float warpSum(float v) {
#pragma unroll
    for (int o = 16; o; o >>= 1) v += __shfl_xor_sync(0xffffffffu, v, o);
    return v;
}
__device__ __forceinline__ int token_to_winrow(int t) {
    int b   = t / (DSZ * DSZ * DSZ);
    int rem = t - b * (DSZ * DSZ * DSZ);
    int dd  = rem / (DSZ * DSZ);
    int hh  = (rem / DSZ) % DSZ;
    int ww  = rem % DSZ;
    int i = (dd + DSZ - SHIFT_) % DSZ;
    int j = (hh + DSZ - SHIFT_) % DSZ;
    int k = (ww + DSZ - SHIFT_) % DSZ;
    int win = (i / WS) * 16 + (j / WS) * 4 + (k / WS);
    int n   = (i % WS) * 49 + (j % WS) * 7 + (k % WS);
    return (b * NWIN + win) * NTOK + n;
}
__device__ __forceinline__ int winrow_to_token(int r) {
    int win = r / NTOK;
    int n   = r - win * NTOK;
    int b   = win >> 6;
    int w64 = win & 63;
    int ni = n / 49, rem = n - ni * 49;
    int nj = rem / 7, nk = rem - nj * 7;
    int i = (w64 >> 4) * 7 + ni;
    int j = ((w64 >> 2) & 3) * 7 + nj;
    int k = (w64 & 3) * 7 + nk;
    int dd = i + SHIFT_; if (dd >= DSZ) dd -= DSZ;
    int hh = j + SHIFT_; if (hh >= DSZ) hh -= DSZ;
    int ww = k + SHIFT_; if (ww >= DSZ) ww -= DSZ;
    return b * (DSZ * DSZ * DSZ) + dd * (DSZ * DSZ) + hh * DSZ + ww;
}

// packed f32x2 -> bf16x2 (one CVT): dst u32 = {hi:hi_val, lo:lo_val}
#define CVTPK(dst, lo_val, hi_val) \
    asm("cvt.rn.satfinite.bf16x2.f32 %0, %1, %2;" : "=r"(dst) : "f"(hi_val), "f"(lo_val))

// fast exact-ish GELU (tanh form, exp2-based)
__device__ __forceinline__ float gelu_fast(float xv) {
    float u  = xv * (0.7978845608028654f + 0.035677408136300125f * xv * xv);
    float au = fabsf(u);
    float t  = __frcp_rn(1.0f + exp2f(au * 2.8853900817779268f));
    float th = copysignf(1.0f - 2.0f * t, u);
    return 0.5f * xv * (1.0f + th);
}

#define CP_ASYNC16(dst_u32, src_ptr) \
    asm volatile("cp.async.cg.shared.global [%0], [%1], 16;" :: "r"(dst_u32), "l"(src_ptr))
#define CP_COMMIT() asm volatile("cp.async.commit_group;")
#define CP_WAIT(n)  asm volatile("cp.async.wait_group %0;" :: "n"(n))

#define LDMX4(r0, r1, r2, r3, addr) \
    asm volatile("ldmatrix.sync.aligned.m8n8.x4.shared.b16 {%0,%1,%2,%3}, [%4];" \
                 : "=r"(r0), "=r"(r1), "=r"(r2), "=r"(r3) : "r"(addr))

#define MMA16816(d, a0, a1, a2, a3, b0, b1) \
    asm volatile("mma.sync.aligned.m16n8k16.row.col.f32.bf16.bf16.f32 " \
                 "{%0,%1,%2,%3}, {%4,%5,%6,%7}, {%8,%9}, {%0,%1,%2,%3};" \
                 : "+f"((d)[0]), "+f"((d)[1]), "+f"((d)[2]), "+f"((d)[3]) \
                 : "r"(a0), "r"(a1), "r"(a2), "r"(a3), "r"(b0), "r"(b1))

// ---------------- merged weight conversion (q-rows folded) ----------------
__global__ void cvt4_kernel(const float* __restrict__ s0, __nv_bfloat16* __restrict__ d0, int n0,
                            const float* __restrict__ s1, __nv_bfloat16* __restrict__ d1, int n1,
                            const float* __restrict__ s2, __nv_bfloat16* __restrict__ d2, int n2,
                            const float* __restrict__ s3, __nv_bfloat16* __restrict__ d3, int n3) {
    int i = blockIdx.x * 256 + threadIdx.x;
    if (i < n0) {
        float v = s0[i];
        if (i < CDIM * CDIM) v *= QFOLD;
        d0[i] = __float2bfloat16(v);
        return;
    }
    i -= n0;
    if (i < n1) { d1[i] = __float2bfloat16(s1[i]); return; }
    i -= n1;
    if (i < n2) { d2[i] = __float2bfloat16(s2[i]); return; }
    i -= n2;
    if (i < n3) { d3[i] = __float2bfloat16(s3[i]); }
}

__global__ void biasq_kernel(const float* __restrict__ qkv_b, float* __restrict__ qb) {
    int i = blockIdx.x * 192 + threadIdx.x;
    if (i < 3 * CDIM) qb[i] = (i < CDIM) ? qkv_b[i] * QFOLD : qkv_b[i];
}

// ---------------- combined bias+mask precompute ----------------
__global__ void comb_pre_kernel(const float* __restrict__ table,
                                __nv_bfloat16* __restrict__ comb) {
    int idx = blockIdx.x * 256 + threadIdx.x;
    if (idx >= COMB_ELEMS) return;
    int col  = idx % CPITCH;
    int row  = (idx / CPITCH) % CPITCH;
    int hc   = idx / (CPITCH * CPITCH);
    int h = hc >> 3, cls = hc & 7;
    float val = -160.f;
    if (col < NTOK && row < NTOK) {
        int i3 = row / 49, j3 = (row / 7) % 7, k3 = row % 7;
        int ci = col / 49, cj = (col / 7) % 7, ck = col % 7;
        int rel = (i3 - ci + 6) * 169 + (j3 - cj + 6) * 13 + (k3 - ck + 6);
        float v = table[rel * HEADS + h];
        bool diff = ((cls & 4) && ((i3 < 4) != (ci < 4))) ||
                    ((cls & 2) && ((j3 < 4) != (cj < 4))) ||
                    ((cls & 1) && ((k3 < 4) != (ck < 4)));
        if (diff) v -= 100.f;
        val = v * LOG2E;
    }
    comb[idx] = __float2bfloat16(val);
}

// ---------------- LN1 + shift + partition ----------------
__global__ __launch_bounds__(256) void ln1_kernel(const float* __restrict__ x,
                                                  const float* __restrict__ g,
                                                  const float* __restrict__ b,
                                                  __nv_bfloat16* __restrict__ xw) {
    int t = blockIdx.x * 8 + (threadIdx.x >> 5);
    int lane = threadIdx.x & 31;
    const float2* xp = (const float2*)(x + (size_t)t * CDIM);
    const float2* gp = (const float2*)g;
    const float2* bp = (const float2*)b;
    float2 v[3];
    float s = 0.f, s2 = 0.f;
#pragma unroll
    for (int i = 0; i < 3; i++) {
        v[i] = xp[lane + i * 32];
        s += v[i].x + v[i].y;
        s2 += v[i].x * v[i].x + v[i].y * v[i].y;
    }
    s = warpSum(s); s2 = warpSum(s2);
    float mean = s * (1.0f / CDIM);
    float rstd = rsqrtf(s2 * (1.0f / CDIM) - mean * mean + 1e-5f);
    int row = token_to_winrow(t);
    uint32_t* op = (uint32_t*)(xw + (size_t)row * CDIM);
#pragma unroll
    for (int i = 0; i < 3; i++) {
        int c = lane + i * 32;
        float2 gg = gp[c], bb = bp[c];
        float o0 = (v[i].x - mean) * rstd * gg.x + bb.x;
        float o1 = (v[i].y - mean) * rstd * gg.y + bb.y;
        uint32_t pk; CVTPK(pk, o0, o1);
        op[c] = pk;
    }
}

// ---------------- GEMM tile loader ----------------
__device__ __forceinline__ void gemm_issue(const __nv_bfloat16* __restrict__ A,
                                           const __nv_bfloat16* __restrict__ Wt,
                                           int bm, int bn, int Ktot, int lr, int lc8,
                                           char* bA, char* bB, int k0) {
#pragma unroll
    for (int rr = 0; rr < 4; rr++) {
        int r = lr + rr * 32;
        uint32_t off = (uint32_t)(r * 128 + lc8 * 2);
        off ^= (off >> 3) & 0x70;
        CP_ASYNC16(s2u(bA + off), A + (size_t)(bm + r) * Ktot + k0 + lc8);
    }
#pragma unroll
    for (int rr = 0; rr < 2; rr++) {
        int br = lr + rr * 32;
        uint32_t off = (uint32_t)(br * 128 + lc8 * 2);
        off ^= (off >> 3) & 0x70;
        CP_ASYNC16(s2u(bB + off), Wt + (size_t)(bn + br) * Ktot + k0 + lc8);
    }
    CP_COMMIT();
}

// ---------------- HMMA bf16 GEMM ----------------
// EPI: 0 = bias -> fp32; 1 = bias+gelu -> bf16; 2 = bias+resid -> fp32;
//      3 = bias -> bf16;  4 = bias + x[token] -> xres[token] (row-permuted)
template <int EPI, bool FULLK>
__global__ __launch_bounds__(256)
void gemm_mma_kernel(const __nv_bfloat16* __restrict__ A,
                     const __nv_bfloat16* __restrict__ Wt,
                     const float* __restrict__ bias,
                     const float* __restrict__ resid,
                     void* __restrict__ Cv, int Ktot, int Ntot)
{
    extern __shared__ __align__(1024) char dsm[];
    char* bufA[3] = {dsm, dsm + 16384, dsm + 32768};
    char* bufB[3] = {dsm + 49152, dsm + 57344, dsm + 65536};

    const int tid = threadIdx.x;
    const int lane = tid & 31;
    const int wid = tid >> 5;
    const int wm = (wid & 3) * 32;
    const int wn = (wid >> 2) * 32;
    const int bm = blockIdx.y * BM;
    const int bn = blockIdx.x * BN;

    float acc[2][4][4];
#pragma unroll
    for (int a = 0; a < 2; a++)
#pragma unroll
        for (int b = 0; b < 4; b++)
#pragma unroll
            for (int c = 0; c < 4; c++) acc[a][b][c] = 0.f;

    const int lr = tid >> 3;
    const int lc8 = (tid & 7) * 8;

    if (FULLK) {
#pragma unroll
        for (int ch = 0; ch < 3; ch++)
            gemm_issue(A, Wt, bm, bn, Ktot, lr, lc8, bufA[ch], bufB[ch], ch * KB);
#pragma unroll
        for (int chunk = 0; chunk < 3; chunk++) {
            if (chunk == 0)      CP_WAIT(2);
            else if (chunk == 1) CP_WAIT(1);
            else                 CP_WAIT(0);
            __syncthreads();
            const uint32_t sA = s2u(bufA[chunk]);
            const uint32_t sB = s2u(bufB[chunk]);
#pragma unroll
            for (int kk = 0; kk < 4; kk++) {
                uint32_t a0[2], a1[2], a2[2], a3[2];
#pragma unroll
                for (int mi = 0; mi < 2; mi++) {
                    uint32_t off = (uint32_t)((wm + mi * 16 + (lane & 15)) * 128 + kk * 32 + (lane >> 4) * 16);
                    off ^= (off >> 3) & 0x70;
                    LDMX4(a0[mi], a1[mi], a2[mi], a3[mi], sA + off);
                }
#pragma unroll
                for (int nj = 0; nj < 2; nj++) {
                    uint32_t off = (uint32_t)((wn + nj * 16 + (lane & 15)) * 128 + kk * 32 + (lane >> 4) * 16);
                    off ^= (off >> 3) & 0x70;
                    uint32_t r0, r1, r2, r3;
                    LDMX4(r0, r1, r2, r3, sB + off);
#pragma unroll
                    for (int mi = 0; mi < 2; mi++) {
                        MMA16816(acc[mi][2 * nj], a0[mi], a1[mi], a2[mi], a3[mi], r0, r2);
                        MMA16816(acc[mi][2 * nj + 1], a0[mi], a1[mi], a2[mi], a3[mi], r1, r3);
                    }
                }
            }
        }
    } else {
        const int nch = Ktot / KB;
        gemm_issue(A, Wt, bm, bn, Ktot, lr, lc8, bufA[0], bufB[0], 0);
        gemm_issue(A, Wt, bm, bn, Ktot, lr, lc8, bufA[1], bufB[1], KB);
        for (int ch = 0; ch < nch; ch++) {
            if (ch + 2 < nch)
                gemm_issue(A, Wt, bm, bn, Ktot, lr, lc8,
                           bufA[(ch + 2) % 3], bufB[(ch + 2) % 3], (ch + 2) * KB);
            const int rem = nch - ch - 1;
            if (rem >= 2)      CP_WAIT(2);
            else if (rem == 1) CP_WAIT(1);
            else               CP_WAIT(0);
            __syncthreads();

            const uint32_t sA = s2u(bufA[ch % 3]);
            const uint32_t sB = s2u(bufB[ch % 3]);
#pragma unroll
            for (int kk = 0; kk < KB / 16; kk++) {
                uint32_t a0[2], a1[2], a2[2], a3[2];
#pragma unroll
                for (int mi = 0; mi < 2; mi++) {
                    uint32_t off = (uint32_t)((wm + mi * 16 + (lane & 15)) * 128 + kk * 32 + (lane >> 4) * 16);
                    off ^= (off >> 3) & 0x70;
                    LDMX4(a0[mi], a1[mi], a2[mi], a3[mi], sA + off);
                }
#pragma unroll
                for (int nj = 0; nj < 2; nj++) {
                    uint32_t off = (uint32_t)((wn + nj * 16 + (lane & 15)) * 128 + kk * 32 + (lane >> 4) * 16);
                    off ^= (off >> 3) & 0x70;
                    uint32_t r0, r1, r2, r3;
                    LDMX4(r0, r1, r2, r3, sB + off);
#pragma unroll
                    for (int mi = 0; mi < 2; mi++) {
                        MMA16816(acc[mi][2 * nj], a0[mi], a1[mi], a2[mi], a3[mi], r0, r2);
                        MMA16816(acc[mi][2 * nj + 1], a0[mi], a1[mi], a2[mi], a3[mi], r1, r3);
                    }
                }
            }
            __syncthreads();
        }
    }

    const int gq = lane >> 2;
    const int tg = lane & 3;
#pragma unroll
    for (int mi = 0; mi < 2; mi++) {
#pragma unroll
        for (int half = 0; half < 2; half++) {
            int row = bm + wm + mi * 16 + gq + half * 8;
            int orow = row;
            if (EPI == 4) orow = winrow_to_token(row);
#pragma unroll
            for (int ni = 0; ni < 4; ni++) {
                int col = bn + wn + ni * 8 + tg * 2;
                float bia0 = bias[col], bia1 = bias[col + 1];
                float v0 = acc[mi][ni][half * 2 + 0] + bia0;
                float v1 = acc[mi][ni][half * 2 + 1] + bia1;
                size_t oi = (size_t)orow * Ntot + col;
                if (EPI == 1) {
                    v0 = gelu_fast(v0);
                    v1 = gelu_fast(v1);
                    uint32_t pk; CVTPK(pk, v0, v1);
                    *(uint32_t*)((__nv_bfloat16*)Cv + oi) = pk;
                } else if (EPI == 2 || EPI == 4) {
                    float2 rv = *(const float2*)(resid + oi);
                    float2 o; o.x = v0 + rv.x; o.y = v1 + rv.y;
                    *(float2*)((float*)Cv + oi) = o;
                } else if (EPI == 3) {
                    uint32_t pk; CVTPK(pk, v0, v1);
                    *(uint32_t*)((__nv_bfloat16*)Cv + oi) = pk;
                } else {
                    float2 o; o.x = v0; o.y = v1;
                    *(float2*)((float*)Cv + oi) = o;
                }
            }
        }
    }
}

// ---------------- tensor-core attention: persistent K/V, loop q-tiles ----------------
__global__ __launch_bounds__(256, 3) void attn_tc_kernel(
    const __nv_bfloat16* __restrict__ qkv, const __nv_bfloat16* __restrict__ comb,
    __nv_bfloat16* __restrict__ out)
{
    extern __shared__ __align__(1024) char sm[];
    const uint32_t uK = s2u(sm + AOFF_K);
    const uint32_t uV = s2u(sm + AOFF_V);
    const uint32_t uQ = s2u(sm + AOFF_Q);
    const uint32_t uP = s2u(sm + AOFF_P);
    float* rs = (float*)(sm + AOFF_RS);

    const int bx = blockIdx.x;
    const int w  = bx / HEADS;
    const int h  = bx - w * HEADS;
    const int mw = w % NWIN;
    const int wd = mw >> 4, wh = (mw >> 2) & 3, ww = mw & 3;
    const int cls = ((wd == 3) << 2) | ((wh == 3) << 1) | (ww == 3);
    const int tid = threadIdx.x;
    const int lane = tid & 31;
    const int wid = tid >> 5;

    const __nv_bfloat16* base = qkv + (size_t)w * NTOK * (3 * CDIM);

    for (int idx = tid; idx < KPAD * 4; idx += 256) {
        int j = idx >> 2, s = idx & 3;
        uint4 v = make_uint4(0, 0, 0, 0);
        if (j < NTOK) v = *(const uint4*)(base + (size_t)j * (3 * CDIM) + CDIM + h * HD + s * 8);
        *(uint4*)(sm + AOFF_K + j * KPITCH + s * 16) = v;
    }
    for (int jp = tid; jp < KPAD / 2; jp += 256) {
        int j0 = jp * 2;
        __nv_bfloat16 ta[32], tb[32];
        if (j0 < NTOK) {
            const __nv_bfloat16* vp = base + (size_t)j0 * (3 * CDIM) + 2 * CDIM + h * HD;
#pragma unroll
            for (int s = 0; s < 4; s++) *(uint4*)(ta + s * 8) = *(const uint4*)(vp + s * 8);
        } else {
#pragma unroll
            for (int d = 0; d < 32; d++) ta[d] = __float2bfloat16(0.f);
        }
        if (j0 + 1 < NTOK) {
            const __nv_bfloat16* vp = base + (size_t)(j0 + 1) * (3 * CDIM) + 2 * CDIM + h * HD;
#pragma unroll
            for (int s = 0; s < 4; s++) *(uint4*)(tb + s * 8) = *(const uint4*)(vp + s * 8);
        } else {
#pragma unroll
            for (int d = 0; d < 32; d++) tb[d] = __float2bfloat16(0.f);
        }
#pragma unroll
        for (int d = 0; d < 32; d++) {
            __nv_bfloat162 p; p.x = ta[d]; p.y = tb[d];
            *(__nv_bfloat162*)(sm + AOFF_V + d * VPITCH + j0 * 2) = p;
        }
    }

    const int wm = wid & 3, wn = wid >> 2;
    const int vm = wid & 1, vn = wid >> 1;
    const int gq_ = lane >> 2, tg = lane & 3;
    const __nv_bfloat16* cb = comb + (size_t)(h * 8 + cls) * CPITCH * CPITCH;

    for (int qt = 0; qt < NCH; qt++) {
        const int q0 = qt * QT;
        for (int idx = tid; idx < QT * 4; idx += 256) {
            int r = idx >> 2, s = idx & 3;
            int gq = q0 + r;
            uint4 v = make_uint4(0, 0, 0, 0);
            if (gq < NTOK) v = *(const uint4*)(base + (size_t)gq * (3 * CDIM) + h * HD + s * 8);
            *(uint4*)(sm + AOFF_Q + r * QPITCH + s * 16) = v;
        }
        __syncthreads();

        float acc_o[2][4];
#pragma unroll
        for (int t = 0; t < 2; t++)
#pragma unroll
            for (int c = 0; c < 4; c++) acc_o[t][c] = 0.f;
        float rs0 = 0.f, rs1 = 0.f;

        const int r0g = q0 + wm * 16 + gq_;
        const __nv_bfloat16* c0p = cb + (size_t)r0g * CPITCH;
        const __nv_bfloat16* c1p = c0p + 8 * CPITCH;

        for (int ch = 0; ch < NCH; ch++) {
            const int j0 = ch * NC;
            float acc[4][4];
#pragma unroll
            for (int t = 0; t < 4; t++)
#pragma unroll
                for (int c = 0; c < 4; c++) acc[t][c] = 0.f;

#pragma unroll
            for (int ks = 0; ks < 2; ks++) {
                uint32_t a0, a1, a2, a3;
                LDMX4(a0, a1, a2, a3,
                      uQ + (uint32_t)((wm * 16 + (lane & 15)) * QPITCH + ks * 32 + (lane >> 4) * 16));
#pragma unroll
                for (int nj = 0; nj < 2; nj++) {
                    uint32_t r0, r1, r2, r3;
                    LDMX4(r0, r1, r2, r3,
                          uK + (uint32_t)((j0 + wn * 32 + nj * 16 + (lane & 15)) * KPITCH + ks * 32 + (lane >> 4) * 16));
                    MMA16816(acc[2 * nj], a0, a1, a2, a3, r0, r2);
                    MMA16816(acc[2 * nj + 1], a0, a1, a2, a3, r1, r3);
                }
            }

#pragma unroll
            for (int ti = 0; ti < 4; ti++) {
                int jl = wn * 32 + (ti >> 1) * 16 + (ti & 1) * 8 + tg * 2;
                int ja = j0 + jl;
                __nv_bfloat162 b0 = *(const __nv_bfloat162*)(c0p + ja);
                __nv_bfloat162 b1 = *(const __nv_bfloat162*)(c1p + ja);
                float e00 = exp2f(acc[ti][0] + __bfloat162float(b0.x));
                float e01 = exp2f(acc[ti][1] + __bfloat162float(b0.y));
                float e10 = exp2f(acc[ti][2] + __bfloat162float(b1.x));
                float e11 = exp2f(acc[ti][3] + __bfloat162float(b1.y));
                rs0 += e00 + e01;
                rs1 += e10 + e11;
                uint32_t p0, p1;
                CVTPK(p0, e00, e01);
                CVTPK(p1, e10, e11);
                int rloc0 = wm * 16 + gq_;
                *(uint32_t*)(sm + AOFF_P + rloc0 * PPITCH + jl * 2) = p0;
                *(uint32_t*)(sm + AOFF_P + (rloc0 + 8) * PPITCH + jl * 2) = p1;
            }
            __syncthreads();

#pragma unroll
            for (int kk = 0; kk < 4; kk++) {
                uint32_t a0, a1, a2, a3;
                LDMX4(a0, a1, a2, a3,
                      uV + (uint32_t)((vm * 16 + (lane & 15)) * VPITCH + j0 * 2 + kk * 32 + (lane >> 4) * 16));
                uint32_t r0, r1, r2, r3;
                LDMX4(r0, r1, r2, r3,
                      uP + (uint32_t)((vn * 16 + (lane & 15)) * PPITCH + kk * 32 + (lane >> 4) * 16));
                MMA16816(acc_o[0], a0, a1, a2, a3, r0, r2);
                MMA16816(acc_o[1], a0, a1, a2, a3, r1, r3);
            }
            __syncthreads();
        }

        rs0 += __shfl_xor_sync(0xffffffffu, rs0, 1);
        rs0 += __shfl_xor_sync(0xffffffffu, rs0, 2);
        rs1 += __shfl_xor_sync(0xffffffffu, rs1, 1);
        rs1 += __shfl_xor_sync(0xffffffffu, rs1, 2);
        if (tg == 0) {
            rs[(wm * 16 + gq_) * 2 + wn] = rs0;
            rs[(wm * 16 + gq_ + 8) * 2 + wn] = rs1;
        }

        float* Ost = (float*)(sm + AOFF_P);
#pragma unroll
        for (int t = 0; t < 2; t++) {
            int qc = vn * 16 + t * 8 + tg * 2;
            int d0 = vm * 16 + gq_;
            Ost[d0 * 65 + qc]     = acc_o[t][0];
            Ost[d0 * 65 + qc + 1] = acc_o[t][1];
            Ost[(d0 + 8) * 65 + qc]     = acc_o[t][2];
            Ost[(d0 + 8) * 65 + qc + 1] = acc_o[t][3];
        }
        __syncthreads();

        {
            int q = tid >> 2, ds = (tid & 3) * 8;
            int gq = q0 + q;
            if (gq < NTOK) {
                float inv = __frcp_rn(rs[q * 2] + rs[q * 2 + 1]);
                __nv_bfloat16 o[8];
#pragma unroll
                for (int u = 0; u < 8; u++)
                    o[u] = __float2bfloat16(Ost[(ds + u) * 65 + q] * inv);
                *(uint4*)(out + (size_t)(w * NTOK + gq) * CDIM + h * HD + ds) = *(uint4*)o;
            }
        }
        __syncthreads();
    }
}

// ---------------- pure LN2 ----------------
__global__ __launch_bounds__(256) void ln2_kernel(const float* __restrict__ xres,
                                                  const float* __restrict__ g,
                                                  const float* __restrict__ b,
                                                  __nv_bfloat16* __restrict__ ln2o) {
    int t = blockIdx.x * 8 + (threadIdx.x >> 5);
    int lane = threadIdx.x & 31;
    const float2* xp = (const float2*)(xres + (size_t)t * CDIM);
    const float2* gp = (const float2*)g;
    const float2* bp = (const float2*)b;
    float2 v[3];
    float s = 0.f, s2 = 0.f;
#pragma unroll
    for (int i = 0; i < 3; i++) {
        v[i] = xp[lane + i * 32];
        s += v[i].x + v[i].y;
        s2 += v[i].x * v[i].x + v[i].y * v[i].y;
    }
    s = warpSum(s); s2 = warpSum(s2);
    float mean = s * (1.0f / CDIM);
    float rstd = rsqrtf(s2 * (1.0f / CDIM) - mean * mean + 1e-5f);
    uint32_t* op = (uint32_t*)(ln2o + (size_t)t * CDIM);
#pragma unroll
    for (int i = 0; i < 3; i++) {
        int c = lane + i * 32;
        float2 gg = gp[c], bb = bp[c];
        float o0 = (v[i].x - mean) * rstd * gg.x + bb.x;
        float o1 = (v[i].y - mean) * rstd * gg.y + bb.y;
        uint32_t pk; CVTPK(pk, o0, o1);
        op[c] = pk;
    }
}

// ---------------- host-side stream/event singletons ----------------
static cudaStream_t make_stream() {
    cudaStream_t s;
    cudaStreamCreateWithFlags(&s, cudaStreamNonBlocking);
    return s;
}
static cudaEvent_t make_event() {
    cudaEvent_t e;
    cudaEventCreateWithFlags(&e, cudaEventDisableTiming);
    return e;
}

// ---------------- launch ----------------
extern "C" void kernel_launch(void* const* d_in, const int* in_sizes, int n_in,
                              void* d_out, int out_size) {
    (void)in_sizes; (void)n_in; (void)out_size;
    const float* x       = (const float*)d_in[0];
    const float* table   = (const float*)d_in[3];
    const float* n1g     = (const float*)d_in[4];
    const float* n1b     = (const float*)d_in[5];
    const float* qkv_w   = (const float*)d_in[6];
    const float* qkv_b   = (const float*)d_in[7];
    const float* proj_w  = (const float*)d_in[8];
    const float* proj_b  = (const float*)d_in[9];
    const float* n2g     = (const float*)d_in[10];
    const float* n2b     = (const float*)d_in[11];
    const float* fc1_w   = (const float*)d_in[12];
    const float* fc1_b   = (const float*)d_in[13];
    const float* fc2_w   = (const float*)d_in[14];
    const float* fc2_b   = (const float*)d_in[15];
    float* out = (float*)d_out;

    __nv_bfloat16 *xwb, *qkvb, *attnb, *ln2b, *h1b, *wqkv, *wproj, *wfc1, *wfc2, *comb;
    float *xres, *qbias;
    cudaGetSymbolAddress((void**)&xwb,   g_xwb);
    cudaGetSymbolAddress((void**)&qkvb,  g_qkvb);
    cudaGetSymbolAddress((void**)&attnb, g_attnb);
    cudaGetSymbolAddress((void**)&xres,  g_xres);
    cudaGetSymbolAddress((void**)&ln2b,  g_ln2b);
    cudaGetSymbolAddress((void**)&h1b,   g_h1b);
    cudaGetSymbolAddress((void**)&wqkv,  g_wqkv);
    cudaGetSymbolAddress((void**)&wproj, g_wproj);
    cudaGetSymbolAddress((void**)&wfc1,  g_wfc1);
    cudaGetSymbolAddress((void**)&wfc2,  g_wfc2);
    cudaGetSymbolAddress((void**)&comb,  g_comb);
    cudaGetSymbolAddress((void**)&qbias, g_qbias);

    cudaFuncSetAttribute(attn_tc_kernel, cudaFuncAttributeMaxDynamicSharedMemorySize,
                         ATTN_SMEM_BYTES);
    cudaFuncSetAttribute((gemm_mma_kernel<3, true>), cudaFuncAttributeMaxDynamicSharedMemorySize, GEMM_SMEM_BYTES);
    cudaFuncSetAttribute((gemm_mma_kernel<4, true>), cudaFuncAttributeMaxDynamicSharedMemorySize, GEMM_SMEM_BYTES);
    cudaFuncSetAttribute((gemm_mma_kernel<1, true>), cudaFuncAttributeMaxDynamicSharedMemorySize, GEMM_SMEM_BYTES);
    cudaFuncSetAttribute((gemm_mma_kernel<2, false>), cudaFuncAttributeMaxDynamicSharedMemorySize, GEMM_SMEM_BYTES);

    static cudaStream_t s1 = make_stream();
    static cudaStream_t s2 = make_stream();
    static cudaEvent_t ev_root = make_event();
    static cudaEvent_t ev_w    = make_event();
    static cudaEvent_t ev_c    = make_event();

    const int n0 = 3 * CDIM * CDIM, n1 = CDIM * CDIM, n2 = HID * CDIM, n3 = CDIM * HID;

    cudaEventRecord(ev_root, 0);
    cudaStreamWaitEvent(s1, ev_root, 0);
    cudaStreamWaitEvent(s2, ev_root, 0);

    cvt4_kernel<<<(n0 + n1 + n2 + n3 + 255) / 256, 256, 0, s1>>>(
        qkv_w, wqkv, n0, proj_w, wproj, n1, fc1_w, wfc1, n2, fc2_w, wfc2, n3);
    biasq_kernel<<<3, 192, 0, s1>>>(qkv_b, qbias);
    cudaEventRecord(ev_w, s1);

    comb_pre_kernel<<<(COMB_ELEMS + 255) / 256, 256, 0, s2>>>(table, comb);
    cudaEventRecord(ev_c, s2);

    ln1_kernel<<<TOK / 8, 256>>>(x, n1g, n1b, xwb);

    cudaStreamWaitEvent(0, ev_w, 0);
    gemm_mma_kernel<3, true><<<dim3(576 / BN, TOK / BM), 256, GEMM_SMEM_BYTES>>>(
        xwb, wqkv, qbias, nullptr, qkvb, CDIM, 3 * CDIM);

    cudaStreamWaitEvent(0, ev_c, 0);
    attn_tc_kernel<<<TOTWIN * HEADS, 256, ATTN_SMEM_BYTES>>>(qkvb, comb, attnb);

    gemm_mma_kernel<4, true><<<dim3(CDIM / BN, TOK / BM), 256, GEMM_SMEM_BYTES>>>(
        attnb, wproj, proj_b, x, xres, CDIM, CDIM);
    ln2_kernel<<<TOK / 8, 256>>>(xres, n2g, n2b, ln2b);
    gemm_mma_kernel<1, true><<<dim3(HID / BN, TOK / BM), 256, GEMM_SMEM_BYTES>>>(
        ln2b, wfc1, fc1_b, nullptr, h1b, CDIM, HID);
    gemm_mma_kernel<2, false><<<dim3(CDIM / BN, TOK / BM), 256, GEMM_SMEM_BYTES>>>(
        h1b, wfc2, fc2_b, xres, out, HID, CDIM);
}

// round 16
// speedup vs baseline: 1.2342x; 1.0834x over previous
#include <cuda_runtime.h>
#include <cuda_bf16.h>
#include <math.h>
#include <stdint.h>

// ---------------- problem constants ----------------
#define BATCH   2
#define DSZ     28
#define WS      7
#define SHIFT_  3
#define CDIM    192
#define HEADS   6
#define HD      32
#define NTOK    343
#define NWIN    64
#define TOTWIN  128
#define TOK     43904
#define HID     768
#define SCALE   0.17677669529663687f
#define LOG2E   1.4426950408889634f
#define QFOLD   (SCALE * LOG2E)

// GEMM tiling (CTA 128x64, warp 32x32)
#define BM      128
#define BN      64
#define KB      64
#define GEMM_SMEM_BYTES 73728

// attention tiling
#define QT      64
#define NC      64
#define KPAD    384
#define NCH     6
#define KPITCH  80            // bytes per row; multiple of 16 (ldmatrix/uint4 alignment)
#define CPITCH  384
// smem offsets (bytes); O aliases Q (Q is register-hoisted before O writes)
#define AOFF_K   0
#define AOFF_V   30720
#define AOFF_Q   61440
#define AOFF_O   61440
#define AOFF_RS  70144
#define ATTN_SMEM_BYTES 70656
#define OPITCH   34

#define COMB_ELEMS (48 * CPITCH * CPITCH)

// ---------------- scratch (device globals) ----------------
__device__ __nv_bfloat16 g_xwb [TOK * CDIM];
__device__ __nv_bfloat16 g_qkvb[TOK * 3 * CDIM];
__device__ __nv_bfloat16 g_attnb[TOK * CDIM];
__device__ float         g_xres[TOK * CDIM];
__device__ __nv_bfloat16 g_ln2b[TOK * CDIM];
__device__ __nv_bfloat16 g_h1b [TOK * HID];
__device__ __nv_bfloat16 g_wqkv[3 * CDIM * CDIM];
__device__ __nv_bfloat16 g_wproj[CDIM * CDIM];
__device__ __nv_bfloat16 g_wfc1[HID * CDIM];
__device__ __nv_bfloat16 g_wfc2[CDIM * HID];
__device__ __nv_bfloat16 g_comb[COMB_ELEMS];
__device__ float         g_qbias[3 * CDIM];

// ---------------- helpers ----------------
__device__ __forceinline__ uint32_t s2u(const void* p) {
    uint32_t r;
    asm("{ .reg .u64 t; cvta.to.shared.u64 t, %1; cvt.u32.u64 %0, t; }" : "=r"(r) : "l"(p));
    return r;
}
__device__ __forceinline__ float warpSum(float v) {
#pragma unroll
    for (int o = 16; o; o >>= 1) v += __shfl_xor_sync(0xffffffffu, v, o);
    return v;
}
__device__ __forceinline__ int token_to_winrow(int t) {
    int b   = t / (DSZ * DSZ * DSZ);
    int rem = t - b * (DSZ * DSZ * DSZ);
    int dd  = rem / (DSZ * DSZ);
    int hh  = (rem / DSZ) % DSZ;
    int ww  = rem % DSZ;
    int i = (dd + DSZ - SHIFT_) % DSZ;
    int j = (hh + DSZ - SHIFT_) % DSZ;
    int k = (ww + DSZ - SHIFT_) % DSZ;
    int win = (i / WS) * 16 + (j / WS) * 4 + (k / WS);
    int n   = (i % WS) * 49 + (j % WS) * 7 + (k % WS);
    return (b * NWIN + win) * NTOK + n;
}
__device__ __forceinline__ int winrow_to_token(int r) {
    int win = r / NTOK;
    int n   = r - win * NTOK;
    int b   = win >> 6;
    int w64 = win & 63;
    int ni = n / 49, rem = n - ni * 49;
    int nj = rem / 7, nk = rem - nj * 7;
    int i = (w64 >> 4) * 7 + ni;
    int j = ((w64 >> 2) & 3) * 7 + nj;
    int k = (w64 & 3) * 7 + nk;
    int dd = i + SHIFT_; if (dd >= DSZ) dd -= DSZ;
    int hh = j + SHIFT_; if (hh >= DSZ) hh -= DSZ;
    int ww = k + SHIFT_; if (ww >= DSZ) ww -= DSZ;
    return b * (DSZ * DSZ * DSZ) + dd * (DSZ * DSZ) + hh * DSZ + ww;
}

// packed f32x2 -> bf16x2 (one CVT): dst u32 = {hi:hi_val, lo:lo_val}
#define CVTPK(dst, lo_val, hi_val) \
    asm("cvt.rn.satfinite.bf16x2.f32 %0, %1, %2;" : "=r"(dst) : "f"(hi_val), "f"(lo_val))

// fast GELU (tanh form, exp2-based)
__device__ __forceinline__ float gelu_fast(float xv) {
    float u  = xv * (0.7978845608028654f + 0.035677408136300125f * xv * xv);
    float au = fabsf(u);
    float t  = __frcp_rn(1.0f + exp2f(au * 2.8853900817779268f));
    float th = copysignf(1.0f - 2.0f * t, u);
    return 0.5f * xv * (1.0f + th);
}

#define CP_ASYNC16(dst_u32, src_ptr) \
    asm volatile("cp.async.cg.shared.global [%0], [%1], 16;" :: "r"(dst_u32), "l"(src_ptr))
#define CP_COMMIT() asm volatile("cp.async.commit_group;")
#define CP_WAIT(n)  asm volatile("cp.async.wait_group %0;" :: "n"(n))

#define LDMX4(r0, r1, r2, r3, addr) \
    asm volatile("ldmatrix.sync.aligned.m8n8.x4.shared.b16 {%0,%1,%2,%3}, [%4];" \
                 : "=r"(r0), "=r"(r1), "=r"(r2), "=r"(r3) : "r"(addr))
#define LDMX4T(r0, r1, r2, r3, addr) \
    asm volatile("ldmatrix.sync.aligned.m8n8.x4.trans.shared.b16 {%0,%1,%2,%3}, [%4];" \
                 : "=r"(r0), "=r"(r1), "=r"(r2), "=r"(r3) : "r"(addr))

#define MMA16816(d, a0, a1, a2, a3, b0, b1) \
    asm volatile("mma.sync.aligned.m16n8k16.row.col.f32.bf16.bf16.f32 " \
                 "{%0,%1,%2,%3}, {%4,%5,%6,%7}, {%8,%9}, {%0,%1,%2,%3};" \
                 : "+f"((d)[0]), "+f"((d)[1]), "+f"((d)[2]), "+f"((d)[3]) \
                 : "r"(a0), "r"(a1), "r"(a2), "r"(a3), "r"(b0), "r"(b1))

// ---------------- merged weight conversion (q-rows folded) ----------------
__global__ void cvt4_kernel(const float* __restrict__ s0, __nv_bfloat16* __restrict__ d0, int n0,
                            const float* __restrict__ s1, __nv_bfloat16* __restrict__ d1, int n1,
                            const float* __restrict__ s2, __nv_bfloat16* __restrict__ d2, int n2,
                            const float* __restrict__ s3, __nv_bfloat16* __restrict__ d3, int n3) {
    int i = blockIdx.x * 256 + threadIdx.x;
    if (i < n0) {
        float v = s0[i];
        if (i < CDIM * CDIM) v *= QFOLD;
        d0[i] = __float2bfloat16(v);
        return;
    }
    i -= n0;
    if (i < n1) { d1[i] = __float2bfloat16(s1[i]); return; }
    i -= n1;
    if (i < n2) { d2[i] = __float2bfloat16(s2[i]); return; }
    i -= n2;
    if (i < n3) { d3[i] = __float2bfloat16(s3[i]); }
}

__global__ void biasq_kernel(const float* __restrict__ qkv_b, float* __restrict__ qb) {
    int i = blockIdx.x * 192 + threadIdx.x;
    if (i < 3 * CDIM) qb[i] = (i < CDIM) ? qkv_b[i] * QFOLD : qkv_b[i];
}

// ---------------- combined bias+mask precompute ----------------
__global__ void comb_pre_kernel(const float* __restrict__ table,
                                __nv_bfloat16* __restrict__ comb) {
    int idx = blockIdx.x * 256 + threadIdx.x;
    if (idx >= COMB_ELEMS) return;
    int col  = idx % CPITCH;
    int row  = (idx / CPITCH) % CPITCH;
    int hc   = idx / (CPITCH * CPITCH);
    int h = hc >> 3, cls = hc & 7;
    float val = -160.f;
    if (col < NTOK && row < NTOK) {
        int i3 = row / 49, j3 = (row / 7) % 7, k3 = row % 7;
        int ci = col / 49, cj = (col / 7) % 7, ck = col % 7;
        int rel = (i3 - ci + 6) * 169 + (j3 - cj + 6) * 13 + (k3 - ck + 6);
        float v = table[rel * HEADS + h];
        bool diff = ((cls & 4) && ((i3 < 4) != (ci < 4))) ||
                    ((cls & 2) && ((j3 < 4) != (cj < 4))) ||
                    ((cls & 1) && ((k3 < 4) != (ck < 4)));
        if (diff) v -= 100.f;
        val = v * LOG2E;
    }
    comb[idx] = __float2bfloat16(val);
}

// ---------------- LN1 + shift + partition ----------------
__global__ __launch_bounds__(256) void ln1_kernel(const float* __restrict__ x,
                                                  const float* __restrict__ g,
                                                  const float* __restrict__ b,
                                                  __nv_bfloat16* __restrict__ xw) {
    int t = blockIdx.x * 8 + (threadIdx.x >> 5);
    int lane = threadIdx.x & 31;
    const float2* xp = (const float2*)(x + (size_t)t * CDIM);
    const float2* gp = (const float2*)g;
    const float2* bp = (const float2*)b;
    float2 v[3];
    float s = 0.f, s2 = 0.f;
#pragma unroll
    for (int i = 0; i < 3; i++) {
        v[i] = xp[lane + i * 32];
        s += v[i].x + v[i].y;
        s2 += v[i].x * v[i].x + v[i].y * v[i].y;
    }
    s = warpSum(s); s2 = warpSum(s2);
    float mean = s * (1.0f / CDIM);
    float rstd = rsqrtf(s2 * (1.0f / CDIM) - mean * mean + 1e-5f);
    int row = token_to_winrow(t);
    uint32_t* op = (uint32_t*)(xw + (size_t)row * CDIM);
#pragma unroll
    for (int i = 0; i < 3; i++) {
        int c = lane + i * 32;
        float2 gg = gp[c], bb = bp[c];
        float o0 = (v[i].x - mean) * rstd * gg.x + bb.x;
        float o1 = (v[i].y - mean) * rstd * gg.y + bb.y;
        uint32_t pk; CVTPK(pk, o0, o1);
        op[c] = pk;
    }
}

// ---------------- GEMM tile loader ----------------
__device__ __forceinline__ void gemm_issue(const __nv_bfloat16* __restrict__ A,
                                           const __nv_bfloat16* __restrict__ Wt,
                                           int bm, int bn, int Ktot, int lr, int lc8,
                                           char* bA, char* bB, int k0) {
#pragma unroll
    for (int rr = 0; rr < 4; rr++) {
        int r = lr + rr * 32;
        uint32_t off = (uint32_t)(r * 128 + lc8 * 2);
        off ^= (off >> 3) & 0x70;
        CP_ASYNC16(s2u(bA + off), A + (size_t)(bm + r) * Ktot + k0 + lc8);
    }
#pragma unroll
    for (int rr = 0; rr < 2; rr++) {
        int br = lr + rr * 32;
        uint32_t off = (uint32_t)(br * 128 + lc8 * 2);
        off ^= (off >> 3) & 0x70;
        CP_ASYNC16(s2u(bB + off), Wt + (size_t)(bn + br) * Ktot + k0 + lc8);
    }
    CP_COMMIT();
}

// ---------------- HMMA bf16 GEMM ----------------
// EPI: 0 = bias -> fp32; 1 = bias+gelu -> bf16; 2 = bias+resid -> fp32;
//      3 = bias -> bf16;  4 = bias + x[token] -> xres[token] (row-permuted)
template <int EPI, bool FULLK>
__global__ __launch_bounds__(256)
void gemm_mma_kernel(const __nv_bfloat16* __restrict__ A,
                     const __nv_bfloat16* __restrict__ Wt,
                     const float* __restrict__ bias,
                     const float* __restrict__ resid,
                     void* __restrict__ Cv, int Ktot, int Ntot)
{
    extern __shared__ __align__(1024) char dsm[];
    char* bufA[3] = {dsm, dsm + 16384, dsm + 32768};
    char* bufB[3] = {dsm + 49152, dsm + 57344, dsm + 65536};

    const int tid = threadIdx.x;
    const int lane = tid & 31;
    const int wid = tid >> 5;
    const int wm = (wid & 3) * 32;
    const int wn = (wid >> 2) * 32;
    const int bm = blockIdx.y * BM;
    const int bn = blockIdx.x * BN;

    float acc[2][4][4];
#pragma unroll
    for (int a = 0; a < 2; a++)
#pragma unroll
        for (int b = 0; b < 4; b++)
#pragma unroll
            for (int c = 0; c < 4; c++) acc[a][b][c] = 0.f;

    const int lr = tid >> 3;
    const int lc8 = (tid & 7) * 8;

    if (FULLK) {
#pragma unroll
        for (int ch = 0; ch < 3; ch++)
            gemm_issue(A, Wt, bm, bn, Ktot, lr, lc8, bufA[ch], bufB[ch], ch * KB);
#pragma unroll
        for (int chunk = 0; chunk < 3; chunk++) {
            if (chunk == 0)      CP_WAIT(2);
            else if (chunk == 1) CP_WAIT(1);
            else                 CP_WAIT(0);
            __syncthreads();
            const uint32_t sA = s2u(bufA[chunk]);
            const uint32_t sB = s2u(bufB[chunk]);
#pragma unroll
            for (int kk = 0; kk < 4; kk++) {
                uint32_t a0[2], a1[2], a2[2], a3[2];
#pragma unroll
                for (int mi = 0; mi < 2; mi++) {
                    uint32_t off = (uint32_t)((wm + mi * 16 + (lane & 15)) * 128 + kk * 32 + (lane >> 4) * 16);
                    off ^= (off >> 3) & 0x70;
                    LDMX4(a0[mi], a1[mi], a2[mi], a3[mi], sA + off);
                }
#pragma unroll
                for (int nj = 0; nj < 2; nj++) {
                    uint32_t off = (uint32_t)((wn + nj * 16 + (lane & 15)) * 128 + kk * 32 + (lane >> 4) * 16);
                    off ^= (off >> 3) & 0x70;
                    uint32_t r0, r1, r2, r3;
                    LDMX4(r0, r1, r2, r3, sB + off);
#pragma unroll
                    for (int mi = 0; mi < 2; mi++) {
                        MMA16816(acc[mi][2 * nj], a0[mi], a1[mi], a2[mi], a3[mi], r0, r2);
                        MMA16816(acc[mi][2 * nj + 1], a0[mi], a1[mi], a2[mi], a3[mi], r1, r3);
                    }
                }
            }
        }
    } else {
        const int nch = Ktot / KB;
        gemm_issue(A, Wt, bm, bn, Ktot, lr, lc8, bufA[0], bufB[0], 0);
        gemm_issue(A, Wt, bm, bn, Ktot, lr, lc8, bufA[1], bufB[1], KB);
        for (int ch = 0; ch < nch; ch++) {
            if (ch + 2 < nch)
                gemm_issue(A, Wt, bm, bn, Ktot, lr, lc8,
                           bufA[(ch + 2) % 3], bufB[(ch + 2) % 3], (ch + 2) * KB);
            const int rem = nch - ch - 1;
            if (rem >= 2)      CP_WAIT(2);
            else if (rem == 1) CP_WAIT(1);
            else               CP_WAIT(0);
            __syncthreads();

            const uint32_t sA = s2u(bufA[ch % 3]);
            const uint32_t sB = s2u(bufB[ch % 3]);
#pragma unroll
            for (int kk = 0; kk < KB / 16; kk++) {
                uint32_t a0[2], a1[2], a2[2], a3[2];
#pragma unroll
                for (int mi = 0; mi < 2; mi++) {
                    uint32_t off = (uint32_t)((wm + mi * 16 + (lane & 15)) * 128 + kk * 32 + (lane >> 4) * 16);
                    off ^= (off >> 3) & 0x70;
                    LDMX4(a0[mi], a1[mi], a2[mi], a3[mi], sA + off);
                }
#pragma unroll
                for (int nj = 0; nj < 2; nj++) {
                    uint32_t off = (uint32_t)((wn + nj * 16 + (lane & 15)) * 128 + kk * 32 + (lane >> 4) * 16);
                    off ^= (off >> 3) & 0x70;
                    uint32_t r0, r1, r2, r3;
                    LDMX4(r0, r1, r2, r3, sB + off);
#pragma unroll
                    for (int mi = 0; mi < 2; mi++) {
                        MMA16816(acc[mi][2 * nj], a0[mi], a1[mi], a2[mi], a3[mi], r0, r2);
                        MMA16816(acc[mi][2 * nj + 1], a0[mi], a1[mi], a2[mi], a3[mi], r1, r3);
                    }
                }
            }
            __syncthreads();
        }
    }

    const int gq = lane >> 2;
    const int tg = lane & 3;
#pragma unroll
    for (int mi = 0; mi < 2; mi++) {
#pragma unroll
        for (int half = 0; half < 2; half++) {
            int row = bm + wm + mi * 16 + gq + half * 8;
            int orow = row;
            if (EPI == 4) orow = winrow_to_token(row);
#pragma unroll
            for (int ni = 0; ni < 4; ni++) {
                int col = bn + wn + ni * 8 + tg * 2;
                float bia0 = bias[col], bia1 = bias[col + 1];
                float v0 = acc[mi][ni][half * 2 + 0] + bia0;
                float v1 = acc[mi][ni][half * 2 + 1] + bia1;
                size_t oi = (size_t)orow * Ntot + col;
                if (EPI == 1) {
                    v0 = gelu_fast(v0);
                    v1 = gelu_fast(v1);
                    uint32_t pk; CVTPK(pk, v0, v1);
                    *(uint32_t*)((__nv_bfloat16*)Cv + oi) = pk;
                } else if (EPI == 2 || EPI == 4) {
                    float2 rv = *(const float2*)(resid + oi);
                    float2 o; o.x = v0 + rv.x; o.y = v1 + rv.y;
                    *(float2*)((float*)Cv + oi) = o;
                } else if (EPI == 3) {
                    uint32_t pk; CVTPK(pk, v0, v1);
                    *(uint32_t*)((__nv_bfloat16*)Cv + oi) = pk;
                } else {
                    float2 o; o.x = v0; o.y = v1;
                    *(float2*)((float*)Cv + oi) = o;
                }
            }
        }
    }
}

// ---------------- FA2-style attention: register-resident P, no inner barriers ----------------
// grid (TOTWIN*HEADS); block 256, 3 CTAs/SM. K and V both [j][d], pitch 80.
__global__ __launch_bounds__(256, 3) void attn_tc_kernel(
    const __nv_bfloat16* __restrict__ qkv, const __nv_bfloat16* __restrict__ comb,
    __nv_bfloat16* __restrict__ out)
{
    extern __shared__ __align__(1024) char sm[];
    const uint32_t uK = s2u(sm + AOFF_K);
    const uint32_t uV = s2u(sm + AOFF_V);
    const uint32_t uQ = s2u(sm + AOFF_Q);
    float* Ost = (float*)(sm + AOFF_O);     // aliases Q region (Q hoisted first)
    float* rs  = (float*)(sm + AOFF_RS);

    const int bx = blockIdx.x;
    const int w  = bx / HEADS;
    const int h  = bx - w * HEADS;
    const int mw = w % NWIN;
    const int wd = mw >> 4, wh = (mw >> 2) & 3, ww = mw & 3;
    const int cls = ((wd == 3) << 2) | ((wh == 3) << 1) | (ww == 3);
    const int tid = threadIdx.x;
    const int lane = tid & 31;
    const int wid = tid >> 5;

    const __nv_bfloat16* base = qkv + (size_t)w * NTOK * (3 * CDIM);

    // K and V: both [j][d] rows, zero-padded (once per block)
    for (int idx = tid; idx < KPAD * 4; idx += 256) {
        int j = idx >> 2, s = idx & 3;
        uint4 vk = make_uint4(0, 0, 0, 0);
        uint4 vv = make_uint4(0, 0, 0, 0);
        if (j < NTOK) {
            const __nv_bfloat16* rp = base + (size_t)j * (3 * CDIM) + h * HD + s * 8;
            vk = *(const uint4*)(rp + CDIM);
            vv = *(const uint4*)(rp + 2 * CDIM);
        }
        *(uint4*)(sm + AOFF_K + j * KPITCH + s * 16) = vk;
        *(uint4*)(sm + AOFF_V + j * KPITCH + s * 16) = vv;
    }

    const int wm = wid & 3, wn = wid >> 2;
    const int gq_ = lane >> 2, tg = lane & 3;
    const __nv_bfloat16* cb = comb + (size_t)(h * 8 + cls) * CPITCH * CPITCH;

    // trans-ldmatrix lane offset for V
    const uint32_t vlane = (uint32_t)(((lane & 7) + ((lane >> 3) & 1) * 8) * KPITCH + (lane >> 4) * 16);

    for (int qt = 0; qt < NCH; qt++) {
        const int q0 = qt * QT;
        for (int idx = tid; idx < QT * 4; idx += 256) {
            int r = idx >> 2, s = idx & 3;
            int gq = q0 + r;
            uint4 v = make_uint4(0, 0, 0, 0);
            if (gq < NTOK) v = *(const uint4*)(base + (size_t)gq * (3 * CDIM) + h * HD + s * 8);
            *(uint4*)(sm + AOFF_Q + r * KPITCH + s * 16) = v;
        }
        __syncthreads();

        // hoist Q fragments for this q-tile
        uint32_t qf[2][4];
#pragma unroll
        for (int ks = 0; ks < 2; ks++)
            LDMX4(qf[ks][0], qf[ks][1], qf[ks][2], qf[ks][3],
                  uQ + (uint32_t)((wm * 16 + (lane & 15)) * KPITCH + ks * 32 + (lane >> 4) * 16));
        __syncthreads();   // Q smem now free; Ost may alias it

        float acc_o[4][4];
#pragma unroll
        for (int t = 0; t < 4; t++)
#pragma unroll
            for (int c = 0; c < 4; c++) acc_o[t][c] = 0.f;
        float rs0 = 0.f, rs1 = 0.f;

        const int r0g = q0 + wm * 16 + gq_;
        const __nv_bfloat16* c0p = cb + (size_t)r0g * CPITCH;
        const __nv_bfloat16* c1p = c0p + 8 * CPITCH;

        for (int ch = 0; ch < NCH; ch++) {
            const int j0 = ch * NC;
            float acc[4][4];
#pragma unroll
            for (int t = 0; t < 4; t++)
#pragma unroll
                for (int c = 0; c < 4; c++) acc[t][c] = 0.f;

            // S = Q @ K^T for this warp's j32
#pragma unroll
            for (int ks = 0; ks < 2; ks++) {
#pragma unroll
                for (int nj = 0; nj < 2; nj++) {
                    uint32_t r0, r1, r2, r3;
                    LDMX4(r0, r1, r2, r3,
                          uK + (uint32_t)((j0 + wn * 32 + nj * 16 + (lane & 15)) * KPITCH + ks * 32 + (lane >> 4) * 16));
                    MMA16816(acc[2 * nj], qf[ks][0], qf[ks][1], qf[ks][2], qf[ks][3], r0, r2);
                    MMA16816(acc[2 * nj + 1], qf[ks][0], qf[ks][1], qf[ks][2], qf[ks][3], r1, r3);
                }
            }

            // epilogue: exp2(acc + comb) -> register P fragments + rowsums
            uint32_t pf[2][4];
#pragma unroll
            for (int ti = 0; ti < 4; ti++) {
                int jl = wn * 32 + (ti >> 1) * 16 + (ti & 1) * 8 + tg * 2;
                int ja = j0 + jl;
                __nv_bfloat162 b0 = *(const __nv_bfloat162*)(c0p + ja);
                __nv_bfloat162 b1 = *(const __nv_bfloat162*)(c1p + ja);
                float e00 = exp2f(acc[ti][0] + __bfloat162float(b0.x));
                float e01 = exp2f(acc[ti][1] + __bfloat162float(b0.y));
                float e10 = exp2f(acc[ti][2] + __bfloat162float(b1.x));
                float e11 = exp2f(acc[ti][3] + __bfloat162float(b1.y));
                rs0 += e00 + e01;
                rs1 += e10 + e11;
                CVTPK(pf[ti >> 1][(ti & 1) * 2 + 0], e00, e01);
                CVTPK(pf[ti >> 1][(ti & 1) * 2 + 1], e10, e11);
            }

            // O += P @ V : V via trans-ldmatrix from [j][d]
#pragma unroll
            for (int kc = 0; kc < 2; kc++) {
                uint32_t vbase = uV + (uint32_t)((j0 + wn * 32 + kc * 16) * KPITCH) + vlane;
#pragma unroll
                for (int dh = 0; dh < 2; dh++) {
                    uint32_t r0, r1, r2, r3;
                    LDMX4T(r0, r1, r2, r3, vbase + dh * 32);
                    MMA16816(acc_o[dh * 2 + 0], pf[kc][0], pf[kc][1], pf[kc][2], pf[kc][3], r0, r1);
                    MMA16816(acc_o[dh * 2 + 1], pf[kc][0], pf[kc][1], pf[kc][2], pf[kc][3], r2, r3);
                }
            }
        }

        // rowsums (quad reduce, per wn slot)
        rs0 += __shfl_xor_sync(0xffffffffu, rs0, 1);
        rs0 += __shfl_xor_sync(0xffffffffu, rs0, 2);
        rs1 += __shfl_xor_sync(0xffffffffu, rs1, 1);
        rs1 += __shfl_xor_sync(0xffffffffu, rs1, 2);
        if (tg == 0) {
            rs[(wm * 16 + gq_) * 2 + wn] = rs0;
            rs[(wm * 16 + gq_ + 8) * 2 + wn] = rs1;
        }

        // O partial reduction across the two j-warps
        if (wn == 0) {
#pragma unroll
            for (int dn = 0; dn < 4; dn++)
#pragma unroll
                for (int half = 0; half < 2; half++) {
                    int q = wm * 16 + gq_ + half * 8;
                    float2 val; val.x = acc_o[dn][half * 2]; val.y = acc_o[dn][half * 2 + 1];
                    *(float2*)&Ost[q * OPITCH + dn * 8 + tg * 2] = val;
                }
        }
        __syncthreads();
        if (wn == 1) {
#pragma unroll
            for (int dn = 0; dn < 4; dn++)
#pragma unroll
                for (int half = 0; half < 2; half++) {
                    int q = wm * 16 + gq_ + half * 8;
                    float2* p = (float2*)&Ost[q * OPITCH + dn * 8 + tg * 2];
                    float2 cur = *p;
                    cur.x += acc_o[dn][half * 2];
                    cur.y += acc_o[dn][half * 2 + 1];
                    *p = cur;
                }
        }
        __syncthreads();

        // writeout
        {
            int q = tid >> 2, ds = (tid & 3) * 8;
            int gq = q0 + q;
            if (gq < NTOK) {
                float inv = __frcp_rn(rs[q * 2] + rs[q * 2 + 1]);
                const float* op = &Ost[q * OPITCH + ds];
                uint32_t pk[4];
#pragma unroll
                for (int u = 0; u < 4; u++) {
                    float2 vv = *(const float2*)(op + 2 * u);
                    CVTPK(pk[u], vv.x * inv, vv.y * inv);
                }
                *(uint4*)(out + (size_t)(w * NTOK + gq) * CDIM + h * HD + ds) = *(uint4*)pk;
            }
        }
        __syncthreads();   // Ost/rs consumed before next tile's Q staging (aliased)
    }
}

// ---------------- pure LN2 ----------------
__global__ __launch_bounds__(256) void ln2_kernel(const float* __restrict__ xres,
                                                  const float* __restrict__ g,
                                                  const float* __restrict__ b,
                                                  __nv_bfloat16* __restrict__ ln2o) {
    int t = blockIdx.x * 8 + (threadIdx.x >> 5);
    int lane = threadIdx.x & 31;
    const float2* xp = (const float2*)(xres + (size_t)t * CDIM);
    const float2* gp = (const float2*)g;
    const float2* bp = (const float2*)b;
    float2 v[3];
    float s = 0.f, s2 = 0.f;
#pragma unroll
    for (int i = 0; i < 3; i++) {
        v[i] = xp[lane + i * 32];
        s += v[i].x + v[i].y;
        s2 += v[i].x * v[i].x + v[i].y * v[i].y;
    }
    s = warpSum(s); s2 = warpSum(s2);
    float mean = s * (1.0f / CDIM);
    float rstd = rsqrtf(s2 * (1.0f / CDIM) - mean * mean + 1e-5f);
    uint32_t* op = (uint32_t*)(ln2o + (size_t)t * CDIM);
#pragma unroll
    for (int i = 0; i < 3; i++) {
        int c = lane + i * 32;
        float2 gg = gp[c], bb = bp[c];
        float o0 = (v[i].x - mean) * rstd * gg.x + bb.x;
        float o1 = (v[i].y - mean) * rstd * gg.y + bb.y;
        uint32_t pk; CVTPK(pk, o0, o1);
        op[c] = pk;
    }
}

// ---------------- host-side stream/event singletons ----------------
static cudaStream_t make_stream() {
    cudaStream_t s;
    cudaStreamCreateWithFlags(&s, cudaStreamNonBlocking);
    return s;
}
static cudaEvent_t make_event() {
    cudaEvent_t e;
    cudaEventCreateWithFlags(&e, cudaEventDisableTiming);
    return e;
}

// ---------------- launch ----------------
extern "C" void kernel_launch(void* const* d_in, const int* in_sizes, int n_in,
                              void* d_out, int out_size) {
    (void)in_sizes; (void)n_in; (void)out_size;
    const float* x       = (const float*)d_in[0];
    const float* table   = (const float*)d_in[3];
    const float* n1g     = (const float*)d_in[4];
    const float* n1b     = (const float*)d_in[5];
    const float* qkv_w   = (const float*)d_in[6];
    const float* qkv_b   = (const float*)d_in[7];
    const float* proj_w  = (const float*)d_in[8];
    const float* proj_b  = (const float*)d_in[9];
    const float* n2g     = (const float*)d_in[10];
    const float* n2b     = (const float*)d_in[11];
    const float* fc1_w   = (const float*)d_in[12];
    const float* fc1_b   = (const float*)d_in[13];
    const float* fc2_w   = (const float*)d_in[14];
    const float* fc2_b   = (const float*)d_in[15];
    float* out = (float*)d_out;

    __nv_bfloat16 *xwb, *qkvb, *attnb, *ln2b, *h1b, *wqkv, *wproj, *wfc1, *wfc2, *comb;
    float *xres, *qbias;
    cudaGetSymbolAddress((void**)&xwb,   g_xwb);
    cudaGetSymbolAddress((void**)&qkvb,  g_qkvb);
    cudaGetSymbolAddress((void**)&attnb, g_attnb);
    cudaGetSymbolAddress((void**)&xres,  g_xres);
    cudaGetSymbolAddress((void**)&ln2b,  g_ln2b);
    cudaGetSymbolAddress((void**)&h1b,   g_h1b);
    cudaGetSymbolAddress((void**)&wqkv,  g_wqkv);
    cudaGetSymbolAddress((void**)&wproj, g_wproj);
    cudaGetSymbolAddress((void**)&wfc1,  g_wfc1);
    cudaGetSymbolAddress((void**)&wfc2,  g_wfc2);
    cudaGetSymbolAddress((void**)&comb,  g_comb);
    cudaGetSymbolAddress((void**)&qbias, g_qbias);

    cudaFuncSetAttribute(attn_tc_kernel, cudaFuncAttributeMaxDynamicSharedMemorySize,
                         ATTN_SMEM_BYTES);
    cudaFuncSetAttribute((gemm_mma_kernel<3, true>), cudaFuncAttributeMaxDynamicSharedMemorySize, GEMM_SMEM_BYTES);
    cudaFuncSetAttribute((gemm_mma_kernel<4, true>), cudaFuncAttributeMaxDynamicSharedMemorySize, GEMM_SMEM_BYTES);
    cudaFuncSetAttribute((gemm_mma_kernel<1, true>), cudaFuncAttributeMaxDynamicSharedMemorySize, GEMM_SMEM_BYTES);
    cudaFuncSetAttribute((gemm_mma_kernel<2, false>), cudaFuncAttributeMaxDynamicSharedMemorySize, GEMM_SMEM_BYTES);

    static cudaStream_t s1 = make_stream();
    static cudaStream_t s2 = make_stream();
    static cudaEvent_t ev_root = make_event();
    static cudaEvent_t ev_w    = make_event();
    static cudaEvent_t ev_c    = make_event();

    const int n0 = 3 * CDIM * CDIM, n1 = CDIM * CDIM, n2 = HID * CDIM, n3 = CDIM * HID;

    cudaEventRecord(ev_root, 0);
    cudaStreamWaitEvent(s1, ev_root, 0);
    cudaStreamWaitEvent(s2, ev_root, 0);

    cvt4_kernel<<<(n0 + n1 + n2 + n3 + 255) / 256, 256, 0, s1>>>(
        qkv_w, wqkv, n0, proj_w, wproj, n1, fc1_w, wfc1, n2, fc2_w, wfc2, n3);
    biasq_kernel<<<3, 192, 0, s1>>>(qkv_b, qbias);
    cudaEventRecord(ev_w, s1);

    comb_pre_kernel<<<(COMB_ELEMS + 255) / 256, 256, 0, s2>>>(table, comb);
    cudaEventRecord(ev_c, s2);

    ln1_kernel<<<TOK / 8, 256>>>(x, n1g, n1b, xwb);

    cudaStreamWaitEvent(0, ev_w, 0);
    gemm_mma_kernel<3, true><<<dim3(576 / BN, TOK / BM), 256, GEMM_SMEM_BYTES>>>(
        xwb, wqkv, qbias, nullptr, qkvb, CDIM, 3 * CDIM);

    cudaStreamWaitEvent(0, ev_c, 0);
    attn_tc_kernel<<<TOTWIN * HEADS, 256, ATTN_SMEM_BYTES>>>(qkvb, comb, attnb);

    gemm_mma_kernel<4, true><<<dim3(CDIM / BN, TOK / BM), 256, GEMM_SMEM_BYTES>>>(
        attnb, wproj, proj_b, x, xres, CDIM, CDIM);
    ln2_kernel<<<TOK / 8, 256>>>(xres, n2g, n2b, ln2b);
    gemm_mma_kernel<1, true><<<dim3(HID / BN, TOK / BM), 256, GEMM_SMEM_BYTES>>>(
        ln2b, wfc1, fc1_b, nullptr, h1b, CDIM, HID);
    gemm_mma_kernel<2, false><<<dim3(CDIM / BN, TOK / BM), 256, GEMM_SMEM_BYTES>>>(
        h1b, wfc2, fc2_b, xres, out, HID, CDIM);
}

// round 17
// speedup vs baseline: 1.2694x; 1.0286x over previous
#include <cuda_runtime.h>
#include <cuda_bf16.h>
#include <math.h>
#include <stdint.h>

// ---------------- problem constants ----------------
#define BATCH   2
#define DSZ     28
#define WS      7
#define SHIFT_  3
#define CDIM    192
#define HEADS   6
#define HD      32
#define NTOK    343
#define NWIN    64
#define TOTWIN  128
#define TOK     43904
#define HID     768
#define SCALE   0.17677669529663687f
#define LOG2E   1.4426950408889634f
#define QFOLD   (SCALE * LOG2E)

// GEMM tiling (CTA 128x64, warp 32x32)
#define BM      128
#define BN      64
#define KB      64
#define GEMM_SMEM_BYTES 73728

// attention tiling
#define QT      64
#define NC      64
#define KPAD    384
#define NCH     6
#define KPITCH  80
#define CPITCH  384
// smem offsets (bytes); O aliases Q (Q is register-hoisted before O writes)
#define AOFF_K   0
#define AOFF_V   30720
#define AOFF_Q   61440
#define AOFF_O   61440
#define AOFF_RS  70144
#define ATTN_SMEM_BYTES 70656
#define OPITCH   34

#define COMB_ELEMS (48 * CPITCH * CPITCH)

// ---------------- scratch (device globals) ----------------
__device__ __nv_bfloat16 g_xwb [TOK * CDIM];
__device__ __nv_bfloat16 g_qkvb[TOK * 3 * CDIM];
__device__ __nv_bfloat16 g_attnb[TOK * CDIM];
__device__ float         g_xres[TOK * CDIM];
__device__ __nv_bfloat16 g_ln2b[TOK * CDIM];
__device__ __nv_bfloat16 g_h1b [TOK * HID];
__device__ __nv_bfloat16 g_wqkv[3 * CDIM * CDIM];
__device__ __nv_bfloat16 g_wproj[CDIM * CDIM];
__device__ __nv_bfloat16 g_wfc1[HID * CDIM];
__device__ __nv_bfloat16 g_wfc2[CDIM * HID];
__device__ __nv_bfloat16 g_comb[COMB_ELEMS];
__device__ float         g_qbias[3 * CDIM];

// ---------------- helpers ----------------
__device__ __forceinline__ uint32_t s2u(const void* p) {
    uint32_t r;
    asm("{ .reg .u64 t; cvta.to.shared.u64 t, %1; cvt.u32.u64 %0, t; }" : "=r"(r) : "l"(p));
    return r;
}
__device__ __forceinline__ int token_to_winrow(int t) {
    int b   = t / (DSZ * DSZ * DSZ);
    int rem = t - b * (DSZ * DSZ * DSZ);
    int dd  = rem / (DSZ * DSZ);
    int hh  = (rem / DSZ) % DSZ;
    int ww  = rem % DSZ;
    int i = (dd + DSZ - SHIFT_) % DSZ;
    int j = (hh + DSZ - SHIFT_) % DSZ;
    int k = (ww + DSZ - SHIFT_) % DSZ;
    int win = (i / WS) * 16 + (j / WS) * 4 + (k / WS);
    int n   = (i % WS) * 49 + (j % WS) * 7 + (k % WS);
    return (b * NWIN + win) * NTOK + n;
}
__device__ __forceinline__ int winrow_to_token(int r) {
    int win = r / NTOK;
    int n   = r - win * NTOK;
    int b   = win >> 6;
    int w64 = win & 63;
    int ni = n / 49, rem = n - ni * 49;
    int nj = rem / 7, nk = rem - nj * 7;
    int i = (w64 >> 4) * 7 + ni;
    int j = ((w64 >> 2) & 3) * 7 + nj;
    int k = (w64 & 3) * 7 + nk;
    int dd = i + SHIFT_; if (dd >= DSZ) dd -= DSZ;
    int hh = j + SHIFT_; if (hh >= DSZ) hh -= DSZ;
    int ww = k + SHIFT_; if (ww >= DSZ) ww -= DSZ;
    return b * (DSZ * DSZ * DSZ) + dd * (DSZ * DSZ) + hh * DSZ + ww;
}

// packed f32x2 -> bf16x2 (one CVT): dst u32 = {hi:hi_val, lo:lo_val}
#define CVTPK(dst, lo_val, hi_val) \
    asm("cvt.rn.satfinite.bf16x2.f32 %0, %1, %2;" : "=r"(dst) : "f"(hi_val), "f"(lo_val))

// fast GELU (tanh form, exp2-based)
__device__ __forceinline__ float gelu_fast(float xv) {
    float u  = xv * (0.7978845608028654f + 0.035677408136300125f * xv * xv);
    float au = fabsf(u);
    float t  = __frcp_rn(1.0f + exp2f(au * 2.8853900817779268f));
    float th = copysignf(1.0f - 2.0f * t, u);
    return 0.5f * xv * (1.0f + th);
}

#define CP_ASYNC16(dst_u32, src_ptr) \
    asm volatile("cp.async.cg.shared.global [%0], [%1], 16;" :: "r"(dst_u32), "l"(src_ptr))
#define CP_COMMIT() asm volatile("cp.async.commit_group;")
#define CP_WAIT(n)  asm volatile("cp.async.wait_group %0;" :: "n"(n))

#define LDMX4(r0, r1, r2, r3, addr) \
    asm volatile("ldmatrix.sync.aligned.m8n8.x4.shared.b16 {%0,%1,%2,%3}, [%4];" \
                 : "=r"(r0), "=r"(r1), "=r"(r2), "=r"(r3) : "r"(addr))
#define LDMX4T(r0, r1, r2, r3, addr) \
    asm volatile("ldmatrix.sync.aligned.m8n8.x4.trans.shared.b16 {%0,%1,%2,%3}, [%4];" \
                 : "=r"(r0), "=r"(r1), "=r"(r2), "=r"(r3) : "r"(addr))

#define MMA16816(d, a0, a1, a2, a3, b0, b1) \
    asm volatile("mma.sync.aligned.m16n8k16.row.col.f32.bf16.bf16.f32 " \
                 "{%0,%1,%2,%3}, {%4,%5,%6,%7}, {%8,%9}, {%0,%1,%2,%3};" \
                 : "+f"((d)[0]), "+f"((d)[1]), "+f"((d)[2]), "+f"((d)[3]) \
                 : "r"(a0), "r"(a1), "r"(a2), "r"(a3), "r"(b0), "r"(b1))

// ---------------- merged weight conversion (q-rows folded) ----------------
__global__ void cvt4_kernel(const float* __restrict__ s0, __nv_bfloat16* __restrict__ d0, int n0,
                            const float* __restrict__ s1, __nv_bfloat16* __restrict__ d1, int n1,
                            const float* __restrict__ s2, __nv_bfloat16* __restrict__ d2, int n2,
                            const float* __restrict__ s3, __nv_bfloat16* __restrict__ d3, int n3) {
    int i = blockIdx.x * 256 + threadIdx.x;
    if (i < n0) {
        float v = s0[i];
        if (i < CDIM * CDIM) v *= QFOLD;
        d0[i] = __float2bfloat16(v);
        return;
    }
    i -= n0;
    if (i < n1) { d1[i] = __float2bfloat16(s1[i]); return; }
    i -= n1;
    if (i < n2) { d2[i] = __float2bfloat16(s2[i]); return; }
    i -= n2;
    if (i < n3) { d3[i] = __float2bfloat16(s3[i]); }
}

__global__ void biasq_kernel(const float* __restrict__ qkv_b, float* __restrict__ qb) {
    int i = blockIdx.x * 192 + threadIdx.x;
    if (i < 3 * CDIM) qb[i] = (i < CDIM) ? qkv_b[i] * QFOLD : qkv_b[i];
}

// ---------------- combined bias+mask precompute ----------------
__global__ void comb_pre_kernel(const float* __restrict__ table,
                                __nv_bfloat16* __restrict__ comb) {
    int idx = blockIdx.x * 256 + threadIdx.x;
    if (idx >= COMB_ELEMS) return;
    int col  = idx % CPITCH;
    int row  = (idx / CPITCH) % CPITCH;
    int hc   = idx / (CPITCH * CPITCH);
    int h = hc >> 3, cls = hc & 7;
    float val = -160.f;
    if (col < NTOK && row < NTOK) {
        int i3 = row / 49, j3 = (row / 7) % 7, k3 = row % 7;
        int ci = col / 49, cj = (col / 7) % 7, ck = col % 7;
        int rel = (i3 - ci + 6) * 169 + (j3 - cj + 6) * 13 + (k3 - ck + 6);
        float v = table[rel * HEADS + h];
        bool diff = ((cls & 4) && ((i3 < 4) != (ci < 4))) ||
                    ((cls & 2) && ((j3 < 4) != (cj < 4))) ||
                    ((cls & 1) && ((k3 < 4) != (ck < 4)));
        if (diff) v -= 100.f;
        val = v * LOG2E;
    }
    comb[idx] = __float2bfloat16(val);
}

// ---------------- LN1: half-warp per token, float4 ----------------
__global__ __launch_bounds__(256) void ln1_kernel(const float* __restrict__ x,
                                                  const float* __restrict__ g,
                                                  const float* __restrict__ b,
                                                  __nv_bfloat16* __restrict__ xw) {
    int tid = threadIdx.x;
    int lane = tid & 31;
    int l16 = lane & 15;
    int t = blockIdx.x * 16 + (tid >> 5) * 2 + (lane >> 4);
    const float4* xp = (const float4*)(x + (size_t)t * CDIM);
    const float4* gp = (const float4*)g;
    const float4* bp = (const float4*)b;
    float4 v[3];
    float s = 0.f, s2 = 0.f;
#pragma unroll
    for (int i = 0; i < 3; i++) {
        v[i] = xp[l16 + i * 16];
        s += v[i].x + v[i].y + v[i].z + v[i].w;
        s2 += v[i].x * v[i].x + v[i].y * v[i].y + v[i].z * v[i].z + v[i].w * v[i].w;
    }
#pragma unroll
    for (int o = 8; o; o >>= 1) {
        s += __shfl_xor_sync(0xffffffffu, s, o);
        s2 += __shfl_xor_sync(0xffffffffu, s2, o);
    }
    float mean = s * (1.0f / CDIM);
    float rstd = rsqrtf(s2 * (1.0f / CDIM) - mean * mean + 1e-5f);
    int row = token_to_winrow(t);
    __nv_bfloat16* op = xw + (size_t)row * CDIM;
#pragma unroll
    for (int i = 0; i < 3; i++) {
        int c4 = l16 + i * 16;
        float4 gg = gp[c4], bb = bp[c4];
        float o0 = (v[i].x - mean) * rstd * gg.x + bb.x;
        float o1 = (v[i].y - mean) * rstd * gg.y + bb.y;
        float o2 = (v[i].z - mean) * rstd * gg.z + bb.z;
        float o3 = (v[i].w - mean) * rstd * gg.w + bb.w;
        uint2 pk;
        CVTPK(pk.x, o0, o1);
        CVTPK(pk.y, o2, o3);
        *(uint2*)(op + c4 * 4) = pk;
    }
}

// ---------------- GEMM tile loader ----------------
__device__ __forceinline__ void gemm_issue(const __nv_bfloat16* __restrict__ A,
                                           const __nv_bfloat16* __restrict__ Wt,
                                           int bm, int bn, int Ktot, int lr, int lc8,
                                           char* bA, char* bB, int k0) {
#pragma unroll
    for (int rr = 0; rr < 4; rr++) {
        int r = lr + rr * 32;
        uint32_t off = (uint32_t)(r * 128 + lc8 * 2);
        off ^= (off >> 3) & 0x70;
        CP_ASYNC16(s2u(bA + off), A + (size_t)(bm + r) * Ktot + k0 + lc8);
    }
#pragma unroll
    for (int rr = 0; rr < 2; rr++) {
        int br = lr + rr * 32;
        uint32_t off = (uint32_t)(br * 128 + lc8 * 2);
        off ^= (off >> 3) & 0x70;
        CP_ASYNC16(s2u(bB + off), Wt + (size_t)(bn + br) * Ktot + k0 + lc8);
    }
    CP_COMMIT();
}

// ---------------- chunk mainloop with fragment double-buffering ----------------
__device__ __forceinline__ void chunk_mma(uint32_t sA, uint32_t sB,
                                          float (&acc)[2][4][4],
                                          int wm, int wn, int lane) {
    uint32_t fa[2][8], fb[2][8];
    auto offA = [&](int mi, int kk) {
        uint32_t off = (uint32_t)((wm + mi * 16 + (lane & 15)) * 128 + kk * 32 + (lane >> 4) * 16);
        return off ^ ((off >> 3) & 0x70);
    };
    auto offB = [&](int nj, int kk) {
        uint32_t off = (uint32_t)((wn + nj * 16 + (lane & 15)) * 128 + kk * 32 + (lane >> 4) * 16);
        return off ^ ((off >> 3) & 0x70);
    };
    LDMX4(fa[0][0], fa[0][1], fa[0][2], fa[0][3], sA + offA(0, 0));
    LDMX4(fa[0][4], fa[0][5], fa[0][6], fa[0][7], sA + offA(1, 0));
    LDMX4(fb[0][0], fb[0][1], fb[0][2], fb[0][3], sB + offB(0, 0));
    LDMX4(fb[0][4], fb[0][5], fb[0][6], fb[0][7], sB + offB(1, 0));
#pragma unroll
    for (int kk = 0; kk < 4; kk++) {
        const int cur = kk & 1, nxt = cur ^ 1;
        if (kk < 3) {
            LDMX4(fa[nxt][0], fa[nxt][1], fa[nxt][2], fa[nxt][3], sA + offA(0, kk + 1));
            LDMX4(fa[nxt][4], fa[nxt][5], fa[nxt][6], fa[nxt][7], sA + offA(1, kk + 1));
            LDMX4(fb[nxt][0], fb[nxt][1], fb[nxt][2], fb[nxt][3], sB + offB(0, kk + 1));
            LDMX4(fb[nxt][4], fb[nxt][5], fb[nxt][6], fb[nxt][7], sB + offB(1, kk + 1));
        }
#pragma unroll
        for (int nj = 0; nj < 2; nj++)
#pragma unroll
            for (int mi = 0; mi < 2; mi++) {
                MMA16816(acc[mi][2 * nj], fa[cur][mi * 4 + 0], fa[cur][mi * 4 + 1],
                         fa[cur][mi * 4 + 2], fa[cur][mi * 4 + 3],
                         fb[cur][nj * 4 + 0], fb[cur][nj * 4 + 2]);
                MMA16816(acc[mi][2 * nj + 1], fa[cur][mi * 4 + 0], fa[cur][mi * 4 + 1],
                         fa[cur][mi * 4 + 2], fa[cur][mi * 4 + 3],
                         fb[cur][nj * 4 + 1], fb[cur][nj * 4 + 3]);
            }
    }
}

// ---------------- HMMA bf16 GEMM ----------------
// EPI: 0 = bias -> fp32; 1 = bias+gelu -> bf16; 2 = bias+resid -> fp32;
//      3 = bias -> bf16;  4 = bias + x[token] -> xres[token] (row-permuted)
template <int EPI, bool FULLK>
__global__ __launch_bounds__(256, 3)
void gemm_mma_kernel(const __nv_bfloat16* __restrict__ A,
                     const __nv_bfloat16* __restrict__ Wt,
                     const float* __restrict__ bias,
                     const float* __restrict__ resid,
                     void* __restrict__ Cv, int Ktot, int Ntot)
{
    extern __shared__ __align__(1024) char dsm[];
    char* bufA[3] = {dsm, dsm + 16384, dsm + 32768};
    char* bufB[3] = {dsm + 49152, dsm + 57344, dsm + 65536};

    const int tid = threadIdx.x;
    const int lane = tid & 31;
    const int wid = tid >> 5;
    const int wm = (wid & 3) * 32;
    const int wn = (wid >> 2) * 32;
    const int bm = blockIdx.y * BM;
    const int bn = blockIdx.x * BN;

    float acc[2][4][4];
#pragma unroll
    for (int a = 0; a < 2; a++)
#pragma unroll
        for (int b = 0; b < 4; b++)
#pragma unroll
            for (int c = 0; c < 4; c++) acc[a][b][c] = 0.f;

    const int lr = tid >> 3;
    const int lc8 = (tid & 7) * 8;

    if (FULLK) {
#pragma unroll
        for (int ch = 0; ch < 3; ch++)
            gemm_issue(A, Wt, bm, bn, Ktot, lr, lc8, bufA[ch], bufB[ch], ch * KB);
#pragma unroll
        for (int chunk = 0; chunk < 3; chunk++) {
            if (chunk == 0)      CP_WAIT(2);
            else if (chunk == 1) CP_WAIT(1);
            else                 CP_WAIT(0);
            __syncthreads();
            chunk_mma(s2u(bufA[chunk]), s2u(bufB[chunk]), acc, wm, wn, lane);
        }
    } else {
        const int nch = Ktot / KB;
        gemm_issue(A, Wt, bm, bn, Ktot, lr, lc8, bufA[0], bufB[0], 0);
        gemm_issue(A, Wt, bm, bn, Ktot, lr, lc8, bufA[1], bufB[1], KB);
        for (int ch = 0; ch < nch; ch++) {
            if (ch + 2 < nch)
                gemm_issue(A, Wt, bm, bn, Ktot, lr, lc8,
                           bufA[(ch + 2) % 3], bufB[(ch + 2) % 3], (ch + 2) * KB);
            const int rem = nch - ch - 1;
            if (rem >= 2)      CP_WAIT(2);
            else if (rem == 1) CP_WAIT(1);
            else               CP_WAIT(0);
            __syncthreads();
            chunk_mma(s2u(bufA[ch % 3]), s2u(bufB[ch % 3]), acc, wm, wn, lane);
            __syncthreads();
        }
    }

    const int gq = lane >> 2;
    const int tg = lane & 3;
#pragma unroll
    for (int mi = 0; mi < 2; mi++) {
#pragma unroll
        for (int half = 0; half < 2; half++) {
            int row = bm + wm + mi * 16 + gq + half * 8;
            int orow = row;
            if (EPI == 4) orow = winrow_to_token(row);
#pragma unroll
            for (int ni = 0; ni < 4; ni++) {
                int col = bn + wn + ni * 8 + tg * 2;
                float bia0 = bias[col], bia1 = bias[col + 1];
                float v0 = acc[mi][ni][half * 2 + 0] + bia0;
                float v1 = acc[mi][ni][half * 2 + 1] + bia1;
                size_t oi = (size_t)orow * Ntot + col;
                if (EPI == 1) {
                    v0 = gelu_fast(v0);
                    v1 = gelu_fast(v1);
                    uint32_t pk; CVTPK(pk, v0, v1);
                    *(uint32_t*)((__nv_bfloat16*)Cv + oi) = pk;
                } else if (EPI == 2 || EPI == 4) {
                    float2 rv = *(const float2*)(resid + oi);
                    float2 o; o.x = v0 + rv.x; o.y = v1 + rv.y;
                    *(float2*)((float*)Cv + oi) = o;
                } else if (EPI == 3) {
                    uint32_t pk; CVTPK(pk, v0, v1);
                    *(uint32_t*)((__nv_bfloat16*)Cv + oi) = pk;
                } else {
                    float2 o; o.x = v0; o.y = v1;
                    *(float2*)((float*)Cv + oi) = o;
                }
            }
        }
    }
}

// ---------------- FA2-style attention: register-resident P ----------------
__global__ __launch_bounds__(256, 3) void attn_tc_kernel(
    const __nv_bfloat16* __restrict__ qkv, const __nv_bfloat16* __restrict__ comb,
    __nv_bfloat16* __restrict__ out)
{
    extern __shared__ __align__(1024) char sm[];
    const uint32_t uK = s2u(sm + AOFF_K);
    const uint32_t uV = s2u(sm + AOFF_V);
    const uint32_t uQ = s2u(sm + AOFF_Q);
    float* Ost = (float*)(sm + AOFF_O);
    float* rs  = (float*)(sm + AOFF_RS);

    const int bx = blockIdx.x;
    const int w  = bx / HEADS;
    const int h  = bx - w * HEADS;
    const int mw = w % NWIN;
    const int wd = mw >> 4, wh = (mw >> 2) & 3, ww = mw & 3;
    const int cls = ((wd == 3) << 2) | ((wh == 3) << 1) | (ww == 3);
    const int tid = threadIdx.x;
    const int lane = tid & 31;
    const int wid = tid >> 5;

    const __nv_bfloat16* base = qkv + (size_t)w * NTOK * (3 * CDIM);

    for (int idx = tid; idx < KPAD * 4; idx += 256) {
        int j = idx >> 2, s = idx & 3;
        uint4 vk = make_uint4(0, 0, 0, 0);
        uint4 vv = make_uint4(0, 0, 0, 0);
        if (j < NTOK) {
            const __nv_bfloat16* rp = base + (size_t)j * (3 * CDIM) + h * HD + s * 8;
            vk = *(const uint4*)(rp + CDIM);
            vv = *(const uint4*)(rp + 2 * CDIM);
        }
        *(uint4*)(sm + AOFF_K + j * KPITCH + s * 16) = vk;
        *(uint4*)(sm + AOFF_V + j * KPITCH + s * 16) = vv;
    }

    const int wm = wid & 3, wn = wid >> 2;
    const int gq_ = lane >> 2, tg = lane & 3;
    const __nv_bfloat16* cb = comb + (size_t)(h * 8 + cls) * CPITCH * CPITCH;
    const uint32_t vlane = (uint32_t)(((lane & 7) + ((lane >> 3) & 1) * 8) * KPITCH + (lane >> 4) * 16);

    for (int qt = 0; qt < NCH; qt++) {
        const int q0 = qt * QT;
        for (int idx = tid; idx < QT * 4; idx += 256) {
            int r = idx >> 2, s = idx & 3;
            int gq = q0 + r;
            uint4 v = make_uint4(0, 0, 0, 0);
            if (gq < NTOK) v = *(const uint4*)(base + (size_t)gq * (3 * CDIM) + h * HD + s * 8);
            *(uint4*)(sm + AOFF_Q + r * KPITCH + s * 16) = v;
        }
        __syncthreads();

        uint32_t qf[2][4];
#pragma unroll
        for (int ks = 0; ks < 2; ks++)
            LDMX4(qf[ks][0], qf[ks][1], qf[ks][2], qf[ks][3],
                  uQ + (uint32_t)((wm * 16 + (lane & 15)) * KPITCH + ks * 32 + (lane >> 4) * 16));
        __syncthreads();   // Q smem now free; Ost may alias it

        float acc_o[4][4];
#pragma unroll
        for (int t = 0; t < 4; t++)
#pragma unroll
            for (int c = 0; c < 4; c++) acc_o[t][c] = 0.f;
        float rs0 = 0.f, rs1 = 0.f;

        const int r0g = q0 + wm * 16 + gq_;
        const __nv_bfloat16* c0p = cb + (size_t)r0g * CPITCH;
        const __nv_bfloat16* c1p = c0p + 8 * CPITCH;

        for (int ch = 0; ch < NCH; ch++) {
            const int j0 = ch * NC;
            float acc[4][4];
#pragma unroll
            for (int t = 0; t < 4; t++)
#pragma unroll
                for (int c = 0; c < 4; c++) acc[t][c] = 0.f;

#pragma unroll
            for (int ks = 0; ks < 2; ks++) {
#pragma unroll
                for (int nj = 0; nj < 2; nj++) {
                    uint32_t r0, r1, r2, r3;
                    LDMX4(r0, r1, r2, r3,
                          uK + (uint32_t)((j0 + wn * 32 + nj * 16 + (lane & 15)) * KPITCH + ks * 32 + (lane >> 4) * 16));
                    MMA16816(acc[2 * nj], qf[ks][0], qf[ks][1], qf[ks][2], qf[ks][3], r0, r2);
                    MMA16816(acc[2 * nj + 1], qf[ks][0], qf[ks][1], qf[ks][2], qf[ks][3], r1, r3);
                }
            }

            uint32_t pf[2][4];
#pragma unroll
            for (int ti = 0; ti < 4; ti++) {
                int jl = wn * 32 + (ti >> 1) * 16 + (ti & 1) * 8 + tg * 2;
                int ja = j0 + jl;
                __nv_bfloat162 b0 = *(const __nv_bfloat162*)(c0p + ja);
                __nv_bfloat162 b1 = *(const __nv_bfloat162*)(c1p + ja);
                float e00 = exp2f(acc[ti][0] + __bfloat162float(b0.x));
                float e01 = exp2f(acc[ti][1] + __bfloat162float(b0.y));
                float e10 = exp2f(acc[ti][2] + __bfloat162float(b1.x));
                float e11 = exp2f(acc[ti][3] + __bfloat162float(b1.y));
                rs0 += e00 + e01;
                rs1 += e10 + e11;
                CVTPK(pf[ti >> 1][(ti & 1) * 2 + 0], e00, e01);
                CVTPK(pf[ti >> 1][(ti & 1) * 2 + 1], e10, e11);
            }

#pragma unroll
            for (int kc = 0; kc < 2; kc++) {
                uint32_t vbase = uV + (uint32_t)((j0 + wn * 32 + kc * 16) * KPITCH) + vlane;
#pragma unroll
                for (int dh = 0; dh < 2; dh++) {
                    uint32_t r0, r1, r2, r3;
                    LDMX4T(r0, r1, r2, r3, vbase + dh * 32);
                    MMA16816(acc_o[dh * 2 + 0], pf[kc][0], pf[kc][1], pf[kc][2], pf[kc][3], r0, r1);
                    MMA16816(acc_o[dh * 2 + 1], pf[kc][0], pf[kc][1], pf[kc][2], pf[kc][3], r2, r3);
                }
            }
        }

        rs0 += __shfl_xor_sync(0xffffffffu, rs0, 1);
        rs0 += __shfl_xor_sync(0xffffffffu, rs0, 2);
        rs1 += __shfl_xor_sync(0xffffffffu, rs1, 1);
        rs1 += __shfl_xor_sync(0xffffffffu, rs1, 2);
        if (tg == 0) {
            rs[(wm * 16 + gq_) * 2 + wn] = rs0;
            rs[(wm * 16 + gq_ + 8) * 2 + wn] = rs1;
        }

        if (wn == 0) {
#pragma unroll
            for (int dn = 0; dn < 4; dn++)
#pragma unroll
                for (int half = 0; half < 2; half++) {
                    int q = wm * 16 + gq_ + half * 8;
                    float2 val; val.x = acc_o[dn][half * 2]; val.y = acc_o[dn][half * 2 + 1];
                    *(float2*)&Ost[q * OPITCH + dn * 8 + tg * 2] = val;
                }
        }
        __syncthreads();
        if (wn == 1) {
#pragma unroll
            for (int dn = 0; dn < 4; dn++)
#pragma unroll
                for (int half = 0; half < 2; half++) {
                    int q = wm * 16 + gq_ + half * 8;
                    float2* p = (float2*)&Ost[q * OPITCH + dn * 8 + tg * 2];
                    float2 cur = *p;
                    cur.x += acc_o[dn][half * 2];
                    cur.y += acc_o[dn][half * 2 + 1];
                    *p = cur;
                }
        }
        __syncthreads();

        {
            int q = tid >> 2, ds = (tid & 3) * 8;
            int gq = q0 + q;
            if (gq < NTOK) {
                float inv = __frcp_rn(rs[q * 2] + rs[q * 2 + 1]);
                const float* op = &Ost[q * OPITCH + ds];
                uint32_t pk[4];
#pragma unroll
                for (int u = 0; u < 4; u++) {
                    float2 vv = *(const float2*)(op + 2 * u);
                    CVTPK(pk[u], vv.x * inv, vv.y * inv);
                }
                *(uint4*)(out + (size_t)(w * NTOK + gq) * CDIM + h * HD + ds) = *(uint4*)pk;
            }
        }
        __syncthreads();
    }
}

// ---------------- LN2: half-warp per token, float4 ----------------
__global__ __launch_bounds__(256) void ln2_kernel(const float* __restrict__ xres,
                                                  const float* __restrict__ g,
                                                  const float* __restrict__ b,
                                                  __nv_bfloat16* __restrict__ ln2o) {
    int tid = threadIdx.x;
    int lane = tid & 31;
    int l16 = lane & 15;
    int t = blockIdx.x * 16 + (tid >> 5) * 2 + (lane >> 4);
    const float4* xp = (const float4*)(xres + (size_t)t * CDIM);
    const float4* gp = (const float4*)g;
    const float4* bp = (const float4*)b;
    float4 v[3];
    float s = 0.f, s2 = 0.f;
#pragma unroll
    for (int i = 0; i < 3; i++) {
        v[i] = xp[l16 + i * 16];
        s += v[i].x + v[i].y + v[i].z + v[i].w;
        s2 += v[i].x * v[i].x + v[i].y * v[i].y + v[i].z * v[i].z + v[i].w * v[i].w;
    }
#pragma unroll
    for (int o = 8; o; o >>= 1) {
        s += __shfl_xor_sync(0xffffffffu, s, o);
        s2 += __shfl_xor_sync(0xffffffffu, s2, o);
    }
    float mean = s * (1.0f / CDIM);
    float rstd = rsqrtf(s2 * (1.0f / CDIM) - mean * mean + 1e-5f);
    __nv_bfloat16* op = ln2o + (size_t)t * CDIM;
#pragma unroll
    for (int i = 0; i < 3; i++) {
        int c4 = l16 + i * 16;
        float4 gg = gp[c4], bb = bp[c4];
        float o0 = (v[i].x - mean) * rstd * gg.x + bb.x;
        float o1 = (v[i].y - mean) * rstd * gg.y + bb.y;
        float o2 = (v[i].z - mean) * rstd * gg.z + bb.z;
        float o3 = (v[i].w - mean) * rstd * gg.w + bb.w;
        uint2 pk;
        CVTPK(pk.x, o0, o1);
        CVTPK(pk.y, o2, o3);
        *(uint2*)(op + c4 * 4) = pk;
    }
}

// ---------------- host-side stream/event singletons ----------------
static cudaStream_t make_stream() {
    cudaStream_t s;
    cudaStreamCreateWithFlags(&s, cudaStreamNonBlocking);
    return s;
}
static cudaEvent_t make_event() {
    cudaEvent_t e;
    cudaEventCreateWithFlags(&e, cudaEventDisableTiming);
    return e;
}

// ---------------- launch ----------------
extern "C" void kernel_launch(void* const* d_in, const int* in_sizes, int n_in,
                              void* d_out, int out_size) {
    (void)in_sizes; (void)n_in; (void)out_size;
    const float* x       = (const float*)d_in[0];
    const float* table   = (const float*)d_in[3];
    const float* n1g     = (const float*)d_in[4];
    const float* n1b     = (const float*)d_in[5];
    const float* qkv_w   = (const float*)d_in[6];
    const float* qkv_b   = (const float*)d_in[7];
    const float* proj_w  = (const float*)d_in[8];
    const float* proj_b  = (const float*)d_in[9];
    const float* n2g     = (const float*)d_in[10];
    const float* n2b     = (const float*)d_in[11];
    const float* fc1_w   = (const float*)d_in[12];
    const float* fc1_b   = (const float*)d_in[13];
    const float* fc2_w   = (const float*)d_in[14];
    const float* fc2_b   = (const float*)d_in[15];
    float* out = (float*)d_out;

    __nv_bfloat16 *xwb, *qkvb, *attnb, *ln2b, *h1b, *wqkv, *wproj, *wfc1, *wfc2, *comb;
    float *xres, *qbias;
    cudaGetSymbolAddress((void**)&xwb,   g_xwb);
    cudaGetSymbolAddress((void**)&qkvb,  g_qkvb);
    cudaGetSymbolAddress((void**)&attnb, g_attnb);
    cudaGetSymbolAddress((void**)&xres,  g_xres);
    cudaGetSymbolAddress((void**)&ln2b,  g_ln2b);
    cudaGetSymbolAddress((void**)&h1b,   g_h1b);
    cudaGetSymbolAddress((void**)&wqkv,  g_wqkv);
    cudaGetSymbolAddress((void**)&wproj, g_wproj);
    cudaGetSymbolAddress((void**)&wfc1,  g_wfc1);
    cudaGetSymbolAddress((void**)&wfc2,  g_wfc2);
    cudaGetSymbolAddress((void**)&comb,  g_comb);
    cudaGetSymbolAddress((void**)&qbias, g_qbias);

    cudaFuncSetAttribute(attn_tc_kernel, cudaFuncAttributeMaxDynamicSharedMemorySize,
                         ATTN_SMEM_BYTES);
    cudaFuncSetAttribute((gemm_mma_kernel<3, true>), cudaFuncAttributeMaxDynamicSharedMemorySize, GEMM_SMEM_BYTES);
    cudaFuncSetAttribute((gemm_mma_kernel<4, true>), cudaFuncAttributeMaxDynamicSharedMemorySize, GEMM_SMEM_BYTES);
    cudaFuncSetAttribute((gemm_mma_kernel<1, true>), cudaFuncAttributeMaxDynamicSharedMemorySize, GEMM_SMEM_BYTES);
    cudaFuncSetAttribute((gemm_mma_kernel<2, false>), cudaFuncAttributeMaxDynamicSharedMemorySize, GEMM_SMEM_BYTES);

    static cudaStream_t s1 = make_stream();
    static cudaStream_t s2 = make_stream();
    static cudaEvent_t ev_root = make_event();
    static cudaEvent_t ev_w    = make_event();
    static cudaEvent_t ev_c    = make_event();

    const int n0 = 3 * CDIM * CDIM, n1 = CDIM * CDIM, n2 = HID * CDIM, n3 = CDIM * HID;

    cudaEventRecord(ev_root, 0);
    cudaStreamWaitEvent(s1, ev_root, 0);
    cudaStreamWaitEvent(s2, ev_root, 0);

    cvt4_kernel<<<(n0 + n1 + n2 + n3 + 255) / 256, 256, 0, s1>>>(
        qkv_w, wqkv, n0, proj_w, wproj, n1, fc1_w, wfc1, n2, fc2_w, wfc2, n3);
    biasq_kernel<<<3, 192, 0, s1>>>(qkv_b, qbias);
    cudaEventRecord(ev_w, s1);

    comb_pre_kernel<<<(COMB_ELEMS + 255) / 256, 256, 0, s2>>>(table, comb);
    cudaEventRecord(ev_c, s2);

    ln1_kernel<<<TOK / 16, 256>>>(x, n1g, n1b, xwb);

    cudaStreamWaitEvent(0, ev_w, 0);
    gemm_mma_kernel<3, true><<<dim3(576 / BN, TOK / BM), 256, GEMM_SMEM_BYTES>>>(
        xwb, wqkv, qbias, nullptr, qkvb, CDIM, 3 * CDIM);

    cudaStreamWaitEvent(0, ev_c, 0);
    attn_tc_kernel<<<TOTWIN * HEADS, 256, ATTN_SMEM_BYTES>>>(qkvb, comb, attnb);

    gemm_mma_kernel<4, true><<<dim3(CDIM / BN, TOK / BM), 256, GEMM_SMEM_BYTES>>>(
        attnb, wproj, proj_b, x, xres, CDIM, CDIM);
    ln2_kernel<<<TOK / 16, 256>>>(xres, n2g, n2b, ln2b);
    gemm_mma_kernel<1, true><<<dim3(HID / BN, TOK / BM), 256, GEMM_SMEM_BYTES>>>(
        ln2b, wfc1, fc1_b, nullptr, h1b, CDIM, HID);
    gemm_mma_kernel<2, false><<<dim3(CDIM / BN, TOK / BM), 256, GEMM_SMEM_BYTES>>>(
        h1b, wfc2, fc2_b, xres, out, HID, CDIM);
}